// round 3
// baseline (speedup 1.0000x reference)
#include <cuda_runtime.h>

constexpr int Hc = 128, Wc = 128, HWc = Hc * Wc;

// ---------------- scratch (device globals; no allocation allowed) ----------------
__device__ float g_h1[2 * 64 * HWc];
__device__ float g_h2[2 * 64 * HWc];
__device__ float g_po[2 * 432 * HWc];
__device__ float g_dp[4 * 2 * 64 * HWc];   // [split][b][co][hw]

// ---------------- packed f32x2 helpers ----------------
__device__ __forceinline__ unsigned long long pack2(float lo, float hi) {
    unsigned long long r;
    asm("mov.b64 %0, {%1, %2};" : "=l"(r) : "f"(lo), "f"(hi));
    return r;
}
__device__ __forceinline__ void unpack2(unsigned long long v, float& lo, float& hi) {
    asm("mov.b64 {%0, %1}, %2;" : "=f"(lo), "=f"(hi) : "l"(v));
}
__device__ __forceinline__ void fma2(unsigned long long& d, unsigned long long a, unsigned long long b) {
    asm("fma.rn.f32x2 %0, %1, %2, %0;" : "+l"(d) : "l"(a), "l"(b));
}

// ---------------- direct 3x3 conv, smem-tiled, PX pixels/thread ----------------
// Block 256 = 32x8 threads; tile = 32 wide x (8*PX) tall. Each thread handles
// rows ty + 8*p. Each thread: COUT_BLK outputs x PX pixels.
template <int CIN, int COUT_BLK, int NCOB, int PX, bool LEAKY, bool TRANSFORM>
__global__ __launch_bounds__(256)
void conv3x3_kernel(const float* __restrict__ in, const float* __restrict__ wgt,
                    const float* __restrict__ bias, float* __restrict__ out,
                    const float* __restrict__ flow)
{
    constexpr int TW = 32, THROWS = 8 * PX, CK = 8;
    constexpr int NACC = COUT_BLK / 2;
    constexpr int COUT_TOT = COUT_BLK * NCOB;

    __shared__ float s_in[CK][THROWS + 2][TW + 2];
    __shared__ float s_wt[CK * 9 * COUT_BLK];  // [ci][k][co], co contiguous

    const int bz  = blockIdx.z;
    const int b   = bz / NCOB;
    const int coz = bz % NCOB;
    const int x0  = blockIdx.x * TW;
    const int y0  = blockIdx.y * THROWS;
    const int tid = threadIdx.x;
    const int tx  = tid % TW;
    const int ty  = tid / TW;               // 0..7
    const int xx  = x0 + tx;

    unsigned long long acc[PX][NACC];
    {
        const float* bp = bias + coz * COUT_BLK;
        #pragma unroll
        for (int j = 0; j < NACC; j++) {
            unsigned long long bv = pack2(bp[2 * j], bp[2 * j + 1]);
            #pragma unroll
            for (int p = 0; p < PX; p++) acc[p][j] = bv;
        }
    }

    for (int cb = 0; cb < CIN; cb += CK) {
        __syncthreads();
        const float* ip = in + (b * CIN + cb) * HWc;
        #pragma unroll 1
        for (int i = tid; i < CK * (THROWS + 2) * (TW + 2); i += 256) {
            int lx = i % (TW + 2);
            int r  = i / (TW + 2);
            int ly = r % (THROWS + 2);
            int ci = r / (THROWS + 2);
            int gx = x0 + lx - 1, gy = y0 + ly - 1;
            float v = 0.f;
            if ((unsigned)gx < (unsigned)Wc && (unsigned)gy < (unsigned)Hc)
                v = ip[ci * HWc + gy * Wc + gx];
            s_in[ci][ly][lx] = v;
        }
        #pragma unroll 1
        for (int i = tid; i < CK * 9 * COUT_BLK; i += 256) {
            int co = i % COUT_BLK;
            int r  = i / COUT_BLK;
            int k  = r % 9;
            int ci = r / 9;
            s_wt[i] = wgt[((coz * COUT_BLK + co) * CIN + (cb + ci)) * 9 + k];
        }
        __syncthreads();

        #pragma unroll 1
        for (int ci = 0; ci < CK; ci++) {
            float v[PX][9];
            #pragma unroll
            for (int p = 0; p < PX; p++) {
                #pragma unroll
                for (int dy = 0; dy < 3; dy++) {
                    #pragma unroll
                    for (int dx = 0; dx < 3; dx++) {
                        v[p][dy * 3 + dx] = s_in[ci][ty + 8 * p + dy][tx + dx];
                    }
                }
            }
            #pragma unroll
            for (int k = 0; k < 9; k++) {
                unsigned long long vv[PX];
                #pragma unroll
                for (int p = 0; p < PX; p++) vv[p] = pack2(v[p][k], v[p][k]);
                const ulonglong2* wp =
                    reinterpret_cast<const ulonglong2*>(&s_wt[(ci * 9 + k) * COUT_BLK]);
                #pragma unroll
                for (int j = 0; j < NACC / 2; j++) {
                    ulonglong2 w2 = wp[j];
                    #pragma unroll
                    for (int p = 0; p < PX; p++) {
                        fma2(acc[p][2 * j],     w2.x, vv[p]);
                        fma2(acc[p][2 * j + 1], w2.y, vv[p]);
                    }
                }
            }
        }
    }

    #pragma unroll
    for (int p = 0; p < PX; p++) {
        const int yy = y0 + ty + 8 * p;
        float fy = 0.f, fx = 0.f;
        if (TRANSFORM) {
            fy = flow[(b * 2 + 1) * HWc + yy * Wc + xx];
            fx = flow[(b * 2 + 0) * HWc + yy * Wc + xx];
        }
        #pragma unroll
        for (int j = 0; j < NACC; j++) {
            float r0, r1;
            unpack2(acc[p][j], r0, r1);
            float rv[2] = {r0, r1};
            #pragma unroll
            for (int t = 0; t < 2; t++) {
                int co = coz * COUT_BLK + 2 * j + t;
                float a = rv[t];
                if (LEAKY) a = (a >= 0.f) ? a : 0.1f * a;
                if (TRANSFORM) {
                    if (co < 288) a = 10.f * tanhf(a) + ((co & 1) ? fx : fy);
                    else          a = 1.f / (1.f + expf(-a));
                }
                out[(b * COUT_TOT + co) * HWc + yy * Wc + xx] = a;
            }
        }
    }
}

// ---------------- deformable gather + einsum (group-split partials) ----------------
// Grid (8,16,B*NSPLIT), block 128 = 16x8 pixel tile. Each block: 4 groups,
// writes partial 64-channel sums to g_dp[split]. k-loop unrolled x3 for MLP.
constexpr int NSPLIT = 4;
constexpr int GPS = 16 / NSPLIT;   // groups per split = 4

__global__ __launch_bounds__(128)
void deform_kernel(const float* __restrict__ xin, const float* __restrict__ po,
                   const float* __restrict__ wgt, float* __restrict__ dp)
{
    __shared__ float s_wt[GPS * 9 * 4 * 64];  // [gl][k][c][o]

    const int bz    = blockIdx.z;
    const int B     = gridDim.z / NSPLIT;
    const int b     = bz / NSPLIT;
    const int split = bz % NSPLIT;
    const int g0    = split * GPS;
    const int x0    = blockIdx.x * 16, y0 = blockIdx.y * 8;
    const int tid   = threadIdx.x;
    const int tx    = tid % 16, ty = tid / 16;
    const int xx    = x0 + tx, yy = y0 + ty;

    unsigned long long acc[32];
    #pragma unroll
    for (int j = 0; j < 32; j++) acc[j] = 0ULL;

    const float* pob = po + b * 432 * HWc + yy * Wc + xx;
    const float* xb  = xin + b * 64 * HWc;

    #pragma unroll 1
    for (int i = tid; i < GPS * 9 * 4 * 64; i += 128) {
        int o = i & 63;
        int r = i >> 6;
        int c = r & 3;
        r >>= 2;
        int k  = r % 9;
        int gl = r / 9;
        s_wt[i] = wgt[(o * 64 + (g0 + gl) * 4 + c) * 9 + k];
    }
    __syncthreads();

    #pragma unroll 1
    for (int gl = 0; gl < GPS; gl++) {
        const int g = g0 + gl;
        const float* xg = xb + g * 4 * HWc;
        #pragma unroll 3
        for (int k = 0; k < 9; k++) {
            const int gk = g * 9 + k;
            float offy = pob[(2 * gk) * HWc];
            float offx = pob[(2 * gk + 1) * HWc];
            float msk  = pob[(288 + gk) * HWc];

            float py = (float)(yy + k / 3 - 1) + offy;
            float px = (float)(xx + k % 3 - 1) + offx;
            float fy = floorf(py), fxv = floorf(px);
            int iy0 = (int)fy, ix0 = (int)fxv;
            float wy = py - fy, wx = px - fxv;

            bool vy0 = (unsigned)iy0       < (unsigned)Hc;
            bool vy1 = (unsigned)(iy0 + 1) < (unsigned)Hc;
            bool vx0 = (unsigned)ix0       < (unsigned)Wc;
            bool vx1 = (unsigned)(ix0 + 1) < (unsigned)Wc;
            int cy0 = min(max(iy0, 0), Hc - 1), cy1 = min(max(iy0 + 1, 0), Hc - 1);
            int cx0 = min(max(ix0, 0), Wc - 1), cx1 = min(max(ix0 + 1, 0), Wc - 1);

            float w00 = (1.f - wy) * (1.f - wx) * msk; if (!(vy0 && vx0)) w00 = 0.f;
            float w01 = (1.f - wy) * wx        * msk; if (!(vy0 && vx1)) w01 = 0.f;
            float w10 = wy        * (1.f - wx) * msk; if (!(vy1 && vx0)) w10 = 0.f;
            float w11 = wy        * wx         * msk; if (!(vy1 && vx1)) w11 = 0.f;

            int i00 = cy0 * Wc + cx0, i01 = cy0 * Wc + cx1;
            int i10 = cy1 * Wc + cx0, i11 = cy1 * Wc + cx1;

            #pragma unroll
            for (int c = 0; c < 4; c++) {
                const float* p = xg + c * HWc;
                float val = w00 * __ldg(p + i00) + w01 * __ldg(p + i01)
                          + w10 * __ldg(p + i10) + w11 * __ldg(p + i11);
                unsigned long long vv = pack2(val, val);
                const ulonglong2* wp = reinterpret_cast<const ulonglong2*>(
                    &s_wt[((gl * 9 + k) * 4 + c) * 64]);
                #pragma unroll
                for (int j = 0; j < 16; j++) {
                    ulonglong2 w2 = wp[j];
                    fma2(acc[2 * j],     w2.x, vv);
                    fma2(acc[2 * j + 1], w2.y, vv);
                }
            }
        }
    }

    float* dpo = dp + (split * B + b) * 64 * HWc;
    #pragma unroll
    for (int j = 0; j < 32; j++) {
        float lo, hi;
        unpack2(acc[j], lo, hi);
        dpo[(2 * j)     * HWc + yy * Wc + xx] = lo;
        dpo[(2 * j + 1) * HWc + yy * Wc + xx] = hi;
    }
}

// ---------------- combine partials ----------------
__global__ __launch_bounds__(256)
void combine_kernel(const float* __restrict__ dp, float* __restrict__ out, int n4)
{
    int i = blockIdx.x * 256 + threadIdx.x;
    if (i < n4) {
        float4 a0 = reinterpret_cast<const float4*>(dp)[i];
        float4 a1 = reinterpret_cast<const float4*>(dp)[n4 + i];
        float4 a2 = reinterpret_cast<const float4*>(dp)[2 * n4 + i];
        float4 a3 = reinterpret_cast<const float4*>(dp)[3 * n4 + i];
        float4 o;
        o.x = (a0.x + a1.x) + (a2.x + a3.x);
        o.y = (a0.y + a1.y) + (a2.y + a3.y);
        o.z = (a0.z + a1.z) + (a2.z + a3.z);
        o.w = (a0.w + a1.w) + (a2.w + a3.w);
        reinterpret_cast<float4*>(out)[i] = o;
    }
}

// ---------------- launch ----------------
extern "C" void kernel_launch(void* const* d_in, const int* in_sizes, int n_in,
                              void* d_out, int out_size)
{
    const float* x    = (const float*)d_in[0];
    const float* ef   = (const float*)d_in[1];
    const float* flow = (const float*)d_in[2];
    const float* w1   = (const float*)d_in[3];
    const float* b1   = (const float*)d_in[4];
    const float* w2   = (const float*)d_in[5];
    const float* b2   = (const float*)d_in[6];
    const float* w3   = (const float*)d_in[7];
    const float* b3   = (const float*)d_in[8];
    const float* wgt  = (const float*)d_in[9];
    float* out = (float*)d_out;

    const int B = in_sizes[0] / (64 * HWc);  // = 2

    float *h1, *h2, *ppo, *pdp;
    cudaGetSymbolAddress((void**)&h1,  g_h1);
    cudaGetSymbolAddress((void**)&h2,  g_h2);
    cudaGetSymbolAddress((void**)&ppo, g_po);
    cudaGetSymbolAddress((void**)&pdp, g_dp);

    // conv1: 128 -> 64, leaky. PX=2, 16 outs/thread. Grid (4,8,B*4)=256 blocks
    conv3x3_kernel<128, 16, 4, 2, true, false><<<dim3(4, 8, B * 4), 256>>>(ef, w1, b1, h1, nullptr);
    // conv2: 64 -> 64, leaky
    conv3x3_kernel<64, 16, 4, 2, true, false><<<dim3(4, 8, B * 4), 256>>>(h1, w2, b2, h2, nullptr);
    // conv3: 64 -> 432, PX=4, 16 outs/thread. Grid (4,4,B*27)=864 blocks
    conv3x3_kernel<64, 16, 27, 4, false, true><<<dim3(4, 4, B * 27), 256>>>(h2, w3, b3, ppo, flow);
    // deformable gather + einsum, 4-way group split
    deform_kernel<<<dim3(8, 16, B * NSPLIT), 128>>>(x, ppo, wgt, pdp);
    // combine partial sums -> out
    int n4 = B * 64 * HWc / 4;
    combine_kernel<<<(n4 + 255) / 256, 256>>>(pdp, out, n4);
}

// round 5
// speedup vs baseline: 1.4409x; 1.4409x over previous
#include <cuda_runtime.h>

constexpr int Hc = 128, Wc = 128, HWc = Hc * Wc;

// ---------------- scratch (device globals; no allocation allowed) ----------------
__device__ float g_h1[2 * 64 * HWc];
__device__ float g_h2[2 * 64 * HWc];
__device__ float g_po[2 * 432 * HWc];
__device__ float g_xt[2 * 16 * HWc * 4];       // x transposed: [b][g][hw][4]
__device__ float g_dp[2 * 2 * 64 * HWc];       // [gsplit][b][co][hw]

// ---------------- packed f32x2 helpers ----------------
__device__ __forceinline__ unsigned long long pack2(float lo, float hi) {
    unsigned long long r;
    asm("mov.b64 %0, {%1, %2};" : "=l"(r) : "f"(lo), "f"(hi));
    return r;
}
__device__ __forceinline__ void unpack2(unsigned long long v, float& lo, float& hi) {
    asm("mov.b64 {%0, %1}, %2;" : "=f"(lo), "=f"(hi) : "l"(v));
}
__device__ __forceinline__ void fma2(unsigned long long& d, unsigned long long a, unsigned long long b) {
    asm("fma.rn.f32x2 %0, %1, %2, %0;" : "+l"(d) : "l"(a), "l"(b));
}

// ---------------- direct 3x3 conv (exact round-2 config), 2 pixels/thread ----------------
template <int CIN, int COUT_BLK, int NCOB, bool LEAKY, bool TRANSFORM>
__global__ __launch_bounds__(256)
void conv3x3_kernel(const float* __restrict__ in, const float* __restrict__ wgt,
                    const float* __restrict__ bias, float* __restrict__ out,
                    const float* __restrict__ flow)
{
    constexpr int TW = 32, THROWS = 16, CK = 8;
    constexpr int NACC = COUT_BLK / 2;
    constexpr int COUT_TOT = COUT_BLK * NCOB;

    __shared__ float s_in[CK][THROWS + 2][TW + 2];
    __shared__ float s_wt[CK * 9 * COUT_BLK];  // [ci][k][co]

    const int bz  = blockIdx.z;
    const int b   = bz / NCOB;
    const int coz = bz % NCOB;
    const int x0  = blockIdx.x * TW;
    const int y0  = blockIdx.y * THROWS;
    const int tid = threadIdx.x;
    const int tx  = tid % TW;
    const int ty  = tid / TW;
    const int xx  = x0 + tx;
    const int yy0 = y0 + ty, yy1 = y0 + ty + 8;

    unsigned long long acc0[NACC], acc1[NACC];
    {
        const float* bp = bias + coz * COUT_BLK;
        #pragma unroll
        for (int j = 0; j < NACC; j++) {
            unsigned long long bv = pack2(bp[2 * j], bp[2 * j + 1]);
            acc0[j] = bv; acc1[j] = bv;
        }
    }

    for (int cb = 0; cb < CIN; cb += CK) {
        __syncthreads();
        const float* ip = in + (b * CIN + cb) * HWc;
        #pragma unroll 1
        for (int i = tid; i < CK * (THROWS + 2) * (TW + 2); i += 256) {
            int lx = i % (TW + 2);
            int r  = i / (TW + 2);
            int ly = r % (THROWS + 2);
            int ci = r / (THROWS + 2);
            int gx = x0 + lx - 1, gy = y0 + ly - 1;
            float v = 0.f;
            if ((unsigned)gx < (unsigned)Wc && (unsigned)gy < (unsigned)Hc)
                v = ip[ci * HWc + gy * Wc + gx];
            s_in[ci][ly][lx] = v;
        }
        #pragma unroll 1
        for (int i = tid; i < CK * 9 * COUT_BLK; i += 256) {
            int co = i % COUT_BLK;
            int r  = i / COUT_BLK;
            int k  = r % 9;
            int ci = r / 9;
            s_wt[i] = wgt[((coz * COUT_BLK + co) * CIN + (cb + ci)) * 9 + k];
        }
        __syncthreads();

        #pragma unroll 1
        for (int ci = 0; ci < CK; ci++) {
            float v0[9], v1[9];
            #pragma unroll
            for (int dy = 0; dy < 3; dy++) {
                #pragma unroll
                for (int dx = 0; dx < 3; dx++) {
                    v0[dy * 3 + dx] = s_in[ci][ty + dy][tx + dx];
                    v1[dy * 3 + dx] = s_in[ci][ty + 8 + dy][tx + dx];
                }
            }
            #pragma unroll
            for (int k = 0; k < 9; k++) {
                unsigned long long vv0 = pack2(v0[k], v0[k]);
                unsigned long long vv1 = pack2(v1[k], v1[k]);
                const ulonglong2* wp =
                    reinterpret_cast<const ulonglong2*>(&s_wt[(ci * 9 + k) * COUT_BLK]);
                #pragma unroll
                for (int j = 0; j < NACC / 2; j++) {
                    ulonglong2 w2 = wp[j];
                    fma2(acc0[2 * j],     w2.x, vv0);
                    fma2(acc0[2 * j + 1], w2.y, vv0);
                    fma2(acc1[2 * j],     w2.x, vv1);
                    fma2(acc1[2 * j + 1], w2.y, vv1);
                }
            }
        }
    }

    float fy0 = 0.f, fx0 = 0.f, fy1 = 0.f, fx1 = 0.f;
    if (TRANSFORM) {
        fy0 = flow[(b * 2 + 1) * HWc + yy0 * Wc + xx];
        fx0 = flow[(b * 2 + 0) * HWc + yy0 * Wc + xx];
        fy1 = flow[(b * 2 + 1) * HWc + yy1 * Wc + xx];
        fx1 = flow[(b * 2 + 0) * HWc + yy1 * Wc + xx];
    }
    #pragma unroll
    for (int j = 0; j < NACC; j++) {
        float r00, r01, r10, r11;
        unpack2(acc0[j], r00, r01);
        unpack2(acc1[j], r10, r11);
        float rv0[2] = {r00, r01};
        float rv1[2] = {r10, r11};
        #pragma unroll
        for (int t = 0; t < 2; t++) {
            int co = coz * COUT_BLK + 2 * j + t;
            float a = rv0[t], c = rv1[t];
            if (LEAKY) {
                a = (a >= 0.f) ? a : 0.1f * a;
                c = (c >= 0.f) ? c : 0.1f * c;
            }
            if (TRANSFORM) {
                if (co < 288) {
                    a = 10.f * tanhf(a) + ((co & 1) ? fx0 : fy0);
                    c = 10.f * tanhf(c) + ((co & 1) ? fx1 : fy1);
                } else {
                    a = 1.f / (1.f + expf(-a));
                    c = 1.f / (1.f + expf(-c));
                }
            }
            out[(b * COUT_TOT + co) * HWc + yy0 * Wc + xx] = a;
            out[(b * COUT_TOT + co) * HWc + yy1 * Wc + xx] = c;
        }
    }
}

// ---------------- x transpose: [b][64][HW] -> [b][g][HW][4] ----------------
__global__ __launch_bounds__(256)
void transpose_kernel(const float* __restrict__ x, float* __restrict__ xt)
{
    int hw = blockIdx.x * 256 + threadIdx.x;
    int g  = blockIdx.y;
    int b  = blockIdx.z;
    const float* xp = x + (b * 64 + g * 4) * HWc + hw;
    float4 v;
    v.x = xp[0];
    v.y = xp[HWc];
    v.z = xp[2 * HWc];
    v.w = xp[3 * HWc];
    reinterpret_cast<float4*>(xt + ((b * 16 + g) * HWc + hw) * 4)[0] = v;
}

// ---------------- deformable gather + einsum ----------------
// Channel-split 2 (32 outs/block) x group-split 2 (8 groups/block).
// Grid (8,16,B*4), block 128 = 16x8 pixel tile. float4 gathers from xt.
__global__ __launch_bounds__(128)
void deform_kernel(const float* __restrict__ xt, const float* __restrict__ po,
                   const float* __restrict__ wgt, float* __restrict__ dp)
{
    __shared__ float s_wt[8 * 9 * 4 * 32];  // [gl][k][c][o] 36KB

    const int bz    = blockIdx.z;
    const int B     = gridDim.z / 4;
    const int b     = bz / 4;
    const int gsp   = (bz % 4) / 2;        // group split: 0 or 1
    const int csp   = bz % 2;              // channel split: 0 or 1
    const int g0    = gsp * 8;
    const int o0    = csp * 32;
    const int x0    = blockIdx.x * 16, y0 = blockIdx.y * 8;
    const int tid   = threadIdx.x;
    const int tx    = tid % 16, ty = tid / 16;
    const int xx    = x0 + tx, yy = y0 + ty;

    unsigned long long acc[16];
    #pragma unroll
    for (int j = 0; j < 16; j++) acc[j] = 0ULL;

    const float* pob = po + b * 432 * HWc + yy * Wc + xx;
    const float* xtb = xt + b * 16 * HWc * 4;

    #pragma unroll 1
    for (int i = tid; i < 8 * 9 * 4 * 32; i += 128) {
        int o = i & 31;
        int r = i >> 5;
        int c = r & 3;
        r >>= 2;
        int k  = r % 9;
        int gl = r / 9;
        s_wt[i] = wgt[((o0 + o) * 64 + (g0 + gl) * 4 + c) * 9 + k];
    }
    __syncthreads();

    #pragma unroll 1
    for (int gl = 0; gl < 8; gl++) {
        const int g = g0 + gl;
        const float4* xg = reinterpret_cast<const float4*>(xtb + g * HWc * 4);
        #pragma unroll 3
        for (int k = 0; k < 9; k++) {
            const int gk = g * 9 + k;
            float offy = pob[(2 * gk) * HWc];
            float offx = pob[(2 * gk + 1) * HWc];
            float msk  = pob[(288 + gk) * HWc];

            float py = (float)(yy + k / 3 - 1) + offy;
            float px = (float)(xx + k % 3 - 1) + offx;
            float fy = floorf(py), fxv = floorf(px);
            int iy0 = (int)fy, ix0 = (int)fxv;
            float wy = py - fy, wx = px - fxv;

            bool vy0 = (unsigned)iy0       < (unsigned)Hc;
            bool vy1 = (unsigned)(iy0 + 1) < (unsigned)Hc;
            bool vx0 = (unsigned)ix0       < (unsigned)Wc;
            bool vx1 = (unsigned)(ix0 + 1) < (unsigned)Wc;
            int cy0 = min(max(iy0, 0), Hc - 1), cy1 = min(max(iy0 + 1, 0), Hc - 1);
            int cx0 = min(max(ix0, 0), Wc - 1), cx1 = min(max(ix0 + 1, 0), Wc - 1);

            float w00 = (1.f - wy) * (1.f - wx) * msk; if (!(vy0 && vx0)) w00 = 0.f;
            float w01 = (1.f - wy) * wx        * msk; if (!(vy0 && vx1)) w01 = 0.f;
            float w10 = wy        * (1.f - wx) * msk; if (!(vy1 && vx0)) w10 = 0.f;
            float w11 = wy        * wx         * msk; if (!(vy1 && vx1)) w11 = 0.f;

            float4 p00 = __ldg(xg + cy0 * Wc + cx0);
            float4 p01 = __ldg(xg + cy0 * Wc + cx1);
            float4 p10 = __ldg(xg + cy1 * Wc + cx0);
            float4 p11 = __ldg(xg + cy1 * Wc + cx1);

            float val[4];
            val[0] = w00 * p00.x + w01 * p01.x + w10 * p10.x + w11 * p11.x;
            val[1] = w00 * p00.y + w01 * p01.y + w10 * p10.y + w11 * p11.y;
            val[2] = w00 * p00.z + w01 * p01.z + w10 * p10.z + w11 * p11.z;
            val[3] = w00 * p00.w + w01 * p01.w + w10 * p10.w + w11 * p11.w;

            #pragma unroll
            for (int c = 0; c < 4; c++) {
                unsigned long long vv = pack2(val[c], val[c]);
                const ulonglong2* wp = reinterpret_cast<const ulonglong2*>(
                    &s_wt[((gl * 9 + k) * 4 + c) * 32]);
                #pragma unroll
                for (int j = 0; j < 8; j++) {
                    ulonglong2 w2 = wp[j];
                    fma2(acc[2 * j],     w2.x, vv);
                    fma2(acc[2 * j + 1], w2.y, vv);
                }
            }
        }
    }

    // dp layout: [gsplit][b][co 0..63][hw]; csp picks co-half (no overlap)
    float* dpo = dp + (gsp * B + b) * 64 * HWc + o0 * HWc;
    #pragma unroll
    for (int j = 0; j < 16; j++) {
        float lo, hi;
        unpack2(acc[j], lo, hi);
        dpo[(2 * j)     * HWc + yy * Wc + xx] = lo;
        dpo[(2 * j + 1) * HWc + yy * Wc + xx] = hi;
    }
}

// ---------------- combine partials (2-way) ----------------
__global__ __launch_bounds__(256)
void combine_kernel(const float* __restrict__ dp, float* __restrict__ out, int n4)
{
    int i = blockIdx.x * 256 + threadIdx.x;
    if (i < n4) {
        float4 a = reinterpret_cast<const float4*>(dp)[i];
        float4 c = reinterpret_cast<const float4*>(dp)[n4 + i];
        float4 o;
        o.x = a.x + c.x; o.y = a.y + c.y; o.z = a.z + c.z; o.w = a.w + c.w;
        reinterpret_cast<float4*>(out)[i] = o;
    }
}

// ---------------- launch ----------------
extern "C" void kernel_launch(void* const* d_in, const int* in_sizes, int n_in,
                              void* d_out, int out_size)
{
    const float* x    = (const float*)d_in[0];
    const float* ef   = (const float*)d_in[1];
    const float* flow = (const float*)d_in[2];
    const float* w1   = (const float*)d_in[3];
    const float* b1   = (const float*)d_in[4];
    const float* w2   = (const float*)d_in[5];
    const float* b2   = (const float*)d_in[6];
    const float* w3   = (const float*)d_in[7];
    const float* b3   = (const float*)d_in[8];
    const float* wgt  = (const float*)d_in[9];
    float* out = (float*)d_out;

    const int B = in_sizes[0] / (64 * HWc);  // = 2

    float *h1, *h2, *ppo, *pxt, *pdp;
    cudaGetSymbolAddress((void**)&h1,  g_h1);
    cudaGetSymbolAddress((void**)&h2,  g_h2);
    cudaGetSymbolAddress((void**)&ppo, g_po);
    cudaGetSymbolAddress((void**)&pxt, g_xt);
    cudaGetSymbolAddress((void**)&pdp, g_dp);

    // transpose x to NHWC-per-group (independent of conv chain; run first)
    transpose_kernel<<<dim3(HWc / 256, 16, B), 256>>>(x, pxt);
    // conv1: 128 -> 64, leaky (round-2 config)
    conv3x3_kernel<128, 32, 2, true, false><<<dim3(4, 8, B * 2), 256>>>(ef, w1, b1, h1, nullptr);
    // conv2: 64 -> 64, leaky
    conv3x3_kernel<64, 32, 2, true, false><<<dim3(4, 8, B * 2), 256>>>(h1, w2, b2, h2, nullptr);
    // conv3: 64 -> 432, fused tanh/flow/sigmoid epilogue
    conv3x3_kernel<64, 24, 18, false, true><<<dim3(4, 8, B * 18), 256>>>(h2, w3, b3, ppo, flow);
    // deformable gather + einsum: channel-split 2 x group-split 2
    deform_kernel<<<dim3(8, 16, B * 4), 128>>>(pxt, ppo, wgt, pdp);
    // combine group-split partials -> out
    int n4 = B * 64 * HWc / 4;
    combine_kernel<<<(n4 + 255) / 256, 256>>>(pdp, out, n4);
}

// round 6
// speedup vs baseline: 1.6148x; 1.1207x over previous
#include <cuda_runtime.h>

constexpr int Hc = 128, Wc = 128, HWc = Hc * Wc;

// ---------------- scratch (device globals; no allocation allowed) ----------------
__device__ float g_h1[2 * 64 * HWc];
__device__ float g_h2[2 * 64 * HWc];
__device__ float g_po[2 * 432 * HWc];
__device__ float g_xt[2 * 16 * HWc * 4];       // x transposed: [b][g][hw][4]
__device__ float g_dp[2 * 2 * 64 * HWc];       // [gsplit][b][co][hw]

// ---------------- packed f32x2 helpers ----------------
__device__ __forceinline__ unsigned long long pack2(float lo, float hi) {
    unsigned long long r;
    asm("mov.b64 %0, {%1, %2};" : "=l"(r) : "f"(lo), "f"(hi));
    return r;
}
__device__ __forceinline__ void unpack2(unsigned long long v, float& lo, float& hi) {
    asm("mov.b64 {%0, %1}, %2;" : "=f"(lo), "=f"(hi) : "l"(v));
}
__device__ __forceinline__ void fma2(unsigned long long& d, unsigned long long a, unsigned long long b) {
    asm("fma.rn.f32x2 %0, %1, %2, %0;" : "+l"(d) : "l"(a), "l"(b));
}

// ---------------- direct 3x3 conv, smem-tiled, 2 pixels/thread, 3 blocks/SM ----------------
template <int CIN, int COUT_BLK, int NCOB, bool LEAKY, bool TRANSFORM>
__global__ __launch_bounds__(256, 3)
void conv3x3_kernel(const float* __restrict__ in, const float* __restrict__ wgt,
                    const float* __restrict__ bias, float* __restrict__ out,
                    const float* __restrict__ flow)
{
    constexpr int TW = 32, THROWS = 16, CK = 8;
    constexpr int NACC = COUT_BLK / 2;
    constexpr int COUT_TOT = COUT_BLK * NCOB;

    __shared__ float s_in[CK][THROWS + 2][TW + 2];
    __shared__ float s_wt[CK * 9 * COUT_BLK];  // [ci][k][co]

    const int bz  = blockIdx.z;
    const int b   = bz / NCOB;
    const int coz = bz % NCOB;
    const int x0  = blockIdx.x * TW;
    const int y0  = blockIdx.y * THROWS;
    const int tid = threadIdx.x;
    const int tx  = tid % TW;
    const int ty  = tid / TW;
    const int xx  = x0 + tx;
    const int yy0 = y0 + ty, yy1 = y0 + ty + 8;

    unsigned long long acc0[NACC], acc1[NACC];
    {
        const float* bp = bias + coz * COUT_BLK;
        #pragma unroll
        for (int j = 0; j < NACC; j++) {
            unsigned long long bv = pack2(bp[2 * j], bp[2 * j + 1]);
            acc0[j] = bv; acc1[j] = bv;
        }
    }

    for (int cb = 0; cb < CIN; cb += CK) {
        __syncthreads();
        const float* ip = in + (b * CIN + cb) * HWc;
        #pragma unroll 1
        for (int i = tid; i < CK * (THROWS + 2) * (TW + 2); i += 256) {
            int lx = i % (TW + 2);
            int r  = i / (TW + 2);
            int ly = r % (THROWS + 2);
            int ci = r / (THROWS + 2);
            int gx = x0 + lx - 1, gy = y0 + ly - 1;
            float v = 0.f;
            if ((unsigned)gx < (unsigned)Wc && (unsigned)gy < (unsigned)Hc)
                v = ip[ci * HWc + gy * Wc + gx];
            s_in[ci][ly][lx] = v;
        }
        #pragma unroll 1
        for (int i = tid; i < CK * 9 * COUT_BLK; i += 256) {
            int co = i % COUT_BLK;
            int r  = i / COUT_BLK;
            int k  = r % 9;
            int ci = r / 9;
            s_wt[i] = wgt[((coz * COUT_BLK + co) * CIN + (cb + ci)) * 9 + k];
        }
        __syncthreads();

        #pragma unroll 1
        for (int ci = 0; ci < CK; ci++) {
            float v0[9], v1[9];
            #pragma unroll
            for (int dy = 0; dy < 3; dy++) {
                #pragma unroll
                for (int dx = 0; dx < 3; dx++) {
                    v0[dy * 3 + dx] = s_in[ci][ty + dy][tx + dx];
                    v1[dy * 3 + dx] = s_in[ci][ty + 8 + dy][tx + dx];
                }
            }
            #pragma unroll
            for (int k = 0; k < 9; k++) {
                unsigned long long vv0 = pack2(v0[k], v0[k]);
                unsigned long long vv1 = pack2(v1[k], v1[k]);
                const ulonglong2* wp =
                    reinterpret_cast<const ulonglong2*>(&s_wt[(ci * 9 + k) * COUT_BLK]);
                #pragma unroll
                for (int j = 0; j < NACC / 2; j++) {
                    ulonglong2 w2 = wp[j];
                    fma2(acc0[2 * j],     w2.x, vv0);
                    fma2(acc0[2 * j + 1], w2.y, vv0);
                    fma2(acc1[2 * j],     w2.x, vv1);
                    fma2(acc1[2 * j + 1], w2.y, vv1);
                }
            }
        }
    }

    float fy0 = 0.f, fx0 = 0.f, fy1 = 0.f, fx1 = 0.f;
    if (TRANSFORM) {
        fy0 = flow[(b * 2 + 1) * HWc + yy0 * Wc + xx];
        fx0 = flow[(b * 2 + 0) * HWc + yy0 * Wc + xx];
        fy1 = flow[(b * 2 + 1) * HWc + yy1 * Wc + xx];
        fx1 = flow[(b * 2 + 0) * HWc + yy1 * Wc + xx];
    }
    #pragma unroll
    for (int j = 0; j < NACC; j++) {
        float r00, r01, r10, r11;
        unpack2(acc0[j], r00, r01);
        unpack2(acc1[j], r10, r11);
        float rv0[2] = {r00, r01};
        float rv1[2] = {r10, r11};
        #pragma unroll
        for (int t = 0; t < 2; t++) {
            int co = coz * COUT_BLK + 2 * j + t;
            float a = rv0[t], c = rv1[t];
            if (LEAKY) {
                a = (a >= 0.f) ? a : 0.1f * a;
                c = (c >= 0.f) ? c : 0.1f * c;
            }
            if (TRANSFORM) {
                if (co < 288) {
                    a = 10.f * tanhf(a) + ((co & 1) ? fx0 : fy0);
                    c = 10.f * tanhf(c) + ((co & 1) ? fx1 : fy1);
                } else {
                    a = 1.f / (1.f + expf(-a));
                    c = 1.f / (1.f + expf(-c));
                }
            }
            out[(b * COUT_TOT + co) * HWc + yy0 * Wc + xx] = a;
            out[(b * COUT_TOT + co) * HWc + yy1 * Wc + xx] = c;
        }
    }
}

// ---------------- x transpose: [b][64][HW] -> [b][g][HW][4] ----------------
__global__ __launch_bounds__(256)
void transpose_kernel(const float* __restrict__ x, float* __restrict__ xt)
{
    int hw = blockIdx.x * 256 + threadIdx.x;
    int g  = blockIdx.y;
    int b  = blockIdx.z;
    const float* xp = x + (b * 64 + g * 4) * HWc + hw;
    float4 v;
    v.x = xp[0];
    v.y = xp[HWc];
    v.z = xp[2 * HWc];
    v.w = xp[3 * HWc];
    reinterpret_cast<float4*>(xt + ((b * 16 + g) * HWc + hw) * 4)[0] = v;
}

// ---------------- deformable gather + einsum ----------------
// Channel-split 2 (32 outs/block) x group-split 2 (8 groups/block).
// Grid (8,16,B*4), block 128 = 16x8 pixel tile. float4 gathers from xt.
__global__ __launch_bounds__(128)
void deform_kernel(const float* __restrict__ xt, const float* __restrict__ po,
                   const float* __restrict__ wgt, float* __restrict__ dp)
{
    __shared__ float s_wt[8 * 9 * 4 * 32];  // [gl][k][c][o] 36KB

    const int bz    = blockIdx.z;
    const int B     = gridDim.z / 4;
    const int b     = bz / 4;
    const int gsp   = (bz % 4) / 2;        // group split: 0 or 1
    const int csp   = bz % 2;              // channel split: 0 or 1
    const int g0    = gsp * 8;
    const int o0    = csp * 32;
    const int x0    = blockIdx.x * 16, y0 = blockIdx.y * 8;
    const int tid   = threadIdx.x;
    const int tx    = tid % 16, ty = tid / 16;
    const int xx    = x0 + tx, yy = y0 + ty;

    unsigned long long acc[16];
    #pragma unroll
    for (int j = 0; j < 16; j++) acc[j] = 0ULL;

    const float* pob = po + b * 432 * HWc + yy * Wc + xx;
    const float* xtb = xt + b * 16 * HWc * 4;

    #pragma unroll 1
    for (int i = tid; i < 8 * 9 * 4 * 32; i += 128) {
        int o = i & 31;
        int r = i >> 5;
        int c = r & 3;
        r >>= 2;
        int k  = r % 9;
        int gl = r / 9;
        s_wt[i] = wgt[((o0 + o) * 64 + (g0 + gl) * 4 + c) * 9 + k];
    }
    __syncthreads();

    #pragma unroll 1
    for (int gl = 0; gl < 8; gl++) {
        const int g = g0 + gl;
        const float4* xg = reinterpret_cast<const float4*>(xtb + g * HWc * 4);
        #pragma unroll 3
        for (int k = 0; k < 9; k++) {
            const int gk = g * 9 + k;
            float offy = pob[(2 * gk) * HWc];
            float offx = pob[(2 * gk + 1) * HWc];
            float msk  = pob[(288 + gk) * HWc];

            float py = (float)(yy + k / 3 - 1) + offy;
            float px = (float)(xx + k % 3 - 1) + offx;
            float fy = floorf(py), fxv = floorf(px);
            int iy0 = (int)fy, ix0 = (int)fxv;
            float wy = py - fy, wx = px - fxv;

            bool vy0 = (unsigned)iy0       < (unsigned)Hc;
            bool vy1 = (unsigned)(iy0 + 1) < (unsigned)Hc;
            bool vx0 = (unsigned)ix0       < (unsigned)Wc;
            bool vx1 = (unsigned)(ix0 + 1) < (unsigned)Wc;
            int cy0 = min(max(iy0, 0), Hc - 1), cy1 = min(max(iy0 + 1, 0), Hc - 1);
            int cx0 = min(max(ix0, 0), Wc - 1), cx1 = min(max(ix0 + 1, 0), Wc - 1);

            float w00 = (1.f - wy) * (1.f - wx) * msk; if (!(vy0 && vx0)) w00 = 0.f;
            float w01 = (1.f - wy) * wx        * msk; if (!(vy0 && vx1)) w01 = 0.f;
            float w10 = wy        * (1.f - wx) * msk; if (!(vy1 && vx0)) w10 = 0.f;
            float w11 = wy        * wx         * msk; if (!(vy1 && vx1)) w11 = 0.f;

            float4 p00 = __ldg(xg + cy0 * Wc + cx0);
            float4 p01 = __ldg(xg + cy0 * Wc + cx1);
            float4 p10 = __ldg(xg + cy1 * Wc + cx0);
            float4 p11 = __ldg(xg + cy1 * Wc + cx1);

            float val[4];
            val[0] = w00 * p00.x + w01 * p01.x + w10 * p10.x + w11 * p11.x;
            val[1] = w00 * p00.y + w01 * p01.y + w10 * p10.y + w11 * p11.y;
            val[2] = w00 * p00.z + w01 * p01.z + w10 * p10.z + w11 * p11.z;
            val[3] = w00 * p00.w + w01 * p01.w + w10 * p10.w + w11 * p11.w;

            #pragma unroll
            for (int c = 0; c < 4; c++) {
                unsigned long long vv = pack2(val[c], val[c]);
                const ulonglong2* wp = reinterpret_cast<const ulonglong2*>(
                    &s_wt[((gl * 9 + k) * 4 + c) * 32]);
                #pragma unroll
                for (int j = 0; j < 8; j++) {
                    ulonglong2 w2 = wp[j];
                    fma2(acc[2 * j],     w2.x, vv);
                    fma2(acc[2 * j + 1], w2.y, vv);
                }
            }
        }
    }

    // dp layout: [gsplit][b][co 0..63][hw]; csp picks co-half (no overlap)
    float* dpo = dp + (gsp * B + b) * 64 * HWc + o0 * HWc;
    #pragma unroll
    for (int j = 0; j < 16; j++) {
        float lo, hi;
        unpack2(acc[j], lo, hi);
        dpo[(2 * j)     * HWc + yy * Wc + xx] = lo;
        dpo[(2 * j + 1) * HWc + yy * Wc + xx] = hi;
    }
}

// ---------------- combine partials (2-way) ----------------
__global__ __launch_bounds__(256)
void combine_kernel(const float* __restrict__ dp, float* __restrict__ out, int n4)
{
    int i = blockIdx.x * 256 + threadIdx.x;
    if (i < n4) {
        float4 a = reinterpret_cast<const float4*>(dp)[i];
        float4 c = reinterpret_cast<const float4*>(dp)[n4 + i];
        float4 o;
        o.x = a.x + c.x; o.y = a.y + c.y; o.z = a.z + c.z; o.w = a.w + c.w;
        reinterpret_cast<float4*>(out)[i] = o;
    }
}

// ---------------- launch ----------------
extern "C" void kernel_launch(void* const* d_in, const int* in_sizes, int n_in,
                              void* d_out, int out_size)
{
    const float* x    = (const float*)d_in[0];
    const float* ef   = (const float*)d_in[1];
    const float* flow = (const float*)d_in[2];
    const float* w1   = (const float*)d_in[3];
    const float* b1   = (const float*)d_in[4];
    const float* w2   = (const float*)d_in[5];
    const float* b2   = (const float*)d_in[6];
    const float* w3   = (const float*)d_in[7];
    const float* b3   = (const float*)d_in[8];
    const float* wgt  = (const float*)d_in[9];
    float* out = (float*)d_out;

    const int B = in_sizes[0] / (64 * HWc);  // = 2

    float *h1, *h2, *ppo, *pxt, *pdp;
    cudaGetSymbolAddress((void**)&h1,  g_h1);
    cudaGetSymbolAddress((void**)&h2,  g_h2);
    cudaGetSymbolAddress((void**)&ppo, g_po);
    cudaGetSymbolAddress((void**)&pxt, g_xt);
    cudaGetSymbolAddress((void**)&pdp, g_dp);

    // transpose x to NHWC-per-group (independent of conv chain; run first)
    transpose_kernel<<<dim3(HWc / 256, 16, B), 256>>>(x, pxt);
    // conv1: 128 -> 64, leaky. 256 blocks, fills the chip
    conv3x3_kernel<128, 16, 4, true, false><<<dim3(4, 8, B * 4), 256>>>(ef, w1, b1, h1, nullptr);
    // conv2: 64 -> 64, leaky. 256 blocks
    conv3x3_kernel<64, 16, 4, true, false><<<dim3(4, 8, B * 4), 256>>>(h1, w2, b2, h2, nullptr);
    // conv3: 64 -> 432, fused tanh/flow/sigmoid epilogue. 1152 blocks, 3/SM
    conv3x3_kernel<64, 24, 18, false, true><<<dim3(4, 8, B * 18), 256>>>(h2, w3, b3, ppo, flow);
    // deformable gather + einsum: channel-split 2 x group-split 2
    deform_kernel<<<dim3(8, 16, B * 4), 128>>>(pxt, ppo, wgt, pdp);
    // combine group-split partials -> out
    int n4 = B * 64 * HWc / 4;
    combine_kernel<<<(n4 + 255) / 256, 256>>>(pdp, out, n4);
}

// round 10
// speedup vs baseline: 2.1606x; 1.3380x over previous
#include <cuda_runtime.h>
#include <cuda_bf16.h>
#include <cstdint>

constexpr int Hc = 128, Wc = 128, HWc = Hc * Wc;
constexpr int HP = 130;   // padded h2 spatial dim

// ---------------- scratch (device globals; no allocation allowed) ----------------
__device__ float g_h1[2 * 64 * HWc];
__device__ float g_po[2 * 432 * HWc];
__device__ float g_xt[2 * 16 * HWc * 4];            // x transposed: [b][g][hw][4]
__device__ float g_dp[2 * 2 * 64 * HWc];            // [gsplit][b][co][hw]
__device__ __nv_bfloat16 g_h2ph[2 * HP * HP * 64];  // h2 padded HWC, bf16 hi
__device__ __nv_bfloat16 g_h2pl[2 * HP * HP * 64];  // h2 padded HWC, bf16 lo
__device__ __nv_bfloat16 g_w3bh[9 * 432 * 64];      // w3 [k][co][ci] bf16 hi
__device__ __nv_bfloat16 g_w3bl[9 * 432 * 64];      // w3 [k][co][ci] bf16 lo

// ---------------- packed f32x2 helpers ----------------
__device__ __forceinline__ unsigned long long pack2(float lo, float hi) {
    unsigned long long r;
    asm("mov.b64 %0, {%1, %2};" : "=l"(r) : "f"(lo), "f"(hi));
    return r;
}
__device__ __forceinline__ void unpack2(unsigned long long v, float& lo, float& hi) {
    asm("mov.b64 {%0, %1}, %2;" : "=f"(lo), "=f"(hi) : "l"(v));
}
__device__ __forceinline__ void fma2(unsigned long long& d, unsigned long long a, unsigned long long b) {
    asm("fma.rn.f32x2 %0, %1, %2, %0;" : "+l"(d) : "l"(a), "l"(b));
}

// ---------------- warp MMA helpers (arch-neutral PTX, compiles for compute_103) ----------------
__device__ __forceinline__ uint32_t smem_to_u32(const void* p) {
    uint32_t a;
    asm("{ .reg .u64 t; cvta.to.shared.u64 t, %1; cvt.u32.u64 %0, t; }" : "=r"(a) : "l"(p));
    return a;
}
__device__ __forceinline__ void ldsm_x4(uint32_t (&r)[4], uint32_t addr) {
    asm volatile("ldmatrix.sync.aligned.m8n8.x4.shared.b16 {%0,%1,%2,%3}, [%4];"
        : "=r"(r[0]), "=r"(r[1]), "=r"(r[2]), "=r"(r[3]) : "r"(addr));
}
__device__ __forceinline__ void ldsm_x2(uint32_t (&r)[2], uint32_t addr) {
    asm volatile("ldmatrix.sync.aligned.m8n8.x2.shared.b16 {%0,%1}, [%2];"
        : "=r"(r[0]), "=r"(r[1]) : "r"(addr));
}
__device__ __forceinline__ void mma_bf16(float (&c)[4], const uint32_t (&a)[4], const uint32_t (&bb)[2]) {
    asm volatile("mma.sync.aligned.m16n8k16.row.col.f32.bf16.bf16.f32 "
        "{%0,%1,%2,%3}, {%4,%5,%6,%7}, {%8,%9}, {%0,%1,%2,%3};"
        : "+f"(c[0]), "+f"(c[1]), "+f"(c[2]), "+f"(c[3])
        : "r"(a[0]), "r"(a[1]), "r"(a[2]), "r"(a[3]), "r"(bb[0]), "r"(bb[1]));
}

// ---------------- direct 3x3 conv (FFMA2), 2 pixels/thread ----------------
template <int CIN, int COUT_BLK, int NCOB, bool LEAKY, bool BF16OUT>
__global__ __launch_bounds__(256, 3)
void conv3x3_kernel(const float* __restrict__ in, const float* __restrict__ wgt,
                    const float* __restrict__ bias, float* __restrict__ out,
                    __nv_bfloat16* __restrict__ outh, __nv_bfloat16* __restrict__ outl)
{
    constexpr int TW = 32, THROWS = 16, CK = 8;
    constexpr int NACC = COUT_BLK / 2;
    constexpr int COUT_TOT = COUT_BLK * NCOB;

    __shared__ float s_in[CK][THROWS + 2][TW + 2];
    __shared__ float s_wt[CK * 9 * COUT_BLK];

    const int bz  = blockIdx.z;
    const int b   = bz / NCOB;
    const int coz = bz % NCOB;
    const int x0  = blockIdx.x * TW;
    const int y0  = blockIdx.y * THROWS;
    const int tid = threadIdx.x;
    const int tx  = tid % TW;
    const int ty  = tid / TW;
    const int xx  = x0 + tx;

    unsigned long long acc0[NACC], acc1[NACC];
    {
        const float* bp = bias + coz * COUT_BLK;
        #pragma unroll
        for (int j = 0; j < NACC; j++) {
            unsigned long long bv = pack2(bp[2 * j], bp[2 * j + 1]);
            acc0[j] = bv; acc1[j] = bv;
        }
    }

    for (int cb = 0; cb < CIN; cb += CK) {
        __syncthreads();
        const float* ip = in + (b * CIN + cb) * HWc;
        #pragma unroll 1
        for (int i = tid; i < CK * (THROWS + 2) * (TW + 2); i += 256) {
            int lx = i % (TW + 2);
            int r  = i / (TW + 2);
            int ly = r % (THROWS + 2);
            int ci = r / (THROWS + 2);
            int gx = x0 + lx - 1, gy = y0 + ly - 1;
            float v = 0.f;
            if ((unsigned)gx < (unsigned)Wc && (unsigned)gy < (unsigned)Hc)
                v = ip[ci * HWc + gy * Wc + gx];
            s_in[ci][ly][lx] = v;
        }
        #pragma unroll 1
        for (int i = tid; i < CK * 9 * COUT_BLK; i += 256) {
            int co = i % COUT_BLK;
            int r  = i / COUT_BLK;
            int k  = r % 9;
            int ci = r / 9;
            s_wt[i] = wgt[((coz * COUT_BLK + co) * CIN + (cb + ci)) * 9 + k];
        }
        __syncthreads();

        #pragma unroll 1
        for (int ci = 0; ci < CK; ci++) {
            float v0[9], v1[9];
            #pragma unroll
            for (int dy = 0; dy < 3; dy++) {
                #pragma unroll
                for (int dx = 0; dx < 3; dx++) {
                    v0[dy * 3 + dx] = s_in[ci][ty + dy][tx + dx];
                    v1[dy * 3 + dx] = s_in[ci][ty + 8 + dy][tx + dx];
                }
            }
            #pragma unroll
            for (int k = 0; k < 9; k++) {
                unsigned long long vv0 = pack2(v0[k], v0[k]);
                unsigned long long vv1 = pack2(v1[k], v1[k]);
                const ulonglong2* wp =
                    reinterpret_cast<const ulonglong2*>(&s_wt[(ci * 9 + k) * COUT_BLK]);
                #pragma unroll
                for (int j = 0; j < NACC / 2; j++) {
                    ulonglong2 w2 = wp[j];
                    fma2(acc0[2 * j],     w2.x, vv0);
                    fma2(acc0[2 * j + 1], w2.y, vv0);
                    fma2(acc1[2 * j],     w2.x, vv1);
                    fma2(acc1[2 * j + 1], w2.y, vv1);
                }
            }
        }
    }

    #pragma unroll
    for (int pp = 0; pp < 2; pp++) {
        const int yy = y0 + ty + 8 * pp;
        #pragma unroll
        for (int j = 0; j < NACC; j++) {
            float r0, r1;
            if (pp == 0) unpack2(acc0[j], r0, r1); else unpack2(acc1[j], r0, r1);
            float rv[2] = {r0, r1};
            #pragma unroll
            for (int t = 0; t < 2; t++) {
                int co = coz * COUT_BLK + 2 * j + t;
                float a = rv[t];
                if (LEAKY) a = (a >= 0.f) ? a : 0.1f * a;
                if (BF16OUT) {
                    size_t base = ((size_t)b * HP * HP + (size_t)(yy + 1) * HP + (xx + 1)) * 64 + co;
                    __nv_bfloat16 h = __float2bfloat16(a);
                    __nv_bfloat16 l = __float2bfloat16(a - __bfloat162float(h));
                    outh[base] = h;
                    outl[base] = l;
                } else {
                    out[(b * COUT_TOT + co) * HWc + yy * Wc + xx] = a;
                }
            }
        }
    }
}

// ---------------- zero-fill h2 padded buffers ----------------
__global__ __launch_bounds__(256)
void fill0_kernel(__nv_bfloat16* a, __nv_bfloat16* c, int n4)
{
    int i = blockIdx.x * 256 + threadIdx.x;
    uint4 z = {0u, 0u, 0u, 0u};
    if (i < n4) {
        reinterpret_cast<uint4*>(a)[i] = z;
        reinterpret_cast<uint4*>(c)[i] = z;
    }
}

// ---------------- w3 -> bf16 hi/lo [k][co][ci] ----------------
__global__ __launch_bounds__(256)
void wprep_kernel(const float* __restrict__ w3, __nv_bfloat16* __restrict__ wh,
                  __nv_bfloat16* __restrict__ wl)
{
    int idx = blockIdx.x * 256 + threadIdx.x;
    if (idx < 9 * 432 * 64) {
        int ci = idx & 63;
        int t  = idx >> 6;
        int co = t % 432;
        int k  = t / 432;
        float v = w3[(co * 64 + ci) * 9 + k];
        __nv_bfloat16 h = __float2bfloat16(v);
        __nv_bfloat16 l = __float2bfloat16(v - __bfloat162float(h));
        wh[idx] = h;
        wl[idx] = l;
    }
}

// ---------------- conv3 via warp MMA (bf16 hi/lo split), fused epilogue ----------------
// Grid (Hc, 3, B), block 512 = 16 warps (8 M x 2 N). CTA tile: M=128 pixels (one row),
// N=144 couts, K=576 (9 taps x 4 k16) x 3 hi/lo combos.
// Smem (dynamic): Ah[128][72], Al[128][72], Bh[144][72], Bl[144][72] bf16, 144B row stride
// (conflict-free for ldmatrix).
constexpr int A_STRIDE_B = 144;                    // bytes per smem row (72 bf16)
constexpr int OFF_AH3 = 0;
constexpr int OFF_AL3 = 128 * A_STRIDE_B;          // 18432
constexpr int OFF_BH3 = OFF_AL3 + 128 * A_STRIDE_B;   // 36864
constexpr int OFF_BL3 = OFF_BH3 + 144 * A_STRIDE_B;   // 57600
constexpr int SMEM3_TOTAL = OFF_BL3 + 144 * A_STRIDE_B;  // 78336

__global__ __launch_bounds__(512)
void conv3_hmma_kernel(const __nv_bfloat16* __restrict__ h2ph, const __nv_bfloat16* __restrict__ h2pl,
                       const __nv_bfloat16* __restrict__ wbh, const __nv_bfloat16* __restrict__ wbl,
                       const float* __restrict__ b3, const float* __restrict__ flow,
                       float* __restrict__ po)
{
    extern __shared__ char smem[];
    const uint32_t sbase = smem_to_u32(smem);
    const int tid  = threadIdx.x;
    const int wid  = tid / 32;
    const int lane = tid % 32;
    const int mw   = wid / 2;          // 0..7  (M warp: rows mw*16..+16)
    const int wn   = wid % 2;          // 0..1  (N warp: cols wn*72..+72)
    const int y    = blockIdx.x;
    const int nt   = blockIdx.y;       // N tile: couts nt*144..+144
    const int b    = blockIdx.z;

    float C[9][4];
    #pragma unroll
    for (int j = 0; j < 9; j++)
        #pragma unroll
        for (int r = 0; r < 4; r++) C[j][r] = 0.f;

    // per-lane ldmatrix source addresses (row parts independent of tap/chunk)
    const int a_row = mw * 16 + (lane & 15);
    const int a_khalf = (lane & 16) ? 16 : 0;              // +8 bf16 -> +16B
    const int bl15 = lane & 15;
    const int b_rowin = bl15 & 7;
    const int b_khalf = (bl15 & 8) ? 16 : 0;

    #pragma unroll 1
    for (int tap = 0; tap < 9; tap++) {
        const int dy = tap / 3, dx = tap % 3;
        __syncthreads();
        // load A: 128 rows x 64 ch, hi+lo (row = pixel x, 64 ch contiguous in gmem)
        const size_t abase = ((size_t)(b * HP + y + dy) * HP + dx) * 64;
        const uint4* gAh = reinterpret_cast<const uint4*>(h2ph + abase);
        const uint4* gAl = reinterpret_cast<const uint4*>(h2pl + abase);
        #pragma unroll 1
        for (int i = tid; i < 2048; i += 512) {
            int buf = i >> 10, rem = i & 1023, r = rem >> 3, c = rem & 7;
            uint4 v = (buf ? gAl : gAh)[r * 8 + c];
            *reinterpret_cast<uint4*>(smem + (buf ? OFF_AL3 : OFF_AH3) + r * A_STRIDE_B + c * 16) = v;
        }
        // load B: 144 rows (couts) x 64 ch, hi+lo
        const uint4* gBh = reinterpret_cast<const uint4*>(wbh + ((size_t)tap * 432 + nt * 144) * 64);
        const uint4* gBl = reinterpret_cast<const uint4*>(wbl + ((size_t)tap * 432 + nt * 144) * 64);
        #pragma unroll 1
        for (int i = tid; i < 2304; i += 512) {
            int buf = (i >= 1152) ? 1 : 0;
            int j2  = buf ? i - 1152 : i;
            int r = j2 >> 3, c = j2 & 7;
            uint4 v = (buf ? gBl : gBh)[r * 8 + c];
            *reinterpret_cast<uint4*>(smem + (buf ? OFF_BL3 : OFF_BH3) + r * A_STRIDE_B + c * 16) = v;
        }
        __syncthreads();

        #pragma unroll
        for (int kc = 0; kc < 4; kc++) {
            const int k0b = kc * 32;   // 16 bf16 = 32 bytes per chunk
            uint32_t a_h[4], a_l[4];
            ldsm_x4(a_h, sbase + OFF_AH3 + a_row * A_STRIDE_B + k0b + a_khalf);
            ldsm_x4(a_l, sbase + OFF_AL3 + a_row * A_STRIDE_B + k0b + a_khalf);
            #pragma unroll
            for (int j = 0; j < 9; j++) {
                const int brow = wn * 72 + j * 8 + b_rowin;
                uint32_t b_h[2], b_l[2];
                ldsm_x2(b_h, sbase + OFF_BH3 + brow * A_STRIDE_B + k0b + b_khalf);
                ldsm_x2(b_l, sbase + OFF_BL3 + brow * A_STRIDE_B + k0b + b_khalf);
                mma_bf16(C[j], a_h, b_h);
                mma_bf16(C[j], a_h, b_l);
                mma_bf16(C[j], a_l, b_h);
            }
        }
    }

    // epilogue: fragment (g,t) -> pixels (mw*16+g, +8), couts nt*144 + wn*72 + j*8 + t*2 + {0,1}
    const int g = lane >> 2, t = lane & 3;
    const int hw0 = y * Wc + mw * 16 + g;
    const int hw1 = hw0 + 8;
    const float fy0 = flow[(b * 2 + 1) * HWc + hw0];
    const float fx0 = flow[(b * 2 + 0) * HWc + hw0];
    const float fy1 = flow[(b * 2 + 1) * HWc + hw1];
    const float fx1 = flow[(b * 2 + 0) * HWc + hw1];
    #pragma unroll
    for (int j = 0; j < 9; j++) {
        const int cobase = nt * 144 + wn * 72 + j * 8 + t * 2;
        #pragma unroll
        for (int r = 0; r < 4; r++) {
            const int co = cobase + (r & 1);
            const int hw = (r < 2) ? hw0 : hw1;
            float v = C[j][r] + __ldg(&b3[co]);
            if (co < 288) {
                const float fyv = (r < 2) ? fy0 : fy1;
                const float fxv = (r < 2) ? fx0 : fx1;
                v = 10.f * tanhf(v) + ((co & 1) ? fxv : fyv);
            } else {
                v = 1.f / (1.f + expf(-v));
            }
            po[((size_t)b * 432 + co) * HWc + hw] = v;
        }
    }
}

// ---------------- x transpose: [b][64][HW] -> [b][g][HW][4] ----------------
__global__ __launch_bounds__(256)
void transpose_kernel(const float* __restrict__ x, float* __restrict__ xt)
{
    int hw = blockIdx.x * 256 + threadIdx.x;
    int g  = blockIdx.y;
    int b  = blockIdx.z;
    const float* xp = x + (b * 64 + g * 4) * HWc + hw;
    float4 v;
    v.x = xp[0];
    v.y = xp[HWc];
    v.z = xp[2 * HWc];
    v.w = xp[3 * HWc];
    reinterpret_cast<float4*>(xt + ((b * 16 + g) * HWc + hw) * 4)[0] = v;
}

// ---------------- deformable gather + einsum ----------------
__global__ __launch_bounds__(128)
void deform_kernel(const float* __restrict__ xt, const float* __restrict__ po,
                   const float* __restrict__ wgt, float* __restrict__ dp)
{
    __shared__ float s_wt[8 * 9 * 4 * 32];

    const int bz    = blockIdx.z;
    const int B     = gridDim.z / 4;
    const int b     = bz / 4;
    const int gsp   = (bz % 4) / 2;
    const int csp   = bz % 2;
    const int g0    = gsp * 8;
    const int o0    = csp * 32;
    const int x0    = blockIdx.x * 16, y0 = blockIdx.y * 8;
    const int tid   = threadIdx.x;
    const int tx    = tid % 16, ty = tid / 16;
    const int xx    = x0 + tx, yy = y0 + ty;

    unsigned long long acc[16];
    #pragma unroll
    for (int j = 0; j < 16; j++) acc[j] = 0ULL;

    const float* pob = po + b * 432 * HWc + yy * Wc + xx;
    const float* xtb = xt + b * 16 * HWc * 4;

    #pragma unroll 1
    for (int i = tid; i < 8 * 9 * 4 * 32; i += 128) {
        int o = i & 31;
        int r = i >> 5;
        int c = r & 3;
        r >>= 2;
        int k  = r % 9;
        int gl = r / 9;
        s_wt[i] = wgt[((o0 + o) * 64 + (g0 + gl) * 4 + c) * 9 + k];
    }
    __syncthreads();

    #pragma unroll 1
    for (int gl = 0; gl < 8; gl++) {
        const int g = g0 + gl;
        const float4* xg = reinterpret_cast<const float4*>(xtb + g * HWc * 4);
        #pragma unroll 3
        for (int k = 0; k < 9; k++) {
            const int gk = g * 9 + k;
            float offy = pob[(2 * gk) * HWc];
            float offx = pob[(2 * gk + 1) * HWc];
            float msk  = pob[(288 + gk) * HWc];

            float py = (float)(yy + k / 3 - 1) + offy;
            float px = (float)(xx + k % 3 - 1) + offx;
            float fy = floorf(py), fxv = floorf(px);
            int iy0 = (int)fy, ix0 = (int)fxv;
            float wy = py - fy, wx = px - fxv;

            bool vy0 = (unsigned)iy0       < (unsigned)Hc;
            bool vy1 = (unsigned)(iy0 + 1) < (unsigned)Hc;
            bool vx0 = (unsigned)ix0       < (unsigned)Wc;
            bool vx1 = (unsigned)(ix0 + 1) < (unsigned)Wc;
            int cy0 = min(max(iy0, 0), Hc - 1), cy1 = min(max(iy0 + 1, 0), Hc - 1);
            int cx0 = min(max(ix0, 0), Wc - 1), cx1 = min(max(ix0 + 1, 0), Wc - 1);

            float w00 = (1.f - wy) * (1.f - wx) * msk; if (!(vy0 && vx0)) w00 = 0.f;
            float w01 = (1.f - wy) * wx        * msk; if (!(vy0 && vx1)) w01 = 0.f;
            float w10 = wy        * (1.f - wx) * msk; if (!(vy1 && vx0)) w10 = 0.f;
            float w11 = wy        * wx         * msk; if (!(vy1 && vx1)) w11 = 0.f;

            float4 p00 = __ldg(xg + cy0 * Wc + cx0);
            float4 p01 = __ldg(xg + cy0 * Wc + cx1);
            float4 p10 = __ldg(xg + cy1 * Wc + cx0);
            float4 p11 = __ldg(xg + cy1 * Wc + cx1);

            float val[4];
            val[0] = w00 * p00.x + w01 * p01.x + w10 * p10.x + w11 * p11.x;
            val[1] = w00 * p00.y + w01 * p01.y + w10 * p10.y + w11 * p11.y;
            val[2] = w00 * p00.z + w01 * p01.z + w10 * p10.z + w11 * p11.z;
            val[3] = w00 * p00.w + w01 * p01.w + w10 * p10.w + w11 * p11.w;

            #pragma unroll
            for (int c = 0; c < 4; c++) {
                unsigned long long vv = pack2(val[c], val[c]);
                const ulonglong2* wp = reinterpret_cast<const ulonglong2*>(
                    &s_wt[((gl * 9 + k) * 4 + c) * 32]);
                #pragma unroll
                for (int j = 0; j < 8; j++) {
                    ulonglong2 w2 = wp[j];
                    fma2(acc[2 * j],     w2.x, vv);
                    fma2(acc[2 * j + 1], w2.y, vv);
                }
            }
        }
    }

    float* dpo = dp + (gsp * B + b) * 64 * HWc + o0 * HWc;
    #pragma unroll
    for (int j = 0; j < 16; j++) {
        float lo, hi;
        unpack2(acc[j], lo, hi);
        dpo[(2 * j)     * HWc + yy * Wc + xx] = lo;
        dpo[(2 * j + 1) * HWc + yy * Wc + xx] = hi;
    }
}

// ---------------- combine partials (2-way) ----------------
__global__ __launch_bounds__(256)
void combine_kernel(const float* __restrict__ dp, float* __restrict__ out, int n4)
{
    int i = blockIdx.x * 256 + threadIdx.x;
    if (i < n4) {
        float4 a = reinterpret_cast<const float4*>(dp)[i];
        float4 c = reinterpret_cast<const float4*>(dp)[n4 + i];
        float4 o;
        o.x = a.x + c.x; o.y = a.y + c.y; o.z = a.z + c.z; o.w = a.w + c.w;
        reinterpret_cast<float4*>(out)[i] = o;
    }
}

// ---------------- launch ----------------
extern "C" void kernel_launch(void* const* d_in, const int* in_sizes, int n_in,
                              void* d_out, int out_size)
{
    const float* x    = (const float*)d_in[0];
    const float* ef   = (const float*)d_in[1];
    const float* flow = (const float*)d_in[2];
    const float* w1   = (const float*)d_in[3];
    const float* b1   = (const float*)d_in[4];
    const float* w2   = (const float*)d_in[5];
    const float* b2   = (const float*)d_in[6];
    const float* w3   = (const float*)d_in[7];
    const float* b3   = (const float*)d_in[8];
    const float* wgt  = (const float*)d_in[9];
    float* out = (float*)d_out;

    const int B = in_sizes[0] / (64 * HWc);  // = 2

    float *h1, *ppo, *pxt, *pdp;
    __nv_bfloat16 *ph2h, *ph2l, *pwbh, *pwbl;
    cudaGetSymbolAddress((void**)&h1,   g_h1);
    cudaGetSymbolAddress((void**)&ppo,  g_po);
    cudaGetSymbolAddress((void**)&pxt,  g_xt);
    cudaGetSymbolAddress((void**)&pdp,  g_dp);
    cudaGetSymbolAddress((void**)&ph2h, g_h2ph);
    cudaGetSymbolAddress((void**)&ph2l, g_h2pl);
    cudaGetSymbolAddress((void**)&pwbh, g_w3bh);
    cudaGetSymbolAddress((void**)&pwbl, g_w3bl);

    cudaFuncSetAttribute(conv3_hmma_kernel, cudaFuncAttributeMaxDynamicSharedMemorySize, SMEM3_TOTAL);

    // independent prep
    transpose_kernel<<<dim3(HWc / 256, 16, B), 256>>>(x, pxt);
    int nfill = 2 * HP * HP * 64 * 2 / 16;    // uint4 count per bf16 array
    fill0_kernel<<<(nfill + 255) / 256, 256>>>(ph2h, ph2l, nfill);
    wprep_kernel<<<(9 * 432 * 64 + 255) / 256, 256>>>(w3, pwbh, pwbl);
    // conv1: 128 -> 64, leaky, fp32 CHW
    conv3x3_kernel<128, 16, 4, true, false><<<dim3(4, 8, B * 4), 256>>>(ef, w1, b1, h1, nullptr, nullptr);
    // conv2: 64 -> 64, leaky, bf16 hi/lo padded HWC
    conv3x3_kernel<64, 16, 4, true, true><<<dim3(4, 8, B * 4), 256>>>(h1, w2, b2, nullptr, ph2h, ph2l);
    // conv3 via warp MMA: 64 -> 432 + fused tanh/flow/sigmoid epilogue
    conv3_hmma_kernel<<<dim3(Hc, 3, B), 512, SMEM3_TOTAL>>>(ph2h, ph2l, pwbh, pwbl, b3, flow, ppo);
    // deformable gather + einsum
    deform_kernel<<<dim3(8, 16, B * 4), 128>>>(pxt, ppo, wgt, pdp);
    // combine
    int n4 = B * 64 * HWc / 4;
    combine_kernel<<<(n4 + 255) / 256, 256>>>(pdp, out, n4);
}

// round 11
// speedup vs baseline: 2.7008x; 1.2500x over previous
#include <cuda_runtime.h>
#include <cuda_bf16.h>
#include <cstdint>

constexpr int Hc = 128, Wc = 128, HWc = Hc * Wc;
constexpr int HP = 130;   // padded spatial dim

// ---------------- scratch (device globals; no allocation allowed) ----------------
__device__ float g_po[2 * 432 * HWc];
__device__ float g_xt[2 * 16 * HWc * 4];             // x transposed: [b][g][hw][4]
__device__ float g_dp[2 * 2 * 64 * HWc];             // [gsplit][b][co][hw]
__device__ __nv_bfloat16 g_efph[2 * HP * HP * 128];  // extra_feat padded HWC hi
__device__ __nv_bfloat16 g_efpl[2 * HP * HP * 128];  // extra_feat padded HWC lo
__device__ __nv_bfloat16 g_h1ph[2 * HP * HP * 64];
__device__ __nv_bfloat16 g_h1pl[2 * HP * HP * 64];
__device__ __nv_bfloat16 g_h2ph[2 * HP * HP * 64];
__device__ __nv_bfloat16 g_h2pl[2 * HP * HP * 64];
__device__ __nv_bfloat16 g_w1bh[9 * 64 * 128];
__device__ __nv_bfloat16 g_w1bl[9 * 64 * 128];
__device__ __nv_bfloat16 g_w2bh[9 * 64 * 64];
__device__ __nv_bfloat16 g_w2bl[9 * 64 * 64];
__device__ __nv_bfloat16 g_w3bh[9 * 432 * 64];
__device__ __nv_bfloat16 g_w3bl[9 * 432 * 64];

// ---------------- packed f32x2 helpers ----------------
__device__ __forceinline__ unsigned long long pack2(float lo, float hi) {
    unsigned long long r;
    asm("mov.b64 %0, {%1, %2};" : "=l"(r) : "f"(lo), "f"(hi));
    return r;
}
__device__ __forceinline__ void unpack2(unsigned long long v, float& lo, float& hi) {
    asm("mov.b64 {%0, %1}, %2;" : "=f"(lo), "=f"(hi) : "l"(v));
}
__device__ __forceinline__ void fma2(unsigned long long& d, unsigned long long a, unsigned long long b) {
    asm("fma.rn.f32x2 %0, %1, %2, %0;" : "+l"(d) : "l"(a), "l"(b));
}

// ---------------- warp MMA helpers (arch-neutral PTX) ----------------
__device__ __forceinline__ uint32_t smem_to_u32(const void* p) {
    uint32_t a;
    asm("{ .reg .u64 t; cvta.to.shared.u64 t, %1; cvt.u32.u64 %0, t; }" : "=r"(a) : "l"(p));
    return a;
}
__device__ __forceinline__ void ldsm_x4(uint32_t (&r)[4], uint32_t addr) {
    asm volatile("ldmatrix.sync.aligned.m8n8.x4.shared.b16 {%0,%1,%2,%3}, [%4];"
        : "=r"(r[0]), "=r"(r[1]), "=r"(r[2]), "=r"(r[3]) : "r"(addr));
}
__device__ __forceinline__ void ldsm_x2(uint32_t (&r)[2], uint32_t addr) {
    asm volatile("ldmatrix.sync.aligned.m8n8.x2.shared.b16 {%0,%1}, [%2];"
        : "=r"(r[0]), "=r"(r[1]) : "r"(addr));
}
__device__ __forceinline__ void mma_bf16(float (&c)[4], const uint32_t (&a)[4], const uint32_t (&bb)[2]) {
    asm volatile("mma.sync.aligned.m16n8k16.row.col.f32.bf16.bf16.f32 "
        "{%0,%1,%2,%3}, {%4,%5,%6,%7}, {%8,%9}, {%0,%1,%2,%3};"
        : "+f"(c[0]), "+f"(c[1]), "+f"(c[2]), "+f"(c[3])
        : "r"(a[0]), "r"(a[1]), "r"(a[2]), "r"(a[3]), "r"(bb[0]), "r"(bb[1]));
}

// ---------------- fills & preps ----------------
__global__ __launch_bounds__(256)
void fill0_kernel(__nv_bfloat16* a, __nv_bfloat16* c, int n4)
{
    int i = blockIdx.x * 256 + threadIdx.x;
    uint4 z = {0u, 0u, 0u, 0u};
    if (i < n4) {
        reinterpret_cast<uint4*>(a)[i] = z;
        reinterpret_cast<uint4*>(c)[i] = z;
    }
}

// extra_feat fp32 CHW -> bf16 hi/lo padded HWC [b][HP][HP][128]
__global__ __launch_bounds__(256)
void efprep_kernel(const float* __restrict__ ef, __nv_bfloat16* __restrict__ oh,
                   __nv_bfloat16* __restrict__ ol)
{
    int hw = blockIdx.x * 256 + threadIdx.x;
    int g  = blockIdx.y;                  // ci block of 4
    int b  = blockIdx.z;
    int y = hw >> 7, x = hw & 127;
    const float* p = ef + ((size_t)b * 128 + g * 4) * HWc + hw;
    size_t base = ((size_t)(b * HP + y + 1) * HP + (x + 1)) * 128 + g * 4;
    #pragma unroll
    for (int c = 0; c < 4; c++) {
        float v = p[c * HWc];
        __nv_bfloat16 h = __float2bfloat16(v);
        __nv_bfloat16 l = __float2bfloat16(v - __bfloat162float(h));
        oh[base + c] = h;
        ol[base + c] = l;
    }
}

// weights [CO][CI][3][3] fp32 -> [k][CO][CI] bf16 hi/lo
template <int CO, int CI>
__global__ __launch_bounds__(256)
void wprep_kernel(const float* __restrict__ w, __nv_bfloat16* __restrict__ wh,
                  __nv_bfloat16* __restrict__ wl)
{
    int idx = blockIdx.x * 256 + threadIdx.x;
    if (idx < 9 * CO * CI) {
        int ci = idx % CI;
        int t  = idx / CI;
        int co = t % CO;
        int k  = t / CO;
        float v = w[(co * CI + ci) * 9 + k];
        __nv_bfloat16 h = __float2bfloat16(v);
        __nv_bfloat16 l = __float2bfloat16(v - __bfloat162float(h));
        wh[idx] = h;
        wl[idx] = l;
    }
}

// ---------------- conv1/conv2 via warp MMA, leaky, bf16 hi/lo padded HWC out ----------------
// Grid (Hc, B), block 256 = 8 M-warps; warp tile m16 x n64. K = CIN*9 via taps.
template <int CIN>
__global__ __launch_bounds__(256)
void conv12_hmma_kernel(const __nv_bfloat16* __restrict__ inh, const __nv_bfloat16* __restrict__ inl,
                        const __nv_bfloat16* __restrict__ wbh, const __nv_bfloat16* __restrict__ wbl,
                        const float* __restrict__ bias,
                        __nv_bfloat16* __restrict__ outh, __nv_bfloat16* __restrict__ outl)
{
    constexpr int STRIDE = CIN * 2 + 16;   // bytes per smem row; 4-bank rotation/row
    constexpr int NU4 = CIN / 8;           // uint4 per row
    constexpr int KCH = CIN / 16;
    constexpr int OFF_AH = 0;
    constexpr int OFF_AL = 128 * STRIDE;
    constexpr int OFF_BH = 2 * 128 * STRIDE;
    constexpr int OFF_BL = OFF_BH + 64 * STRIDE;

    extern __shared__ char smem[];
    const uint32_t sbase = smem_to_u32(smem);
    const int tid  = threadIdx.x;
    const int mw   = tid / 32;
    const int lane = tid % 32;
    const int y    = blockIdx.x;
    const int b    = blockIdx.y;

    float C[8][4];
    #pragma unroll
    for (int j = 0; j < 8; j++)
        #pragma unroll
        for (int r = 0; r < 4; r++) C[j][r] = 0.f;

    const int a_row   = mw * 16 + (lane & 15);
    const int a_khalf = (lane & 16) ? 16 : 0;
    const int bl15    = lane & 15;
    const int b_rowin = bl15 & 7;
    const int b_khalf = (bl15 & 8) ? 16 : 0;

    #pragma unroll 1
    for (int tap = 0; tap < 9; tap++) {
        const int dy = tap / 3, dx = tap % 3;
        __syncthreads();
        const size_t abase = ((size_t)(b * HP + y + dy) * HP + dx) * CIN;
        const uint4* gAh = reinterpret_cast<const uint4*>(inh + abase);
        const uint4* gAl = reinterpret_cast<const uint4*>(inl + abase);
        #pragma unroll 1
        for (int i = tid; i < 2 * 128 * NU4; i += 256) {
            int buf = i / (128 * NU4);
            int rem = i - buf * 128 * NU4;
            int r = rem / NU4, c = rem % NU4;
            uint4 v = (buf ? gAl : gAh)[r * NU4 + c];
            *reinterpret_cast<uint4*>(smem + (buf ? OFF_AL : OFF_AH) + r * STRIDE + c * 16) = v;
        }
        const uint4* gBh = reinterpret_cast<const uint4*>(wbh + (size_t)tap * 64 * CIN);
        const uint4* gBl = reinterpret_cast<const uint4*>(wbl + (size_t)tap * 64 * CIN);
        #pragma unroll 1
        for (int i = tid; i < 2 * 64 * NU4; i += 256) {
            int buf = i / (64 * NU4);
            int rem = i - buf * 64 * NU4;
            int r = rem / NU4, c = rem % NU4;
            uint4 v = (buf ? gBl : gBh)[r * NU4 + c];
            *reinterpret_cast<uint4*>(smem + (buf ? OFF_BL : OFF_BH) + r * STRIDE + c * 16) = v;
        }
        __syncthreads();

        #pragma unroll 1
        for (int kc = 0; kc < KCH; kc++) {
            const int k0b = kc * 32;
            uint32_t a_h[4], a_l[4];
            ldsm_x4(a_h, sbase + OFF_AH + a_row * STRIDE + k0b + a_khalf);
            ldsm_x4(a_l, sbase + OFF_AL + a_row * STRIDE + k0b + a_khalf);
            #pragma unroll
            for (int j = 0; j < 8; j++) {
                const int brow = j * 8 + b_rowin;
                uint32_t b_h[2], b_l[2];
                ldsm_x2(b_h, sbase + OFF_BH + brow * STRIDE + k0b + b_khalf);
                ldsm_x2(b_l, sbase + OFF_BL + brow * STRIDE + k0b + b_khalf);
                mma_bf16(C[j], a_h, b_h);
                mma_bf16(C[j], a_h, b_l);
                mma_bf16(C[j], a_l, b_h);
            }
        }
    }

    // epilogue: leaky -> hi/lo split -> padded HWC
    const int g = lane >> 2, t = lane & 3;
    const int xp0 = mw * 16 + g;
    #pragma unroll
    for (int j = 0; j < 8; j++) {
        #pragma unroll
        for (int r = 0; r < 4; r++) {
            const int co = j * 8 + t * 2 + (r & 1);
            const int xp = (r < 2) ? xp0 : xp0 + 8;
            float v = C[j][r] + __ldg(&bias[co]);
            v = (v >= 0.f) ? v : 0.1f * v;
            __nv_bfloat16 h = __float2bfloat16(v);
            __nv_bfloat16 l = __float2bfloat16(v - __bfloat162float(h));
            size_t base = ((size_t)(b * HP + y + 1) * HP + (xp + 1)) * 64 + co;
            outh[base] = h;
            outl[base] = l;
        }
    }
}

// ---------------- conv3 via warp MMA (unchanged from round 10) ----------------
constexpr int A_STRIDE_B = 144;
constexpr int OFF_AH3 = 0;
constexpr int OFF_AL3 = 128 * A_STRIDE_B;
constexpr int OFF_BH3 = OFF_AL3 + 128 * A_STRIDE_B;
constexpr int OFF_BL3 = OFF_BH3 + 144 * A_STRIDE_B;
constexpr int SMEM3_TOTAL = OFF_BL3 + 144 * A_STRIDE_B;  // 78336

__global__ __launch_bounds__(512)
void conv3_hmma_kernel(const __nv_bfloat16* __restrict__ h2ph, const __nv_bfloat16* __restrict__ h2pl,
                       const __nv_bfloat16* __restrict__ wbh, const __nv_bfloat16* __restrict__ wbl,
                       const float* __restrict__ b3, const float* __restrict__ flow,
                       float* __restrict__ po)
{
    extern __shared__ char smem[];
    const uint32_t sbase = smem_to_u32(smem);
    const int tid  = threadIdx.x;
    const int wid  = tid / 32;
    const int lane = tid % 32;
    const int mw   = wid / 2;
    const int wn   = wid % 2;
    const int y    = blockIdx.x;
    const int nt   = blockIdx.y;
    const int b    = blockIdx.z;

    float C[9][4];
    #pragma unroll
    for (int j = 0; j < 9; j++)
        #pragma unroll
        for (int r = 0; r < 4; r++) C[j][r] = 0.f;

    const int a_row = mw * 16 + (lane & 15);
    const int a_khalf = (lane & 16) ? 16 : 0;
    const int bl15 = lane & 15;
    const int b_rowin = bl15 & 7;
    const int b_khalf = (bl15 & 8) ? 16 : 0;

    #pragma unroll 1
    for (int tap = 0; tap < 9; tap++) {
        const int dy = tap / 3, dx = tap % 3;
        __syncthreads();
        const size_t abase = ((size_t)(b * HP + y + dy) * HP + dx) * 64;
        const uint4* gAh = reinterpret_cast<const uint4*>(h2ph + abase);
        const uint4* gAl = reinterpret_cast<const uint4*>(h2pl + abase);
        #pragma unroll 1
        for (int i = tid; i < 2048; i += 512) {
            int buf = i >> 10, rem = i & 1023, r = rem >> 3, c = rem & 7;
            uint4 v = (buf ? gAl : gAh)[r * 8 + c];
            *reinterpret_cast<uint4*>(smem + (buf ? OFF_AL3 : OFF_AH3) + r * A_STRIDE_B + c * 16) = v;
        }
        const uint4* gBh = reinterpret_cast<const uint4*>(wbh + ((size_t)tap * 432 + nt * 144) * 64);
        const uint4* gBl = reinterpret_cast<const uint4*>(wbl + ((size_t)tap * 432 + nt * 144) * 64);
        #pragma unroll 1
        for (int i = tid; i < 2304; i += 512) {
            int buf = (i >= 1152) ? 1 : 0;
            int j2  = buf ? i - 1152 : i;
            int r = j2 >> 3, c = j2 & 7;
            uint4 v = (buf ? gBl : gBh)[r * 8 + c];
            *reinterpret_cast<uint4*>(smem + (buf ? OFF_BL3 : OFF_BH3) + r * A_STRIDE_B + c * 16) = v;
        }
        __syncthreads();

        #pragma unroll
        for (int kc = 0; kc < 4; kc++) {
            const int k0b = kc * 32;
            uint32_t a_h[4], a_l[4];
            ldsm_x4(a_h, sbase + OFF_AH3 + a_row * A_STRIDE_B + k0b + a_khalf);
            ldsm_x4(a_l, sbase + OFF_AL3 + a_row * A_STRIDE_B + k0b + a_khalf);
            #pragma unroll
            for (int j = 0; j < 9; j++) {
                const int brow = wn * 72 + j * 8 + b_rowin;
                uint32_t b_h[2], b_l[2];
                ldsm_x2(b_h, sbase + OFF_BH3 + brow * A_STRIDE_B + k0b + b_khalf);
                ldsm_x2(b_l, sbase + OFF_BL3 + brow * A_STRIDE_B + k0b + b_khalf);
                mma_bf16(C[j], a_h, b_h);
                mma_bf16(C[j], a_h, b_l);
                mma_bf16(C[j], a_l, b_h);
            }
        }
    }

    const int g = lane >> 2, t = lane & 3;
    const int hw0 = y * Wc + mw * 16 + g;
    const int hw1 = hw0 + 8;
    const float fy0 = flow[(b * 2 + 1) * HWc + hw0];
    const float fx0 = flow[(b * 2 + 0) * HWc + hw0];
    const float fy1 = flow[(b * 2 + 1) * HWc + hw1];
    const float fx1 = flow[(b * 2 + 0) * HWc + hw1];
    #pragma unroll
    for (int j = 0; j < 9; j++) {
        const int cobase = nt * 144 + wn * 72 + j * 8 + t * 2;
        #pragma unroll
        for (int r = 0; r < 4; r++) {
            const int co = cobase + (r & 1);
            const int hw = (r < 2) ? hw0 : hw1;
            float v = C[j][r] + __ldg(&b3[co]);
            if (co < 288) {
                const float fyv = (r < 2) ? fy0 : fy1;
                const float fxv = (r < 2) ? fx0 : fx1;
                v = 10.f * tanhf(v) + ((co & 1) ? fxv : fyv);
            } else {
                v = 1.f / (1.f + expf(-v));
            }
            po[((size_t)b * 432 + co) * HWc + hw] = v;
        }
    }
}

// ---------------- x transpose ----------------
__global__ __launch_bounds__(256)
void transpose_kernel(const float* __restrict__ x, float* __restrict__ xt)
{
    int hw = blockIdx.x * 256 + threadIdx.x;
    int g  = blockIdx.y;
    int b  = blockIdx.z;
    const float* xp = x + (b * 64 + g * 4) * HWc + hw;
    float4 v;
    v.x = xp[0];
    v.y = xp[HWc];
    v.z = xp[2 * HWc];
    v.w = xp[3 * HWc];
    reinterpret_cast<float4*>(xt + ((b * 16 + g) * HWc + hw) * 4)[0] = v;
}

// ---------------- deformable gather + einsum (unchanged) ----------------
__global__ __launch_bounds__(128)
void deform_kernel(const float* __restrict__ xt, const float* __restrict__ po,
                   const float* __restrict__ wgt, float* __restrict__ dp)
{
    __shared__ float s_wt[8 * 9 * 4 * 32];

    const int bz    = blockIdx.z;
    const int B     = gridDim.z / 4;
    const int b     = bz / 4;
    const int gsp   = (bz % 4) / 2;
    const int csp   = bz % 2;
    const int g0    = gsp * 8;
    const int o0    = csp * 32;
    const int x0    = blockIdx.x * 16, y0 = blockIdx.y * 8;
    const int tid   = threadIdx.x;
    const int tx    = tid % 16, ty = tid / 16;
    const int xx    = x0 + tx, yy = y0 + ty;

    unsigned long long acc[16];
    #pragma unroll
    for (int j = 0; j < 16; j++) acc[j] = 0ULL;

    const float* pob = po + b * 432 * HWc + yy * Wc + xx;
    const float* xtb = xt + b * 16 * HWc * 4;

    #pragma unroll 1
    for (int i = tid; i < 8 * 9 * 4 * 32; i += 128) {
        int o = i & 31;
        int r = i >> 5;
        int c = r & 3;
        r >>= 2;
        int k  = r % 9;
        int gl = r / 9;
        s_wt[i] = wgt[((o0 + o) * 64 + (g0 + gl) * 4 + c) * 9 + k];
    }
    __syncthreads();

    #pragma unroll 1
    for (int gl = 0; gl < 8; gl++) {
        const int g = g0 + gl;
        const float4* xg = reinterpret_cast<const float4*>(xtb + g * HWc * 4);
        #pragma unroll 3
        for (int k = 0; k < 9; k++) {
            const int gk = g * 9 + k;
            float offy = pob[(2 * gk) * HWc];
            float offx = pob[(2 * gk + 1) * HWc];
            float msk  = pob[(288 + gk) * HWc];

            float py = (float)(yy + k / 3 - 1) + offy;
            float px = (float)(xx + k % 3 - 1) + offx;
            float fy = floorf(py), fxv = floorf(px);
            int iy0 = (int)fy, ix0 = (int)fxv;
            float wy = py - fy, wx = px - fxv;

            bool vy0 = (unsigned)iy0       < (unsigned)Hc;
            bool vy1 = (unsigned)(iy0 + 1) < (unsigned)Hc;
            bool vx0 = (unsigned)ix0       < (unsigned)Wc;
            bool vx1 = (unsigned)(ix0 + 1) < (unsigned)Wc;
            int cy0 = min(max(iy0, 0), Hc - 1), cy1 = min(max(iy0 + 1, 0), Hc - 1);
            int cx0 = min(max(ix0, 0), Wc - 1), cx1 = min(max(ix0 + 1, 0), Wc - 1);

            float w00 = (1.f - wy) * (1.f - wx) * msk; if (!(vy0 && vx0)) w00 = 0.f;
            float w01 = (1.f - wy) * wx        * msk; if (!(vy0 && vx1)) w01 = 0.f;
            float w10 = wy        * (1.f - wx) * msk; if (!(vy1 && vx0)) w10 = 0.f;
            float w11 = wy        * wx         * msk; if (!(vy1 && vx1)) w11 = 0.f;

            float4 p00 = __ldg(xg + cy0 * Wc + cx0);
            float4 p01 = __ldg(xg + cy0 * Wc + cx1);
            float4 p10 = __ldg(xg + cy1 * Wc + cx0);
            float4 p11 = __ldg(xg + cy1 * Wc + cx1);

            float val[4];
            val[0] = w00 * p00.x + w01 * p01.x + w10 * p10.x + w11 * p11.x;
            val[1] = w00 * p00.y + w01 * p01.y + w10 * p10.y + w11 * p11.y;
            val[2] = w00 * p00.z + w01 * p01.z + w10 * p10.z + w11 * p11.z;
            val[3] = w00 * p00.w + w01 * p01.w + w10 * p10.w + w11 * p11.w;

            #pragma unroll
            for (int c = 0; c < 4; c++) {
                unsigned long long vv = pack2(val[c], val[c]);
                const ulonglong2* wp = reinterpret_cast<const ulonglong2*>(
                    &s_wt[((gl * 9 + k) * 4 + c) * 32]);
                #pragma unroll
                for (int j = 0; j < 8; j++) {
                    ulonglong2 w2 = wp[j];
                    fma2(acc[2 * j],     w2.x, vv);
                    fma2(acc[2 * j + 1], w2.y, vv);
                }
            }
        }
    }

    float* dpo = dp + (gsp * B + b) * 64 * HWc + o0 * HWc;
    #pragma unroll
    for (int j = 0; j < 16; j++) {
        float lo, hi;
        unpack2(acc[j], lo, hi);
        dpo[(2 * j)     * HWc + yy * Wc + xx] = lo;
        dpo[(2 * j + 1) * HWc + yy * Wc + xx] = hi;
    }
}

// ---------------- combine partials (2-way) ----------------
__global__ __launch_bounds__(256)
void combine_kernel(const float* __restrict__ dp, float* __restrict__ out, int n4)
{
    int i = blockIdx.x * 256 + threadIdx.x;
    if (i < n4) {
        float4 a = reinterpret_cast<const float4*>(dp)[i];
        float4 c = reinterpret_cast<const float4*>(dp)[n4 + i];
        float4 o;
        o.x = a.x + c.x; o.y = a.y + c.y; o.z = a.z + c.z; o.w = a.w + c.w;
        reinterpret_cast<float4*>(out)[i] = o;
    }
}

// ---------------- launch ----------------
extern "C" void kernel_launch(void* const* d_in, const int* in_sizes, int n_in,
                              void* d_out, int out_size)
{
    const float* x    = (const float*)d_in[0];
    const float* ef   = (const float*)d_in[1];
    const float* flow = (const float*)d_in[2];
    const float* w1   = (const float*)d_in[3];
    const float* b1   = (const float*)d_in[4];
    const float* w2   = (const float*)d_in[5];
    const float* b2   = (const float*)d_in[6];
    const float* w3   = (const float*)d_in[7];
    const float* b3   = (const float*)d_in[8];
    const float* wgt  = (const float*)d_in[9];
    float* out = (float*)d_out;

    const int B = in_sizes[0] / (64 * HWc);  // = 2

    float *ppo, *pxt, *pdp;
    __nv_bfloat16 *pefh, *pefl, *ph1h, *ph1l, *ph2h, *ph2l;
    __nv_bfloat16 *pw1h, *pw1l, *pw2h, *pw2l, *pw3h, *pw3l;
    cudaGetSymbolAddress((void**)&ppo,  g_po);
    cudaGetSymbolAddress((void**)&pxt,  g_xt);
    cudaGetSymbolAddress((void**)&pdp,  g_dp);
    cudaGetSymbolAddress((void**)&pefh, g_efph);
    cudaGetSymbolAddress((void**)&pefl, g_efpl);
    cudaGetSymbolAddress((void**)&ph1h, g_h1ph);
    cudaGetSymbolAddress((void**)&ph1l, g_h1pl);
    cudaGetSymbolAddress((void**)&ph2h, g_h2ph);
    cudaGetSymbolAddress((void**)&ph2l, g_h2pl);
    cudaGetSymbolAddress((void**)&pw1h, g_w1bh);
    cudaGetSymbolAddress((void**)&pw1l, g_w1bl);
    cudaGetSymbolAddress((void**)&pw2h, g_w2bh);
    cudaGetSymbolAddress((void**)&pw2l, g_w2bl);
    cudaGetSymbolAddress((void**)&pw3h, g_w3bh);
    cudaGetSymbolAddress((void**)&pw3l, g_w3bl);

    constexpr int SMEM1 = 2 * 128 * (128 * 2 + 16) + 2 * 64 * (128 * 2 + 16);  // 104448
    constexpr int SMEM2 = 2 * 128 * (64 * 2 + 16) + 2 * 64 * (64 * 2 + 16);    // 55296
    cudaFuncSetAttribute(conv12_hmma_kernel<128>, cudaFuncAttributeMaxDynamicSharedMemorySize, SMEM1);
    cudaFuncSetAttribute(conv12_hmma_kernel<64>,  cudaFuncAttributeMaxDynamicSharedMemorySize, SMEM2);
    cudaFuncSetAttribute(conv3_hmma_kernel, cudaFuncAttributeMaxDynamicSharedMemorySize, SMEM3_TOTAL);

    // prep (independent)
    transpose_kernel<<<dim3(HWc / 256, 16, B), 256>>>(x, pxt);
    int nf_ef = B * HP * HP * 128 / 8;
    int nf_h  = B * HP * HP * 64 / 8;
    fill0_kernel<<<(nf_ef + 255) / 256, 256>>>(pefh, pefl, nf_ef);
    fill0_kernel<<<(nf_h + 255) / 256, 256>>>(ph1h, ph1l, nf_h);
    fill0_kernel<<<(nf_h + 255) / 256, 256>>>(ph2h, ph2l, nf_h);
    efprep_kernel<<<dim3(HWc / 256, 32, B), 256>>>(ef, pefh, pefl);
    wprep_kernel<64, 128><<<(9 * 64 * 128 + 255) / 256, 256>>>(w1, pw1h, pw1l);
    wprep_kernel<64, 64><<<(9 * 64 * 64 + 255) / 256, 256>>>(w2, pw2h, pw2l);
    wprep_kernel<432, 64><<<(9 * 432 * 64 + 255) / 256, 256>>>(w3, pw3h, pw3l);

    // conv chain (all HMMA)
    conv12_hmma_kernel<128><<<dim3(Hc, B), 256, SMEM1>>>(pefh, pefl, pw1h, pw1l, b1, ph1h, ph1l);
    conv12_hmma_kernel<64><<<dim3(Hc, B), 256, SMEM2>>>(ph1h, ph1l, pw2h, pw2l, b2, ph2h, ph2l);
    conv3_hmma_kernel<<<dim3(Hc, 3, B), 512, SMEM3_TOTAL>>>(ph2h, ph2l, pw3h, pw3l, b3, flow, ppo);

    // deformable gather + einsum
    deform_kernel<<<dim3(8, 16, B * 4), 128>>>(pxt, ppo, wgt, pdp);
    int n4 = B * 64 * HWc / 4;
    combine_kernel<<<(n4 + 255) / 256, 256>>>(pdp, out, n4);
}

// round 12
// speedup vs baseline: 3.1621x; 1.1708x over previous
#include <cuda_runtime.h>
#include <cuda_bf16.h>
#include <cstdint>

constexpr int Hc = 128, Wc = 128, HWc = Hc * Wc;
constexpr int HP = 130;   // padded spatial dim

// ---------------- scratch (device globals; no allocation allowed) ----------------
__device__ float g_po[2 * 432 * HWc];
__device__ float g_xt[2 * 16 * HWc * 4];             // x transposed: [b][g][hw][4]
__device__ float g_dp[2 * 2 * 64 * HWc];             // [gsplit][b][co][hw]
__device__ __nv_bfloat16 g_efph[2 * HP * HP * 128];
__device__ __nv_bfloat16 g_efpl[2 * HP * HP * 128];
__device__ __nv_bfloat16 g_h1ph[2 * HP * HP * 64];
__device__ __nv_bfloat16 g_h1pl[2 * HP * HP * 64];
__device__ __nv_bfloat16 g_h2ph[2 * HP * HP * 64];
__device__ __nv_bfloat16 g_h2pl[2 * HP * HP * 64];
__device__ __nv_bfloat16 g_w1bh[9 * 64 * 128];
__device__ __nv_bfloat16 g_w1bl[9 * 64 * 128];
__device__ __nv_bfloat16 g_w2bh[9 * 64 * 64];
__device__ __nv_bfloat16 g_w2bl[9 * 64 * 64];
__device__ __nv_bfloat16 g_w3bh[9 * 432 * 64];
__device__ __nv_bfloat16 g_w3bl[9 * 432 * 64];
__device__ __nv_bfloat16 g_wdh[16 * 64 * 48];        // deform weight [g][co][kk] hi
__device__ __nv_bfloat16 g_wdl[16 * 64 * 48];        // lo

// ---------------- warp MMA helpers (arch-neutral PTX) ----------------
__device__ __forceinline__ uint32_t smem_to_u32(const void* p) {
    uint32_t a;
    asm("{ .reg .u64 t; cvta.to.shared.u64 t, %1; cvt.u32.u64 %0, t; }" : "=r"(a) : "l"(p));
    return a;
}
__device__ __forceinline__ void ldsm_x4(uint32_t (&r)[4], uint32_t addr) {
    asm volatile("ldmatrix.sync.aligned.m8n8.x4.shared.b16 {%0,%1,%2,%3}, [%4];"
        : "=r"(r[0]), "=r"(r[1]), "=r"(r[2]), "=r"(r[3]) : "r"(addr));
}
__device__ __forceinline__ void ldsm_x2(uint32_t (&r)[2], uint32_t addr) {
    asm volatile("ldmatrix.sync.aligned.m8n8.x2.shared.b16 {%0,%1}, [%2];"
        : "=r"(r[0]), "=r"(r[1]) : "r"(addr));
}
__device__ __forceinline__ void mma_bf16(float (&c)[4], const uint32_t (&a)[4], const uint32_t (&bb)[2]) {
    asm volatile("mma.sync.aligned.m16n8k16.row.col.f32.bf16.bf16.f32 "
        "{%0,%1,%2,%3}, {%4,%5,%6,%7}, {%8,%9}, {%0,%1,%2,%3};"
        : "+f"(c[0]), "+f"(c[1]), "+f"(c[2]), "+f"(c[3])
        : "r"(a[0]), "r"(a[1]), "r"(a[2]), "r"(a[3]), "r"(bb[0]), "r"(bb[1]));
}

// ---------------- fills & preps ----------------
__global__ __launch_bounds__(256)
void fill0_kernel(__nv_bfloat16* a, __nv_bfloat16* c, int n4)
{
    int i = blockIdx.x * 256 + threadIdx.x;
    uint4 z = {0u, 0u, 0u, 0u};
    if (i < n4) {
        reinterpret_cast<uint4*>(a)[i] = z;
        reinterpret_cast<uint4*>(c)[i] = z;
    }
}

__global__ __launch_bounds__(256)
void efprep_kernel(const float* __restrict__ ef, __nv_bfloat16* __restrict__ oh,
                   __nv_bfloat16* __restrict__ ol)
{
    int hw = blockIdx.x * 256 + threadIdx.x;
    int g  = blockIdx.y;
    int b  = blockIdx.z;
    int y = hw >> 7, x = hw & 127;
    const float* p = ef + ((size_t)b * 128 + g * 4) * HWc + hw;
    size_t base = ((size_t)(b * HP + y + 1) * HP + (x + 1)) * 128 + g * 4;
    #pragma unroll
    for (int c = 0; c < 4; c++) {
        float v = p[c * HWc];
        __nv_bfloat16 h = __float2bfloat16(v);
        __nv_bfloat16 l = __float2bfloat16(v - __bfloat162float(h));
        oh[base + c] = h;
        ol[base + c] = l;
    }
}

template <int CO, int CI>
__global__ __launch_bounds__(256)
void wprep_kernel(const float* __restrict__ w, __nv_bfloat16* __restrict__ wh,
                  __nv_bfloat16* __restrict__ wl)
{
    int idx = blockIdx.x * 256 + threadIdx.x;
    if (idx < 9 * CO * CI) {
        int ci = idx % CI;
        int t  = idx / CI;
        int co = t % CO;
        int k  = t / CO;
        float v = w[(co * CI + ci) * 9 + k];
        __nv_bfloat16 h = __float2bfloat16(v);
        __nv_bfloat16 l = __float2bfloat16(v - __bfloat162float(h));
        wh[idx] = h;
        wl[idx] = l;
    }
}

// deform weight: weight[(o*64 + g*4 + c)*9 + k] -> [g][o][kk=k*4+c] hi/lo (kk 36..47 zero)
__global__ __launch_bounds__(256)
void wdprep_kernel(const float* __restrict__ w, __nv_bfloat16* __restrict__ wh,
                   __nv_bfloat16* __restrict__ wl)
{
    int idx = blockIdx.x * 256 + threadIdx.x;   // over 16*64*48
    if (idx < 16 * 64 * 48) {
        int kk = idx % 48;
        int t  = idx / 48;
        int o  = t % 64;
        int g  = t / 64;
        __nv_bfloat16 h = __float2bfloat16(0.f), l = __float2bfloat16(0.f);
        if (kk < 36) {
            int k = kk >> 2, c = kk & 3;
            float v = w[(o * 64 + g * 4 + c) * 9 + k];
            h = __float2bfloat16(v);
            l = __float2bfloat16(v - __bfloat162float(h));
        }
        wh[idx] = h;
        wl[idx] = l;
    }
}

// ---------------- conv1/conv2 via warp MMA ----------------
template <int CIN>
__global__ __launch_bounds__(256)
void conv12_hmma_kernel(const __nv_bfloat16* __restrict__ inh, const __nv_bfloat16* __restrict__ inl,
                        const __nv_bfloat16* __restrict__ wbh, const __nv_bfloat16* __restrict__ wbl,
                        const float* __restrict__ bias,
                        __nv_bfloat16* __restrict__ outh, __nv_bfloat16* __restrict__ outl)
{
    constexpr int STRIDE = CIN * 2 + 16;
    constexpr int NU4 = CIN / 8;
    constexpr int KCH = CIN / 16;
    constexpr int OFF_AH = 0;
    constexpr int OFF_AL = 128 * STRIDE;
    constexpr int OFF_BH = 2 * 128 * STRIDE;
    constexpr int OFF_BL = OFF_BH + 64 * STRIDE;

    extern __shared__ char smem[];
    const uint32_t sbase = smem_to_u32(smem);
    const int tid  = threadIdx.x;
    const int mw   = tid / 32;
    const int lane = tid % 32;
    const int y    = blockIdx.x;
    const int b    = blockIdx.y;

    float C[8][4];
    #pragma unroll
    for (int j = 0; j < 8; j++)
        #pragma unroll
        for (int r = 0; r < 4; r++) C[j][r] = 0.f;

    const int a_row   = mw * 16 + (lane & 15);
    const int a_khalf = (lane & 16) ? 16 : 0;
    const int bl15    = lane & 15;
    const int b_rowin = bl15 & 7;
    const int b_khalf = (bl15 & 8) ? 16 : 0;

    #pragma unroll 1
    for (int tap = 0; tap < 9; tap++) {
        const int dy = tap / 3, dx = tap % 3;
        __syncthreads();
        const size_t abase = ((size_t)(b * HP + y + dy) * HP + dx) * CIN;
        const uint4* gAh = reinterpret_cast<const uint4*>(inh + abase);
        const uint4* gAl = reinterpret_cast<const uint4*>(inl + abase);
        #pragma unroll 1
        for (int i = tid; i < 2 * 128 * NU4; i += 256) {
            int buf = i / (128 * NU4);
            int rem = i - buf * 128 * NU4;
            int r = rem / NU4, c = rem % NU4;
            uint4 v = (buf ? gAl : gAh)[r * NU4 + c];
            *reinterpret_cast<uint4*>(smem + (buf ? OFF_AL : OFF_AH) + r * STRIDE + c * 16) = v;
        }
        const uint4* gBh = reinterpret_cast<const uint4*>(wbh + (size_t)tap * 64 * CIN);
        const uint4* gBl = reinterpret_cast<const uint4*>(wbl + (size_t)tap * 64 * CIN);
        #pragma unroll 1
        for (int i = tid; i < 2 * 64 * NU4; i += 256) {
            int buf = i / (64 * NU4);
            int rem = i - buf * 64 * NU4;
            int r = rem / NU4, c = rem % NU4;
            uint4 v = (buf ? gBl : gBh)[r * NU4 + c];
            *reinterpret_cast<uint4*>(smem + (buf ? OFF_BL : OFF_BH) + r * STRIDE + c * 16) = v;
        }
        __syncthreads();

        #pragma unroll 1
        for (int kc = 0; kc < KCH; kc++) {
            const int k0b = kc * 32;
            uint32_t a_h[4], a_l[4];
            ldsm_x4(a_h, sbase + OFF_AH + a_row * STRIDE + k0b + a_khalf);
            ldsm_x4(a_l, sbase + OFF_AL + a_row * STRIDE + k0b + a_khalf);
            #pragma unroll
            for (int j = 0; j < 8; j++) {
                const int brow = j * 8 + b_rowin;
                uint32_t b_h[2], b_l[2];
                ldsm_x2(b_h, sbase + OFF_BH + brow * STRIDE + k0b + b_khalf);
                ldsm_x2(b_l, sbase + OFF_BL + brow * STRIDE + k0b + b_khalf);
                mma_bf16(C[j], a_h, b_h);
                mma_bf16(C[j], a_h, b_l);
                mma_bf16(C[j], a_l, b_h);
            }
        }
    }

    const int g = lane >> 2, t = lane & 3;
    const int xp0 = mw * 16 + g;
    #pragma unroll
    for (int j = 0; j < 8; j++) {
        #pragma unroll
        for (int r = 0; r < 4; r++) {
            const int co = j * 8 + t * 2 + (r & 1);
            const int xp = (r < 2) ? xp0 : xp0 + 8;
            float v = C[j][r] + __ldg(&bias[co]);
            v = (v >= 0.f) ? v : 0.1f * v;
            __nv_bfloat16 h = __float2bfloat16(v);
            __nv_bfloat16 l = __float2bfloat16(v - __bfloat162float(h));
            size_t base = ((size_t)(b * HP + y + 1) * HP + (xp + 1)) * 64 + co;
            outh[base] = h;
            outl[base] = l;
        }
    }
}

// ---------------- conv3 via warp MMA ----------------
constexpr int A_STRIDE_B = 144;
constexpr int OFF_AH3 = 0;
constexpr int OFF_AL3 = 128 * A_STRIDE_B;
constexpr int OFF_BH3 = OFF_AL3 + 128 * A_STRIDE_B;
constexpr int OFF_BL3 = OFF_BH3 + 144 * A_STRIDE_B;
constexpr int SMEM3_TOTAL = OFF_BL3 + 144 * A_STRIDE_B;  // 78336

__global__ __launch_bounds__(512)
void conv3_hmma_kernel(const __nv_bfloat16* __restrict__ h2ph, const __nv_bfloat16* __restrict__ h2pl,
                       const __nv_bfloat16* __restrict__ wbh, const __nv_bfloat16* __restrict__ wbl,
                       const float* __restrict__ b3, const float* __restrict__ flow,
                       float* __restrict__ po)
{
    extern __shared__ char smem[];
    const uint32_t sbase = smem_to_u32(smem);
    const int tid  = threadIdx.x;
    const int wid  = tid / 32;
    const int lane = tid % 32;
    const int mw   = wid / 2;
    const int wn   = wid % 2;
    const int y    = blockIdx.x;
    const int nt   = blockIdx.y;
    const int b    = blockIdx.z;

    float C[9][4];
    #pragma unroll
    for (int j = 0; j < 9; j++)
        #pragma unroll
        for (int r = 0; r < 4; r++) C[j][r] = 0.f;

    const int a_row = mw * 16 + (lane & 15);
    const int a_khalf = (lane & 16) ? 16 : 0;
    const int bl15 = lane & 15;
    const int b_rowin = bl15 & 7;
    const int b_khalf = (bl15 & 8) ? 16 : 0;

    #pragma unroll 1
    for (int tap = 0; tap < 9; tap++) {
        const int dy = tap / 3, dx = tap % 3;
        __syncthreads();
        const size_t abase = ((size_t)(b * HP + y + dy) * HP + dx) * 64;
        const uint4* gAh = reinterpret_cast<const uint4*>(h2ph + abase);
        const uint4* gAl = reinterpret_cast<const uint4*>(h2pl + abase);
        #pragma unroll 1
        for (int i = tid; i < 2048; i += 512) {
            int buf = i >> 10, rem = i & 1023, r = rem >> 3, c = rem & 7;
            uint4 v = (buf ? gAl : gAh)[r * 8 + c];
            *reinterpret_cast<uint4*>(smem + (buf ? OFF_AL3 : OFF_AH3) + r * A_STRIDE_B + c * 16) = v;
        }
        const uint4* gBh = reinterpret_cast<const uint4*>(wbh + ((size_t)tap * 432 + nt * 144) * 64);
        const uint4* gBl = reinterpret_cast<const uint4*>(wbl + ((size_t)tap * 432 + nt * 144) * 64);
        #pragma unroll 1
        for (int i = tid; i < 2304; i += 512) {
            int buf = (i >= 1152) ? 1 : 0;
            int j2  = buf ? i - 1152 : i;
            int r = j2 >> 3, c = j2 & 7;
            uint4 v = (buf ? gBl : gBh)[r * 8 + c];
            *reinterpret_cast<uint4*>(smem + (buf ? OFF_BL3 : OFF_BH3) + r * A_STRIDE_B + c * 16) = v;
        }
        __syncthreads();

        #pragma unroll
        for (int kc = 0; kc < 4; kc++) {
            const int k0b = kc * 32;
            uint32_t a_h[4], a_l[4];
            ldsm_x4(a_h, sbase + OFF_AH3 + a_row * A_STRIDE_B + k0b + a_khalf);
            ldsm_x4(a_l, sbase + OFF_AL3 + a_row * A_STRIDE_B + k0b + a_khalf);
            #pragma unroll
            for (int j = 0; j < 9; j++) {
                const int brow = wn * 72 + j * 8 + b_rowin;
                uint32_t b_h[2], b_l[2];
                ldsm_x2(b_h, sbase + OFF_BH3 + brow * A_STRIDE_B + k0b + b_khalf);
                ldsm_x2(b_l, sbase + OFF_BL3 + brow * A_STRIDE_B + k0b + b_khalf);
                mma_bf16(C[j], a_h, b_h);
                mma_bf16(C[j], a_h, b_l);
                mma_bf16(C[j], a_l, b_h);
            }
        }
    }

    const int g = lane >> 2, t = lane & 3;
    const int hw0 = y * Wc + mw * 16 + g;
    const int hw1 = hw0 + 8;
    const float fy0 = flow[(b * 2 + 1) * HWc + hw0];
    const float fx0 = flow[(b * 2 + 0) * HWc + hw0];
    const float fy1 = flow[(b * 2 + 1) * HWc + hw1];
    const float fx1 = flow[(b * 2 + 0) * HWc + hw1];
    #pragma unroll
    for (int j = 0; j < 9; j++) {
        const int cobase = nt * 144 + wn * 72 + j * 8 + t * 2;
        #pragma unroll
        for (int r = 0; r < 4; r++) {
            const int co = cobase + (r & 1);
            const int hw = (r < 2) ? hw0 : hw1;
            float v = C[j][r] + __ldg(&b3[co]);
            if (co < 288) {
                const float fyv = (r < 2) ? fy0 : fy1;
                const float fxv = (r < 2) ? fx0 : fx1;
                v = 10.f * tanhf(v) + ((co & 1) ? fxv : fyv);
            } else {
                v = 1.f / (1.f + expf(-v));
            }
            po[((size_t)b * 432 + co) * HWc + hw] = v;
        }
    }
}

// ---------------- x transpose ----------------
__global__ __launch_bounds__(256)
void transpose_kernel(const float* __restrict__ x, float* __restrict__ xt)
{
    int hw = blockIdx.x * 256 + threadIdx.x;
    int g  = blockIdx.y;
    int b  = blockIdx.z;
    const float* xp = x + (b * 64 + g * 4) * HWc + hw;
    float4 v;
    v.x = xp[0];
    v.y = xp[HWc];
    v.z = xp[2 * HWc];
    v.w = xp[3 * HWc];
    reinterpret_cast<float4*>(xt + ((b * 16 + g) * HWc + hw) * 4)[0] = v;
}

// ---------------- deformable gather + einsum via HMMA ----------------
// Grid (Hc, 2, B), block 256 = 8 M-warps (m16 each over 128 pixels of one row).
// Per group: gather 9 taps x 4 ch per pixel -> bf16 hi/lo A[128][48], weights B[64][48],
// 3 k16-chunks x 3 hi/lo combos MMA, accumulate over 8 groups. Write dp[gsp].
constexpr int STRA = 112;   // bytes per smem row (48 bf16 data + 8 pad)
constexpr int DOFF_AH = 0;
constexpr int DOFF_AL = 128 * STRA;           // 14336
constexpr int DOFF_BH = 2 * 128 * STRA;       // 28672
constexpr int DOFF_BL = DOFF_BH + 64 * STRA;  // 35840
constexpr int DSMEM = DOFF_BL + 64 * STRA;    // 43008

__global__ __launch_bounds__(256)
void deform_hmma_kernel(const float* __restrict__ xt, const float* __restrict__ po,
                        const __nv_bfloat16* __restrict__ wdh, const __nv_bfloat16* __restrict__ wdl,
                        float* __restrict__ dp)
{
    extern __shared__ char smem[];
    const uint32_t sbase = smem_to_u32(smem);
    const int tid  = threadIdx.x;
    const int mw   = tid / 32;
    const int lane = tid % 32;
    const int y    = blockIdx.x;
    const int gsp  = blockIdx.y;
    const int b    = blockIdx.z;
    const int B    = gridDim.z;

    float C[8][4];
    #pragma unroll
    for (int j = 0; j < 8; j++)
        #pragma unroll
        for (int r = 0; r < 4; r++) C[j][r] = 0.f;

    // zero A K-pad region (bytes 72..96 of each row; kk 36..47) once
    #pragma unroll 1
    for (int i = tid; i < 128 * 2 * 6; i += 256) {
        int w = i % 6;
        int r = (i / 6) % 128;
        int buf = i / (6 * 128);
        *reinterpret_cast<uint32_t*>(smem + (buf ? DOFF_AL : DOFF_AH) + r * STRA + 72 + w * 4) = 0u;
    }

    const int a_row   = mw * 16 + (lane & 15);
    const int a_khalf = (lane & 16) ? 16 : 0;
    const int bl15    = lane & 15;
    const int b_rowin = bl15 & 7;
    const int b_khalf = (bl15 & 8) ? 16 : 0;

    const float* pobase = po + (size_t)b * 432 * HWc + y * Wc;
    const float* xtb = xt + (size_t)b * 16 * HWc * 4;

    #pragma unroll 1
    for (int gl = 0; gl < 8; gl++) {
        const int g = gsp * 8 + gl;
        __syncthreads();   // prior MMA reads done before overwriting A/B

        // stage B[g]: 64 rows x 48 bf16 = 6 uint4/row, hi+lo
        const uint4* gBh = reinterpret_cast<const uint4*>(wdh + (size_t)g * 64 * 48);
        const uint4* gBl = reinterpret_cast<const uint4*>(wdl + (size_t)g * 64 * 48);
        #pragma unroll 1
        for (int i = tid; i < 2 * 64 * 6; i += 256) {
            int buf = i / 384;
            int rem = i - buf * 384;
            int r = rem / 6, c = rem % 6;
            uint4 v = (buf ? gBl : gBh)[r * 6 + c];
            *reinterpret_cast<uint4*>(smem + (buf ? DOFF_BL : DOFF_BH) + r * STRA + c * 16) = v;
        }

        // gather: 9 taps x 128 pixels
        const float4* xg = reinterpret_cast<const float4*>(xtb + (size_t)g * HWc * 4);
        #pragma unroll 1
        for (int i = tid; i < 9 * 128; i += 256) {
            const int px  = i & 127;
            const int tap = i >> 7;
            const int gk  = g * 9 + tap;
            const float* pob = pobase + px;
            float offy = pob[(2 * gk) * HWc];
            float offx = pob[(2 * gk + 1) * HWc];
            float msk  = pob[(288 + gk) * HWc];

            float py = (float)(y + tap / 3 - 1) + offy;
            float pxf = (float)(px + tap % 3 - 1) + offx;
            float fy = floorf(py), fxv = floorf(pxf);
            int iy0 = (int)fy, ix0 = (int)fxv;
            float wy = py - fy, wx = pxf - fxv;

            bool vy0 = (unsigned)iy0       < (unsigned)Hc;
            bool vy1 = (unsigned)(iy0 + 1) < (unsigned)Hc;
            bool vx0 = (unsigned)ix0       < (unsigned)Wc;
            bool vx1 = (unsigned)(ix0 + 1) < (unsigned)Wc;
            int cy0 = min(max(iy0, 0), Hc - 1), cy1 = min(max(iy0 + 1, 0), Hc - 1);
            int cx0 = min(max(ix0, 0), Wc - 1), cx1 = min(max(ix0 + 1, 0), Wc - 1);

            float w00 = (1.f - wy) * (1.f - wx) * msk; if (!(vy0 && vx0)) w00 = 0.f;
            float w01 = (1.f - wy) * wx        * msk; if (!(vy0 && vx1)) w01 = 0.f;
            float w10 = wy        * (1.f - wx) * msk; if (!(vy1 && vx0)) w10 = 0.f;
            float w11 = wy        * wx         * msk; if (!(vy1 && vx1)) w11 = 0.f;

            float4 p00 = __ldg(xg + cy0 * Wc + cx0);
            float4 p01 = __ldg(xg + cy0 * Wc + cx1);
            float4 p10 = __ldg(xg + cy1 * Wc + cx0);
            float4 p11 = __ldg(xg + cy1 * Wc + cx1);

            float val[4];
            val[0] = w00 * p00.x + w01 * p01.x + w10 * p10.x + w11 * p11.x;
            val[1] = w00 * p00.y + w01 * p01.y + w10 * p10.y + w11 * p11.y;
            val[2] = w00 * p00.z + w01 * p01.z + w10 * p10.z + w11 * p11.z;
            val[3] = w00 * p00.w + w01 * p01.w + w10 * p10.w + w11 * p11.w;

            // split hi/lo, pack pairs, store 8B each
            uint32_t h01, h23, l01, l23;
            {
                __nv_bfloat16 h0 = __float2bfloat16(val[0]);
                __nv_bfloat16 h1 = __float2bfloat16(val[1]);
                __nv_bfloat16 h2 = __float2bfloat16(val[2]);
                __nv_bfloat16 h3 = __float2bfloat16(val[3]);
                __nv_bfloat16 l0 = __float2bfloat16(val[0] - __bfloat162float(h0));
                __nv_bfloat16 l1 = __float2bfloat16(val[1] - __bfloat162float(h1));
                __nv_bfloat16 l2 = __float2bfloat16(val[2] - __bfloat162float(h2));
                __nv_bfloat16 l3 = __float2bfloat16(val[3] - __bfloat162float(h3));
                h01 = (uint32_t)__bfloat16_as_ushort(h0) | ((uint32_t)__bfloat16_as_ushort(h1) << 16);
                h23 = (uint32_t)__bfloat16_as_ushort(h2) | ((uint32_t)__bfloat16_as_ushort(h3) << 16);
                l01 = (uint32_t)__bfloat16_as_ushort(l0) | ((uint32_t)__bfloat16_as_ushort(l1) << 16);
                l23 = (uint32_t)__bfloat16_as_ushort(l2) | ((uint32_t)__bfloat16_as_ushort(l3) << 16);
            }
            uint32_t ao = px * STRA + tap * 8;   // kk = tap*4 + c -> bytes tap*8 + c*2
            *reinterpret_cast<uint2*>(smem + DOFF_AH + ao) = make_uint2(h01, h23);
            *reinterpret_cast<uint2*>(smem + DOFF_AL + ao) = make_uint2(l01, l23);
        }
        __syncthreads();

        // MMA: K=48 in 3 chunks
        #pragma unroll
        for (int kc = 0; kc < 3; kc++) {
            const int k0b = kc * 32;
            uint32_t a_h[4], a_l[4];
            ldsm_x4(a_h, sbase + DOFF_AH + a_row * STRA + k0b + a_khalf);
            ldsm_x4(a_l, sbase + DOFF_AL + a_row * STRA + k0b + a_khalf);
            #pragma unroll
            for (int j = 0; j < 8; j++) {
                const int brow = j * 8 + b_rowin;
                uint32_t b_h[2], b_l[2];
                ldsm_x2(b_h, sbase + DOFF_BH + brow * STRA + k0b + b_khalf);
                ldsm_x2(b_l, sbase + DOFF_BL + brow * STRA + k0b + b_khalf);
                mma_bf16(C[j], a_h, b_h);
                mma_bf16(C[j], a_h, b_l);
                mma_bf16(C[j], a_l, b_h);
            }
        }
    }

    // epilogue -> dp[gsp]
    const int gfrag = lane >> 2, t = lane & 3;
    const int xp0 = mw * 16 + gfrag;
    float* dpo = dp + ((size_t)gsp * B + b) * 64 * HWc + y * Wc;
    #pragma unroll
    for (int j = 0; j < 8; j++) {
        #pragma unroll
        for (int r = 0; r < 4; r++) {
            const int co = j * 8 + t * 2 + (r & 1);
            const int xp = (r < 2) ? xp0 : xp0 + 8;
            dpo[(size_t)co * HWc + xp] = C[j][r];
        }
    }
}

// ---------------- combine partials (2-way) ----------------
__global__ __launch_bounds__(256)
void combine_kernel(const float* __restrict__ dp, float* __restrict__ out, int n4)
{
    int i = blockIdx.x * 256 + threadIdx.x;
    if (i < n4) {
        float4 a = reinterpret_cast<const float4*>(dp)[i];
        float4 c = reinterpret_cast<const float4*>(dp)[n4 + i];
        float4 o;
        o.x = a.x + c.x; o.y = a.y + c.y; o.z = a.z + c.z; o.w = a.w + c.w;
        reinterpret_cast<float4*>(out)[i] = o;
    }
}

// ---------------- launch ----------------
extern "C" void kernel_launch(void* const* d_in, const int* in_sizes, int n_in,
                              void* d_out, int out_size)
{
    const float* x    = (const float*)d_in[0];
    const float* ef   = (const float*)d_in[1];
    const float* flow = (const float*)d_in[2];
    const float* w1   = (const float*)d_in[3];
    const float* b1   = (const float*)d_in[4];
    const float* w2   = (const float*)d_in[5];
    const float* b2   = (const float*)d_in[6];
    const float* w3   = (const float*)d_in[7];
    const float* b3   = (const float*)d_in[8];
    const float* wgt  = (const float*)d_in[9];
    float* out = (float*)d_out;

    const int B = in_sizes[0] / (64 * HWc);  // = 2

    float *ppo, *pxt, *pdp;
    __nv_bfloat16 *pefh, *pefl, *ph1h, *ph1l, *ph2h, *ph2l;
    __nv_bfloat16 *pw1h, *pw1l, *pw2h, *pw2l, *pw3h, *pw3l, *pwdh, *pwdl;
    cudaGetSymbolAddress((void**)&ppo,  g_po);
    cudaGetSymbolAddress((void**)&pxt,  g_xt);
    cudaGetSymbolAddress((void**)&pdp,  g_dp);
    cudaGetSymbolAddress((void**)&pefh, g_efph);
    cudaGetSymbolAddress((void**)&pefl, g_efpl);
    cudaGetSymbolAddress((void**)&ph1h, g_h1ph);
    cudaGetSymbolAddress((void**)&ph1l, g_h1pl);
    cudaGetSymbolAddress((void**)&ph2h, g_h2ph);
    cudaGetSymbolAddress((void**)&ph2l, g_h2pl);
    cudaGetSymbolAddress((void**)&pw1h, g_w1bh);
    cudaGetSymbolAddress((void**)&pw1l, g_w1bl);
    cudaGetSymbolAddress((void**)&pw2h, g_w2bh);
    cudaGetSymbolAddress((void**)&pw2l, g_w2bl);
    cudaGetSymbolAddress((void**)&pw3h, g_w3bh);
    cudaGetSymbolAddress((void**)&pw3l, g_w3bl);
    cudaGetSymbolAddress((void**)&pwdh, g_wdh);
    cudaGetSymbolAddress((void**)&pwdl, g_wdl);

    constexpr int SMEM1 = 2 * 128 * (128 * 2 + 16) + 2 * 64 * (128 * 2 + 16);  // 104448
    constexpr int SMEM2 = 2 * 128 * (64 * 2 + 16) + 2 * 64 * (64 * 2 + 16);    // 55296
    cudaFuncSetAttribute(conv12_hmma_kernel<128>, cudaFuncAttributeMaxDynamicSharedMemorySize, SMEM1);
    cudaFuncSetAttribute(conv12_hmma_kernel<64>,  cudaFuncAttributeMaxDynamicSharedMemorySize, SMEM2);
    cudaFuncSetAttribute(conv3_hmma_kernel, cudaFuncAttributeMaxDynamicSharedMemorySize, SMEM3_TOTAL);
    cudaFuncSetAttribute(deform_hmma_kernel, cudaFuncAttributeMaxDynamicSharedMemorySize, DSMEM);

    // prep (independent)
    transpose_kernel<<<dim3(HWc / 256, 16, B), 256>>>(x, pxt);
    int nf_ef = B * HP * HP * 128 / 8;
    int nf_h  = B * HP * HP * 64 / 8;
    fill0_kernel<<<(nf_ef + 255) / 256, 256>>>(pefh, pefl, nf_ef);
    fill0_kernel<<<(nf_h + 255) / 256, 256>>>(ph1h, ph1l, nf_h);
    fill0_kernel<<<(nf_h + 255) / 256, 256>>>(ph2h, ph2l, nf_h);
    efprep_kernel<<<dim3(HWc / 256, 32, B), 256>>>(ef, pefh, pefl);
    wprep_kernel<64, 128><<<(9 * 64 * 128 + 255) / 256, 256>>>(w1, pw1h, pw1l);
    wprep_kernel<64, 64><<<(9 * 64 * 64 + 255) / 256, 256>>>(w2, pw2h, pw2l);
    wprep_kernel<432, 64><<<(9 * 432 * 64 + 255) / 256, 256>>>(w3, pw3h, pw3l);
    wdprep_kernel<<<(16 * 64 * 48 + 255) / 256, 256>>>(wgt, pwdh, pwdl);

    // conv chain (all HMMA)
    conv12_hmma_kernel<128><<<dim3(Hc, B), 256, SMEM1>>>(pefh, pefl, pw1h, pw1l, b1, ph1h, ph1l);
    conv12_hmma_kernel<64><<<dim3(Hc, B), 256, SMEM2>>>(ph1h, ph1l, pw2h, pw2l, b2, ph2h, ph2l);
    conv3_hmma_kernel<<<dim3(Hc, 3, B), 512, SMEM3_TOTAL>>>(ph2h, ph2l, pw3h, pw3l, b3, flow, ppo);

    // deformable gather + einsum via HMMA, 2-way group split
    deform_hmma_kernel<<<dim3(Hc, 2, B), 256, DSMEM>>>(pxt, ppo, pwdh, pwdl, pdp);
    int n4 = B * 64 * HWc / 4;
    combine_kernel<<<(n4 + 255) / 256, 256>>>(pdp, out, n4);
}

// round 13
// speedup vs baseline: 3.4749x; 1.0989x over previous
#include <cuda_runtime.h>
#include <cuda_bf16.h>
#include <cstdint>

constexpr int Hc = 128, Wc = 128, HWc = Hc * Wc;
constexpr int HP = 130;   // padded spatial dim

// ---------------- scratch (device globals; no allocation allowed) ----------------
__device__ float g_po[2 * 432 * HWc];
__device__ float g_xt[2 * 16 * HWc * 4];             // x transposed: [b][g][hw][4]
__device__ float g_dp[2 * 2 * 64 * HWc];             // [gsplit][b][co][hw]
__device__ __nv_bfloat16 g_efph[2 * HP * HP * 128];
__device__ __nv_bfloat16 g_efpl[2 * HP * HP * 128];
__device__ __nv_bfloat16 g_h1ph[2 * HP * HP * 64];
__device__ __nv_bfloat16 g_h1pl[2 * HP * HP * 64];
__device__ __nv_bfloat16 g_h2ph[2 * HP * HP * 64];
__device__ __nv_bfloat16 g_h2pl[2 * HP * HP * 64];
__device__ __nv_bfloat16 g_w1bh[9 * 64 * 128];
__device__ __nv_bfloat16 g_w1bl[9 * 64 * 128];
__device__ __nv_bfloat16 g_w2bh[9 * 64 * 64];
__device__ __nv_bfloat16 g_w2bl[9 * 64 * 64];
__device__ __nv_bfloat16 g_w3bh[9 * 432 * 64];
__device__ __nv_bfloat16 g_w3bl[9 * 432 * 64];
__device__ __nv_bfloat16 g_wdh[16 * 64 * 48];        // deform weight [g][co][kk] hi
__device__ __nv_bfloat16 g_wdl[16 * 64 * 48];        // lo

// ---------------- warp MMA helpers (arch-neutral PTX) ----------------
__device__ __forceinline__ uint32_t smem_to_u32(const void* p) {
    uint32_t a;
    asm("{ .reg .u64 t; cvta.to.shared.u64 t, %1; cvt.u32.u64 %0, t; }" : "=r"(a) : "l"(p));
    return a;
}
__device__ __forceinline__ void ldsm_x4(uint32_t (&r)[4], uint32_t addr) {
    asm volatile("ldmatrix.sync.aligned.m8n8.x4.shared.b16 {%0,%1,%2,%3}, [%4];"
        : "=r"(r[0]), "=r"(r[1]), "=r"(r[2]), "=r"(r[3]) : "r"(addr));
}
__device__ __forceinline__ void ldsm_x2(uint32_t (&r)[2], uint32_t addr) {
    asm volatile("ldmatrix.sync.aligned.m8n8.x2.shared.b16 {%0,%1}, [%2];"
        : "=r"(r[0]), "=r"(r[1]) : "r"(addr));
}
__device__ __forceinline__ void mma_bf16(float (&c)[4], const uint32_t (&a)[4], const uint32_t (&bb)[2]) {
    asm volatile("mma.sync.aligned.m16n8k16.row.col.f32.bf16.bf16.f32 "
        "{%0,%1,%2,%3}, {%4,%5,%6,%7}, {%8,%9}, {%0,%1,%2,%3};"
        : "+f"(c[0]), "+f"(c[1]), "+f"(c[2]), "+f"(c[3])
        : "r"(a[0]), "r"(a[1]), "r"(a[2]), "r"(a[3]), "r"(bb[0]), "r"(bb[1]));
}

// ---------------- fused fills ----------------
__global__ __launch_bounds__(256)
void fill_all_kernel(__nv_bfloat16* efh, __nv_bfloat16* efl,
                     __nv_bfloat16* h1h, __nv_bfloat16* h1l,
                     __nv_bfloat16* h2h, __nv_bfloat16* h2l,
                     int nef, int nh)
{
    int i = blockIdx.x * 256 + threadIdx.x;
    uint4 z = {0u, 0u, 0u, 0u};
    if (i < nef) {
        reinterpret_cast<uint4*>(efh)[i] = z;
        reinterpret_cast<uint4*>(efl)[i] = z;
    }
    if (i < nh) {
        reinterpret_cast<uint4*>(h1h)[i] = z;
        reinterpret_cast<uint4*>(h1l)[i] = z;
        reinterpret_cast<uint4*>(h2h)[i] = z;
        reinterpret_cast<uint4*>(h2l)[i] = z;
    }
}

__global__ __launch_bounds__(256)
void efprep_kernel(const float* __restrict__ ef, __nv_bfloat16* __restrict__ oh,
                   __nv_bfloat16* __restrict__ ol)
{
    int hw = blockIdx.x * 256 + threadIdx.x;
    int g  = blockIdx.y;
    int b  = blockIdx.z;
    int y = hw >> 7, x = hw & 127;
    const float* p = ef + ((size_t)b * 128 + g * 4) * HWc + hw;
    size_t base = ((size_t)(b * HP + y + 1) * HP + (x + 1)) * 128 + g * 4;
    #pragma unroll
    for (int c = 0; c < 4; c++) {
        float v = p[c * HWc];
        __nv_bfloat16 h = __float2bfloat16(v);
        __nv_bfloat16 l = __float2bfloat16(v - __bfloat162float(h));
        oh[base + c] = h;
        ol[base + c] = l;
    }
}

// ---------------- fused weight prep (w1, w2, w3, deform) ----------------
__device__ __forceinline__ void hilo_store(float v, __nv_bfloat16* wh, __nv_bfloat16* wl, int idx) {
    __nv_bfloat16 h = __float2bfloat16(v);
    wh[idx] = h;
    wl[idx] = __float2bfloat16(v - __bfloat162float(h));
}

constexpr int WSEG1 = 9 * 64 * 128;    // 73728
constexpr int WSEG2 = 9 * 64 * 64;     // 36864
constexpr int WSEG3 = 9 * 432 * 64;    // 248832
constexpr int WSEG4 = 16 * 64 * 48;    // 49152
constexpr int WTOT  = WSEG1 + WSEG2 + WSEG3 + WSEG4;

__global__ __launch_bounds__(256)
void wprep_all_kernel(const float* __restrict__ w1, const float* __restrict__ w2,
                      const float* __restrict__ w3, const float* __restrict__ wd,
                      __nv_bfloat16* wh1, __nv_bfloat16* wl1,
                      __nv_bfloat16* wh2, __nv_bfloat16* wl2,
                      __nv_bfloat16* wh3, __nv_bfloat16* wl3,
                      __nv_bfloat16* whd, __nv_bfloat16* wld)
{
    int idx = blockIdx.x * 256 + threadIdx.x;
    if (idx < WSEG1) {
        int ci = idx % 128, t = idx / 128, co = t % 64, k = t / 64;
        hilo_store(w1[(co * 128 + ci) * 9 + k], wh1, wl1, idx);
    } else if (idx < WSEG1 + WSEG2) {
        int j = idx - WSEG1;
        int ci = j % 64, t = j / 64, co = t % 64, k = t / 64;
        hilo_store(w2[(co * 64 + ci) * 9 + k], wh2, wl2, j);
    } else if (idx < WSEG1 + WSEG2 + WSEG3) {
        int j = idx - WSEG1 - WSEG2;
        int ci = j % 64, t = j / 64, co = t % 432, k = t / 432;
        hilo_store(w3[(co * 64 + ci) * 9 + k], wh3, wl3, j);
    } else if (idx < WTOT) {
        int j = idx - WSEG1 - WSEG2 - WSEG3;
        int kk = j % 48, t = j / 48, o = t % 64, g = t / 64;
        float v = 0.f;
        if (kk < 36) {
            int k = kk >> 2, c = kk & 3;
            v = wd[(o * 64 + g * 4 + c) * 9 + k];
        }
        hilo_store(v, whd, wld, j);
    }
}

// ---------------- conv1/conv2 via warp MMA, per-dy A staging ----------------
// Grid (Hc, B), block 256 = 8 M-warps; warp tile m16 x n64.
// A staged once per dy as 130 padded rows; taps dx=0..2 index A at row+dx.
template <int CIN>
__global__ __launch_bounds__(256)
void conv12_hmma_kernel(const __nv_bfloat16* __restrict__ inh, const __nv_bfloat16* __restrict__ inl,
                        const __nv_bfloat16* __restrict__ wbh, const __nv_bfloat16* __restrict__ wbl,
                        const float* __restrict__ bias,
                        __nv_bfloat16* __restrict__ outh, __nv_bfloat16* __restrict__ outl)
{
    constexpr int STRIDE = CIN * 2 + 16;
    constexpr int NU4 = CIN / 8;
    constexpr int KCH = CIN / 16;
    constexpr int OFF_AH = 0;
    constexpr int OFF_AL = 130 * STRIDE;
    constexpr int OFF_BH = 2 * 130 * STRIDE;
    constexpr int OFF_BL = OFF_BH + 64 * STRIDE;

    extern __shared__ char smem[];
    const uint32_t sbase = smem_to_u32(smem);
    const int tid  = threadIdx.x;
    const int mw   = tid / 32;
    const int lane = tid % 32;
    const int y    = blockIdx.x;
    const int b    = blockIdx.y;

    float C[8][4];
    #pragma unroll
    for (int j = 0; j < 8; j++)
        #pragma unroll
        for (int r = 0; r < 4; r++) C[j][r] = 0.f;

    const int a_row   = mw * 16 + (lane & 15);
    const int a_khalf = (lane & 16) ? 16 : 0;
    const int bl15    = lane & 15;
    const int b_rowin = bl15 & 7;
    const int b_khalf = (bl15 & 8) ? 16 : 0;

    #pragma unroll 1
    for (int dy = 0; dy < 3; dy++) {
        __syncthreads();
        // stage A: 130 padded rows, hi+lo
        const size_t abase = (size_t)(b * HP + y + dy) * HP * CIN;
        const uint4* gAh = reinterpret_cast<const uint4*>(inh + abase);
        const uint4* gAl = reinterpret_cast<const uint4*>(inl + abase);
        #pragma unroll 1
        for (int i = tid; i < 2 * 130 * NU4; i += 256) {
            int buf = i / (130 * NU4);
            int rem = i - buf * 130 * NU4;
            int r = rem / NU4, c = rem % NU4;
            uint4 v = (buf ? gAl : gAh)[r * NU4 + c];
            *reinterpret_cast<uint4*>(smem + (buf ? OFF_AL : OFF_AH) + r * STRIDE + c * 16) = v;
        }
        // stage B for tap dy*3
        {
            const int tap = dy * 3;
            const uint4* gBh = reinterpret_cast<const uint4*>(wbh + (size_t)tap * 64 * CIN);
            const uint4* gBl = reinterpret_cast<const uint4*>(wbl + (size_t)tap * 64 * CIN);
            #pragma unroll 1
            for (int i = tid; i < 2 * 64 * NU4; i += 256) {
                int buf = i / (64 * NU4);
                int rem = i - buf * 64 * NU4;
                int r = rem / NU4, c = rem % NU4;
                uint4 v = (buf ? gBl : gBh)[r * NU4 + c];
                *reinterpret_cast<uint4*>(smem + (buf ? OFF_BL : OFF_BH) + r * STRIDE + c * 16) = v;
            }
        }
        __syncthreads();

        #pragma unroll 1
        for (int dx = 0; dx < 3; dx++) {
            if (dx > 0) {
                __syncthreads();
                const int tap = dy * 3 + dx;
                const uint4* gBh = reinterpret_cast<const uint4*>(wbh + (size_t)tap * 64 * CIN);
                const uint4* gBl = reinterpret_cast<const uint4*>(wbl + (size_t)tap * 64 * CIN);
                #pragma unroll 1
                for (int i = tid; i < 2 * 64 * NU4; i += 256) {
                    int buf = i / (64 * NU4);
                    int rem = i - buf * 64 * NU4;
                    int r = rem / NU4, c = rem % NU4;
                    uint4 v = (buf ? gBl : gBh)[r * NU4 + c];
                    *reinterpret_cast<uint4*>(smem + (buf ? OFF_BL : OFF_BH) + r * STRIDE + c * 16) = v;
                }
                __syncthreads();
            }
            const uint32_t arow_b = (a_row + dx) * STRIDE + a_khalf;
            #pragma unroll 1
            for (int kc = 0; kc < KCH; kc++) {
                const int k0b = kc * 32;
                uint32_t a_h[4], a_l[4];
                ldsm_x4(a_h, sbase + OFF_AH + arow_b + k0b);
                ldsm_x4(a_l, sbase + OFF_AL + arow_b + k0b);
                #pragma unroll
                for (int j = 0; j < 8; j++) {
                    const int brow = j * 8 + b_rowin;
                    uint32_t b_h[2], b_l[2];
                    ldsm_x2(b_h, sbase + OFF_BH + brow * STRIDE + k0b + b_khalf);
                    ldsm_x2(b_l, sbase + OFF_BL + brow * STRIDE + k0b + b_khalf);
                    mma_bf16(C[j], a_h, b_h);
                    mma_bf16(C[j], a_h, b_l);
                    mma_bf16(C[j], a_l, b_h);
                }
            }
        }
    }

    const int g = lane >> 2, t = lane & 3;
    const int xp0 = mw * 16 + g;
    #pragma unroll
    for (int j = 0; j < 8; j++) {
        #pragma unroll
        for (int r = 0; r < 4; r++) {
            const int co = j * 8 + t * 2 + (r & 1);
            const int xp = (r < 2) ? xp0 : xp0 + 8;
            float v = C[j][r] + __ldg(&bias[co]);
            v = (v >= 0.f) ? v : 0.1f * v;
            __nv_bfloat16 h = __float2bfloat16(v);
            __nv_bfloat16 l = __float2bfloat16(v - __bfloat162float(h));
            size_t base = ((size_t)(b * HP + y + 1) * HP + (xp + 1)) * 64 + co;
            outh[base] = h;
            outl[base] = l;
        }
    }
}

// ---------------- conv3 via warp MMA, per-dy A staging ----------------
constexpr int STR3 = 144;
constexpr int OFF_AH3 = 0;
constexpr int OFF_AL3 = 130 * STR3;              // 18720
constexpr int OFF_BH3 = 2 * 130 * STR3;          // 37440
constexpr int OFF_BL3 = OFF_BH3 + 144 * STR3;    // 58176
constexpr int SMEM3_TOTAL = OFF_BL3 + 144 * STR3;  // 78912

__global__ __launch_bounds__(512)
void conv3_hmma_kernel(const __nv_bfloat16* __restrict__ h2ph, const __nv_bfloat16* __restrict__ h2pl,
                       const __nv_bfloat16* __restrict__ wbh, const __nv_bfloat16* __restrict__ wbl,
                       const float* __restrict__ b3, const float* __restrict__ flow,
                       float* __restrict__ po)
{
    extern __shared__ char smem[];
    const uint32_t sbase = smem_to_u32(smem);
    const int tid  = threadIdx.x;
    const int wid  = tid / 32;
    const int lane = tid % 32;
    const int mw   = wid / 2;
    const int wn   = wid % 2;
    const int y    = blockIdx.x;
    const int nt   = blockIdx.y;
    const int b    = blockIdx.z;

    float C[9][4];
    #pragma unroll
    for (int j = 0; j < 9; j++)
        #pragma unroll
        for (int r = 0; r < 4; r++) C[j][r] = 0.f;

    const int a_row = mw * 16 + (lane & 15);
    const int a_khalf = (lane & 16) ? 16 : 0;
    const int bl15 = lane & 15;
    const int b_rowin = bl15 & 7;
    const int b_khalf = (bl15 & 8) ? 16 : 0;

    #pragma unroll 1
    for (int dy = 0; dy < 3; dy++) {
        __syncthreads();
        const size_t abase = (size_t)(b * HP + y + dy) * HP * 64;
        const uint4* gAh = reinterpret_cast<const uint4*>(h2ph + abase);
        const uint4* gAl = reinterpret_cast<const uint4*>(h2pl + abase);
        #pragma unroll 1
        for (int i = tid; i < 2 * 130 * 8; i += 512) {
            int buf = i / 1040;
            int rem = i - buf * 1040;
            int r = rem >> 3, c = rem & 7;
            uint4 v = (buf ? gAl : gAh)[r * 8 + c];
            *reinterpret_cast<uint4*>(smem + (buf ? OFF_AL3 : OFF_AH3) + r * STR3 + c * 16) = v;
        }
        {
            const int tap = dy * 3;
            const uint4* gBh = reinterpret_cast<const uint4*>(wbh + ((size_t)tap * 432 + nt * 144) * 64);
            const uint4* gBl = reinterpret_cast<const uint4*>(wbl + ((size_t)tap * 432 + nt * 144) * 64);
            #pragma unroll 1
            for (int i = tid; i < 2304; i += 512) {
                int buf = (i >= 1152) ? 1 : 0;
                int j2  = buf ? i - 1152 : i;
                int r = j2 >> 3, c = j2 & 7;
                uint4 v = (buf ? gBl : gBh)[r * 8 + c];
                *reinterpret_cast<uint4*>(smem + (buf ? OFF_BL3 : OFF_BH3) + r * STR3 + c * 16) = v;
            }
        }
        __syncthreads();

        #pragma unroll 1
        for (int dx = 0; dx < 3; dx++) {
            if (dx > 0) {
                __syncthreads();
                const int tap = dy * 3 + dx;
                const uint4* gBh = reinterpret_cast<const uint4*>(wbh + ((size_t)tap * 432 + nt * 144) * 64);
                const uint4* gBl = reinterpret_cast<const uint4*>(wbl + ((size_t)tap * 432 + nt * 144) * 64);
                #pragma unroll 1
                for (int i = tid; i < 2304; i += 512) {
                    int buf = (i >= 1152) ? 1 : 0;
                    int j2  = buf ? i - 1152 : i;
                    int r = j2 >> 3, c = j2 & 7;
                    uint4 v = (buf ? gBl : gBh)[r * 8 + c];
                    *reinterpret_cast<uint4*>(smem + (buf ? OFF_BL3 : OFF_BH3) + r * STR3 + c * 16) = v;
                }
                __syncthreads();
            }
            const uint32_t arow_b = (a_row + dx) * STR3 + a_khalf;
            #pragma unroll
            for (int kc = 0; kc < 4; kc++) {
                const int k0b = kc * 32;
                uint32_t a_h[4], a_l[4];
                ldsm_x4(a_h, sbase + OFF_AH3 + arow_b + k0b);
                ldsm_x4(a_l, sbase + OFF_AL3 + arow_b + k0b);
                #pragma unroll
                for (int j = 0; j < 9; j++) {
                    const int brow = wn * 72 + j * 8 + b_rowin;
                    uint32_t b_h[2], b_l[2];
                    ldsm_x2(b_h, sbase + OFF_BH3 + brow * STR3 + k0b + b_khalf);
                    ldsm_x2(b_l, sbase + OFF_BL3 + brow * STR3 + k0b + b_khalf);
                    mma_bf16(C[j], a_h, b_h);
                    mma_bf16(C[j], a_h, b_l);
                    mma_bf16(C[j], a_l, b_h);
                }
            }
        }
    }

    const int g = lane >> 2, t = lane & 3;
    const int hw0 = y * Wc + mw * 16 + g;
    const int hw1 = hw0 + 8;
    const float fy0 = flow[(b * 2 + 1) * HWc + hw0];
    const float fx0 = flow[(b * 2 + 0) * HWc + hw0];
    const float fy1 = flow[(b * 2 + 1) * HWc + hw1];
    const float fx1 = flow[(b * 2 + 0) * HWc + hw1];
    #pragma unroll
    for (int j = 0; j < 9; j++) {
        const int cobase = nt * 144 + wn * 72 + j * 8 + t * 2;
        #pragma unroll
        for (int r = 0; r < 4; r++) {
            const int co = cobase + (r & 1);
            const int hw = (r < 2) ? hw0 : hw1;
            float v = C[j][r] + __ldg(&b3[co]);
            if (co < 288) {
                const float fyv = (r < 2) ? fy0 : fy1;
                const float fxv = (r < 2) ? fx0 : fx1;
                v = 10.f * tanhf(v) + ((co & 1) ? fxv : fyv);
            } else {
                v = 1.f / (1.f + expf(-v));
            }
            po[((size_t)b * 432 + co) * HWc + hw] = v;
        }
    }
}

// ---------------- x transpose ----------------
__global__ __launch_bounds__(256)
void transpose_kernel(const float* __restrict__ x, float* __restrict__ xt)
{
    int hw = blockIdx.x * 256 + threadIdx.x;
    int g  = blockIdx.y;
    int b  = blockIdx.z;
    const float* xp = x + (b * 64 + g * 4) * HWc + hw;
    float4 v;
    v.x = xp[0];
    v.y = xp[HWc];
    v.z = xp[2 * HWc];
    v.w = xp[3 * HWc];
    reinterpret_cast<float4*>(xt + ((b * 16 + g) * HWc + hw) * 4)[0] = v;
}

// ---------------- deformable gather + einsum via HMMA ----------------
constexpr int STRA = 112;   // bytes per smem row (48 bf16 data + 8 pad)
constexpr int DOFF_AH = 0;
constexpr int DOFF_AL = 128 * STRA;           // 14336
constexpr int DOFF_BH = 2 * 128 * STRA;       // 28672
constexpr int DOFF_BL = DOFF_BH + 64 * STRA;  // 35840
constexpr int DSMEM = DOFF_BL + 64 * STRA;    // 43008

__global__ __launch_bounds__(256)
void deform_hmma_kernel(const float* __restrict__ xt, const float* __restrict__ po,
                        const __nv_bfloat16* __restrict__ wdh, const __nv_bfloat16* __restrict__ wdl,
                        float* __restrict__ dp)
{
    extern __shared__ char smem[];
    const uint32_t sbase = smem_to_u32(smem);
    const int tid  = threadIdx.x;
    const int mw   = tid / 32;
    const int lane = tid % 32;
    const int y    = blockIdx.x;
    const int gsp  = blockIdx.y;
    const int b    = blockIdx.z;
    const int B    = gridDim.z;

    float C[8][4];
    #pragma unroll
    for (int j = 0; j < 8; j++)
        #pragma unroll
        for (int r = 0; r < 4; r++) C[j][r] = 0.f;

    // zero A K-pad region (kk 36..47) once
    #pragma unroll 1
    for (int i = tid; i < 128 * 2 * 6; i += 256) {
        int w = i % 6;
        int r = (i / 6) % 128;
        int buf = i / (6 * 128);
        *reinterpret_cast<uint32_t*>(smem + (buf ? DOFF_AL : DOFF_AH) + r * STRA + 72 + w * 4) = 0u;
    }

    const int a_row   = mw * 16 + (lane & 15);
    const int a_khalf = (lane & 16) ? 16 : 0;
    const int bl15    = lane & 15;
    const int b_rowin = bl15 & 7;
    const int b_khalf = (bl15 & 8) ? 16 : 0;

    const float* pobase = po + (size_t)b * 432 * HWc + y * Wc;
    const float* xtb = xt + (size_t)b * 16 * HWc * 4;

    #pragma unroll 1
    for (int gl = 0; gl < 8; gl++) {
        const int g = gsp * 8 + gl;
        __syncthreads();

        const uint4* gBh = reinterpret_cast<const uint4*>(wdh + (size_t)g * 64 * 48);
        const uint4* gBl = reinterpret_cast<const uint4*>(wdl + (size_t)g * 64 * 48);
        #pragma unroll 1
        for (int i = tid; i < 2 * 64 * 6; i += 256) {
            int buf = i / 384;
            int rem = i - buf * 384;
            int r = rem / 6, c = rem % 6;
            uint4 v = (buf ? gBl : gBh)[r * 6 + c];
            *reinterpret_cast<uint4*>(smem + (buf ? DOFF_BL : DOFF_BH) + r * STRA + c * 16) = v;
        }

        const float4* xg = reinterpret_cast<const float4*>(xtb + (size_t)g * HWc * 4);
        #pragma unroll 1
        for (int i = tid; i < 9 * 128; i += 256) {
            const int px  = i & 127;
            const int tap = i >> 7;
            const int gk  = g * 9 + tap;
            const float* pob = pobase + px;
            float offy = pob[(2 * gk) * HWc];
            float offx = pob[(2 * gk + 1) * HWc];
            float msk  = pob[(288 + gk) * HWc];

            float py = (float)(y + tap / 3 - 1) + offy;
            float pxf = (float)(px + tap % 3 - 1) + offx;
            float fy = floorf(py), fxv = floorf(pxf);
            int iy0 = (int)fy, ix0 = (int)fxv;
            float wy = py - fy, wx = pxf - fxv;

            bool vy0 = (unsigned)iy0       < (unsigned)Hc;
            bool vy1 = (unsigned)(iy0 + 1) < (unsigned)Hc;
            bool vx0 = (unsigned)ix0       < (unsigned)Wc;
            bool vx1 = (unsigned)(ix0 + 1) < (unsigned)Wc;
            int cy0 = min(max(iy0, 0), Hc - 1), cy1 = min(max(iy0 + 1, 0), Hc - 1);
            int cx0 = min(max(ix0, 0), Wc - 1), cx1 = min(max(ix0 + 1, 0), Wc - 1);

            float w00 = (1.f - wy) * (1.f - wx) * msk; if (!(vy0 && vx0)) w00 = 0.f;
            float w01 = (1.f - wy) * wx        * msk; if (!(vy0 && vx1)) w01 = 0.f;
            float w10 = wy        * (1.f - wx) * msk; if (!(vy1 && vx0)) w10 = 0.f;
            float w11 = wy        * wx         * msk; if (!(vy1 && vx1)) w11 = 0.f;

            float4 p00 = __ldg(xg + cy0 * Wc + cx0);
            float4 p01 = __ldg(xg + cy0 * Wc + cx1);
            float4 p10 = __ldg(xg + cy1 * Wc + cx0);
            float4 p11 = __ldg(xg + cy1 * Wc + cx1);

            float val[4];
            val[0] = w00 * p00.x + w01 * p01.x + w10 * p10.x + w11 * p11.x;
            val[1] = w00 * p00.y + w01 * p01.y + w10 * p10.y + w11 * p11.y;
            val[2] = w00 * p00.z + w01 * p01.z + w10 * p10.z + w11 * p11.z;
            val[3] = w00 * p00.w + w01 * p01.w + w10 * p10.w + w11 * p11.w;

            uint32_t h01, h23, l01, l23;
            {
                __nv_bfloat16 h0 = __float2bfloat16(val[0]);
                __nv_bfloat16 h1 = __float2bfloat16(val[1]);
                __nv_bfloat16 h2 = __float2bfloat16(val[2]);
                __nv_bfloat16 h3 = __float2bfloat16(val[3]);
                __nv_bfloat16 l0 = __float2bfloat16(val[0] - __bfloat162float(h0));
                __nv_bfloat16 l1 = __float2bfloat16(val[1] - __bfloat162float(h1));
                __nv_bfloat16 l2 = __float2bfloat16(val[2] - __bfloat162float(h2));
                __nv_bfloat16 l3 = __float2bfloat16(val[3] - __bfloat162float(h3));
                h01 = (uint32_t)__bfloat16_as_ushort(h0) | ((uint32_t)__bfloat16_as_ushort(h1) << 16);
                h23 = (uint32_t)__bfloat16_as_ushort(h2) | ((uint32_t)__bfloat16_as_ushort(h3) << 16);
                l01 = (uint32_t)__bfloat16_as_ushort(l0) | ((uint32_t)__bfloat16_as_ushort(l1) << 16);
                l23 = (uint32_t)__bfloat16_as_ushort(l2) | ((uint32_t)__bfloat16_as_ushort(l3) << 16);
            }
            uint32_t ao = px * STRA + tap * 8;
            *reinterpret_cast<uint2*>(smem + DOFF_AH + ao) = make_uint2(h01, h23);
            *reinterpret_cast<uint2*>(smem + DOFF_AL + ao) = make_uint2(l01, l23);
        }
        __syncthreads();

        #pragma unroll
        for (int kc = 0; kc < 3; kc++) {
            const int k0b = kc * 32;
            uint32_t a_h[4], a_l[4];
            ldsm_x4(a_h, sbase + DOFF_AH + a_row * STRA + k0b + a_khalf);
            ldsm_x4(a_l, sbase + DOFF_AL + a_row * STRA + k0b + a_khalf);
            #pragma unroll
            for (int j = 0; j < 8; j++) {
                const int brow = j * 8 + b_rowin;
                uint32_t b_h[2], b_l[2];
                ldsm_x2(b_h, sbase + DOFF_BH + brow * STRA + k0b + b_khalf);
                ldsm_x2(b_l, sbase + DOFF_BL + brow * STRA + k0b + b_khalf);
                mma_bf16(C[j], a_h, b_h);
                mma_bf16(C[j], a_h, b_l);
                mma_bf16(C[j], a_l, b_h);
            }
        }
    }

    const int gfrag = lane >> 2, t = lane & 3;
    const int xp0 = mw * 16 + gfrag;
    float* dpo = dp + ((size_t)gsp * B + b) * 64 * HWc + y * Wc;
    #pragma unroll
    for (int j = 0; j < 8; j++) {
        #pragma unroll
        for (int r = 0; r < 4; r++) {
            const int co = j * 8 + t * 2 + (r & 1);
            const int xp = (r < 2) ? xp0 : xp0 + 8;
            dpo[(size_t)co * HWc + xp] = C[j][r];
        }
    }
}

// ---------------- combine partials (2-way) ----------------
__global__ __launch_bounds__(256)
void combine_kernel(const float* __restrict__ dp, float* __restrict__ out, int n4)
{
    int i = blockIdx.x * 256 + threadIdx.x;
    if (i < n4) {
        float4 a = reinterpret_cast<const float4*>(dp)[i];
        float4 c = reinterpret_cast<const float4*>(dp)[n4 + i];
        float4 o;
        o.x = a.x + c.x; o.y = a.y + c.y; o.z = a.z + c.z; o.w = a.w + c.w;
        reinterpret_cast<float4*>(out)[i] = o;
    }
}

// ---------------- launch ----------------
extern "C" void kernel_launch(void* const* d_in, const int* in_sizes, int n_in,
                              void* d_out, int out_size)
{
    const float* x    = (const float*)d_in[0];
    const float* ef   = (const float*)d_in[1];
    const float* flow = (const float*)d_in[2];
    const float* w1   = (const float*)d_in[3];
    const float* b1   = (const float*)d_in[4];
    const float* w2   = (const float*)d_in[5];
    const float* b2   = (const float*)d_in[6];
    const float* w3   = (const float*)d_in[7];
    const float* b3   = (const float*)d_in[8];
    const float* wgt  = (const float*)d_in[9];
    float* out = (float*)d_out;

    const int B = in_sizes[0] / (64 * HWc);  // = 2

    float *ppo, *pxt, *pdp;
    __nv_bfloat16 *pefh, *pefl, *ph1h, *ph1l, *ph2h, *ph2l;
    __nv_bfloat16 *pw1h, *pw1l, *pw2h, *pw2l, *pw3h, *pw3l, *pwdh, *pwdl;
    cudaGetSymbolAddress((void**)&ppo,  g_po);
    cudaGetSymbolAddress((void**)&pxt,  g_xt);
    cudaGetSymbolAddress((void**)&pdp,  g_dp);
    cudaGetSymbolAddress((void**)&pefh, g_efph);
    cudaGetSymbolAddress((void**)&pefl, g_efpl);
    cudaGetSymbolAddress((void**)&ph1h, g_h1ph);
    cudaGetSymbolAddress((void**)&ph1l, g_h1pl);
    cudaGetSymbolAddress((void**)&ph2h, g_h2ph);
    cudaGetSymbolAddress((void**)&ph2l, g_h2pl);
    cudaGetSymbolAddress((void**)&pw1h, g_w1bh);
    cudaGetSymbolAddress((void**)&pw1l, g_w1bl);
    cudaGetSymbolAddress((void**)&pw2h, g_w2bh);
    cudaGetSymbolAddress((void**)&pw2l, g_w2bl);
    cudaGetSymbolAddress((void**)&pw3h, g_w3bh);
    cudaGetSymbolAddress((void**)&pw3l, g_w3bl);
    cudaGetSymbolAddress((void**)&pwdh, g_wdh);
    cudaGetSymbolAddress((void**)&pwdl, g_wdl);

    constexpr int STR1 = 128 * 2 + 16;
    constexpr int STR2 = 64 * 2 + 16;
    constexpr int SMEM1 = 2 * 130 * STR1 + 2 * 64 * STR1;  // 105536
    constexpr int SMEM2 = 2 * 130 * STR2 + 2 * 64 * STR2;  // 55872
    cudaFuncSetAttribute(conv12_hmma_kernel<128>, cudaFuncAttributeMaxDynamicSharedMemorySize, SMEM1);
    cudaFuncSetAttribute(conv12_hmma_kernel<64>,  cudaFuncAttributeMaxDynamicSharedMemorySize, SMEM2);
    cudaFuncSetAttribute(conv3_hmma_kernel, cudaFuncAttributeMaxDynamicSharedMemorySize, SMEM3_TOTAL);
    cudaFuncSetAttribute(deform_hmma_kernel, cudaFuncAttributeMaxDynamicSharedMemorySize, DSMEM);

    // prep
    transpose_kernel<<<dim3(HWc / 256, 16, B), 256>>>(x, pxt);
    int nf_ef = B * HP * HP * 128 / 8;
    int nf_h  = B * HP * HP * 64 / 8;
    fill_all_kernel<<<(nf_ef + 255) / 256, 256>>>(pefh, pefl, ph1h, ph1l, ph2h, ph2l, nf_ef, nf_h);
    efprep_kernel<<<dim3(HWc / 256, 32, B), 256>>>(ef, pefh, pefl);
    wprep_all_kernel<<<(WTOT + 255) / 256, 256>>>(w1, w2, w3, wgt,
                                                  pw1h, pw1l, pw2h, pw2l, pw3h, pw3l, pwdh, pwdl);

    // conv chain (all HMMA)
    conv12_hmma_kernel<128><<<dim3(Hc, B), 256, SMEM1>>>(pefh, pefl, pw1h, pw1l, b1, ph1h, ph1l);
    conv12_hmma_kernel<64><<<dim3(Hc, B), 256, SMEM2>>>(ph1h, ph1l, pw2h, pw2l, b2, ph2h, ph2l);
    conv3_hmma_kernel<<<dim3(Hc, 3, B), 512, SMEM3_TOTAL>>>(ph2h, ph2l, pw3h, pw3l, b3, flow, ppo);

    // deformable gather + einsum via HMMA, 2-way group split
    deform_hmma_kernel<<<dim3(Hc, 2, B), 256, DSMEM>>>(pxt, ppo, pwdh, pwdl, pdp);
    int n4 = B * 64 * HWc / 4;
    combine_kernel<<<(n4 + 255) / 256, 256>>>(pdp, out, n4);
}

// round 14
// speedup vs baseline: 3.5819x; 1.0308x over previous
#include <cuda_runtime.h>
#include <cuda_bf16.h>
#include <cstdint>

constexpr int Hc = 128, Wc = 128, HWc = Hc * Wc;
constexpr int HP = 130;   // padded spatial dim

// ---------------- scratch (device globals; no allocation allowed) ----------------
__device__ float g_po[2 * 432 * HWc];
__device__ float g_xt[2 * 16 * HWc * 4];             // x transposed: [b][g][hw][4]
__device__ float g_dp[4 * 2 * 64 * HWc];             // [gsplit][b][co][hw]
__device__ __nv_bfloat16 g_efph[2 * HP * HP * 128];
__device__ __nv_bfloat16 g_efpl[2 * HP * HP * 128];
__device__ __nv_bfloat16 g_h1ph[2 * HP * HP * 64];
__device__ __nv_bfloat16 g_h1pl[2 * HP * HP * 64];
__device__ __nv_bfloat16 g_h2ph[2 * HP * HP * 64];
__device__ __nv_bfloat16 g_h2pl[2 * HP * HP * 64];
__device__ __nv_bfloat16 g_w1bh[9 * 64 * 128];
__device__ __nv_bfloat16 g_w1bl[9 * 64 * 128];
__device__ __nv_bfloat16 g_w2bh[9 * 64 * 64];
__device__ __nv_bfloat16 g_w2bl[9 * 64 * 64];
__device__ __nv_bfloat16 g_w3bh[9 * 432 * 64];
__device__ __nv_bfloat16 g_w3bl[9 * 432 * 64];
__device__ __nv_bfloat16 g_wdh[16 * 64 * 48];        // deform weight [g][co][kk] hi
__device__ __nv_bfloat16 g_wdl[16 * 64 * 48];        // lo

// ---------------- warp MMA helpers (arch-neutral PTX) ----------------
__device__ __forceinline__ uint32_t smem_to_u32(const void* p) {
    uint32_t a;
    asm("{ .reg .u64 t; cvta.to.shared.u64 t, %1; cvt.u32.u64 %0, t; }" : "=r"(a) : "l"(p));
    return a;
}
__device__ __forceinline__ void ldsm_x4(uint32_t (&r)[4], uint32_t addr) {
    asm volatile("ldmatrix.sync.aligned.m8n8.x4.shared.b16 {%0,%1,%2,%3}, [%4];"
        : "=r"(r[0]), "=r"(r[1]), "=r"(r[2]), "=r"(r[3]) : "r"(addr));
}
__device__ __forceinline__ void ldsm_x2(uint32_t (&r)[2], uint32_t addr) {
    asm volatile("ldmatrix.sync.aligned.m8n8.x2.shared.b16 {%0,%1}, [%2];"
        : "=r"(r[0]), "=r"(r[1]) : "r"(addr));
}
__device__ __forceinline__ void mma_bf16(float (&c)[4], const uint32_t (&a)[4], const uint32_t (&bb)[2]) {
    asm volatile("mma.sync.aligned.m16n8k16.row.col.f32.bf16.bf16.f32 "
        "{%0,%1,%2,%3}, {%4,%5,%6,%7}, {%8,%9}, {%0,%1,%2,%3};"
        : "+f"(c[0]), "+f"(c[1]), "+f"(c[2]), "+f"(c[3])
        : "r"(a[0]), "r"(a[1]), "r"(a[2]), "r"(a[3]), "r"(bb[0]), "r"(bb[1]));
}

// ---------------- border-only zero fill ----------------
__device__ __forceinline__ void border_yx(int p, int& y, int& x) {
    if (p < 130)      { y = 0;        x = p; }
    else if (p < 260) { y = 129;      x = p - 130; }
    else if (p < 388) { y = p - 259;  x = 0; }       // rows 1..128
    else              { y = p - 387;  x = 129; }
}

__global__ __launch_bounds__(256)
void fill_border_kernel(__nv_bfloat16* efh, __nv_bfloat16* efl,
                        __nv_bfloat16* h1h, __nv_bfloat16* h1l,
                        __nv_bfloat16* h2h, __nv_bfloat16* h2l, int B)
{
    int i = blockIdx.x * 256 + threadIdx.x;
    uint4 z = {0u, 0u, 0u, 0u};
    int nef = B * 516 * 16;   // 128 ch * 2B = 16 uint4 per pixel
    int nh  = B * 516 * 8;    // 64 ch * 2B = 8 uint4 per pixel
    if (i < nef) {
        int c = i % 16, t = i / 16, p = t % 516, b = t / 516;
        int y, x;
        border_yx(p, y, x);
        size_t base = ((size_t)(b * HP + y) * HP + x) * 128;
        reinterpret_cast<uint4*>(efh + base)[c] = z;
        reinterpret_cast<uint4*>(efl + base)[c] = z;
    }
    if (i < nh) {
        int c = i % 8, t = i / 8, p = t % 516, b = t / 516;
        int y, x;
        border_yx(p, y, x);
        size_t base = ((size_t)(b * HP + y) * HP + x) * 64;
        reinterpret_cast<uint4*>(h1h + base)[c] = z;
        reinterpret_cast<uint4*>(h1l + base)[c] = z;
        reinterpret_cast<uint4*>(h2h + base)[c] = z;
        reinterpret_cast<uint4*>(h2l + base)[c] = z;
    }
}

__global__ __launch_bounds__(256)
void efprep_kernel(const float* __restrict__ ef, __nv_bfloat16* __restrict__ oh,
                   __nv_bfloat16* __restrict__ ol)
{
    int hw = blockIdx.x * 256 + threadIdx.x;
    int g  = blockIdx.y;
    int b  = blockIdx.z;
    int y = hw >> 7, x = hw & 127;
    const float* p = ef + ((size_t)b * 128 + g * 4) * HWc + hw;
    size_t base = ((size_t)(b * HP + y + 1) * HP + (x + 1)) * 128 + g * 4;
    #pragma unroll
    for (int c = 0; c < 4; c++) {
        float v = p[c * HWc];
        __nv_bfloat16 h = __float2bfloat16(v);
        __nv_bfloat16 l = __float2bfloat16(v - __bfloat162float(h));
        oh[base + c] = h;
        ol[base + c] = l;
    }
}

// ---------------- fused weight prep (w1, w2, w3, deform) ----------------
__device__ __forceinline__ void hilo_store(float v, __nv_bfloat16* wh, __nv_bfloat16* wl, int idx) {
    __nv_bfloat16 h = __float2bfloat16(v);
    wh[idx] = h;
    wl[idx] = __float2bfloat16(v - __bfloat162float(h));
}

constexpr int WSEG1 = 9 * 64 * 128;    // 73728
constexpr int WSEG2 = 9 * 64 * 64;     // 36864
constexpr int WSEG3 = 9 * 432 * 64;    // 248832
constexpr int WSEG4 = 16 * 64 * 48;    // 49152
constexpr int WTOT  = WSEG1 + WSEG2 + WSEG3 + WSEG4;

__global__ __launch_bounds__(256)
void wprep_all_kernel(const float* __restrict__ w1, const float* __restrict__ w2,
                      const float* __restrict__ w3, const float* __restrict__ wd,
                      __nv_bfloat16* wh1, __nv_bfloat16* wl1,
                      __nv_bfloat16* wh2, __nv_bfloat16* wl2,
                      __nv_bfloat16* wh3, __nv_bfloat16* wl3,
                      __nv_bfloat16* whd, __nv_bfloat16* wld)
{
    int idx = blockIdx.x * 256 + threadIdx.x;
    if (idx < WSEG1) {
        int ci = idx % 128, t = idx / 128, co = t % 64, k = t / 64;
        hilo_store(w1[(co * 128 + ci) * 9 + k], wh1, wl1, idx);
    } else if (idx < WSEG1 + WSEG2) {
        int j = idx - WSEG1;
        int ci = j % 64, t = j / 64, co = t % 64, k = t / 64;
        hilo_store(w2[(co * 64 + ci) * 9 + k], wh2, wl2, j);
    } else if (idx < WSEG1 + WSEG2 + WSEG3) {
        int j = idx - WSEG1 - WSEG2;
        int ci = j % 64, t = j / 64, co = t % 432, k = t / 432;
        hilo_store(w3[(co * 64 + ci) * 9 + k], wh3, wl3, j);
    } else if (idx < WTOT) {
        int j = idx - WSEG1 - WSEG2 - WSEG3;
        int kk = j % 48, t = j / 48, o = t % 64, g = t / 64;
        float v = 0.f;
        if (kk < 36) {
            int k = kk >> 2, c = kk & 3;
            v = wd[(o * 64 + g * 4 + c) * 9 + k];
        }
        hilo_store(v, whd, wld, j);
    }
}

// ---------------- conv1/conv2 via warp MMA, per-dy A staging ----------------
template <int CIN>
__global__ __launch_bounds__(256)
void conv12_hmma_kernel(const __nv_bfloat16* __restrict__ inh, const __nv_bfloat16* __restrict__ inl,
                        const __nv_bfloat16* __restrict__ wbh, const __nv_bfloat16* __restrict__ wbl,
                        const float* __restrict__ bias,
                        __nv_bfloat16* __restrict__ outh, __nv_bfloat16* __restrict__ outl)
{
    constexpr int STRIDE = CIN * 2 + 16;
    constexpr int NU4 = CIN / 8;
    constexpr int KCH = CIN / 16;
    constexpr int OFF_AH = 0;
    constexpr int OFF_AL = 130 * STRIDE;
    constexpr int OFF_BH = 2 * 130 * STRIDE;
    constexpr int OFF_BL = OFF_BH + 64 * STRIDE;

    extern __shared__ char smem[];
    const uint32_t sbase = smem_to_u32(smem);
    const int tid  = threadIdx.x;
    const int mw   = tid / 32;
    const int lane = tid % 32;
    const int y    = blockIdx.x;
    const int b    = blockIdx.y;

    float C[8][4];
    #pragma unroll
    for (int j = 0; j < 8; j++)
        #pragma unroll
        for (int r = 0; r < 4; r++) C[j][r] = 0.f;

    const int a_row   = mw * 16 + (lane & 15);
    const int a_khalf = (lane & 16) ? 16 : 0;
    const int bl15    = lane & 15;
    const int b_rowin = bl15 & 7;
    const int b_khalf = (bl15 & 8) ? 16 : 0;

    #pragma unroll 1
    for (int dy = 0; dy < 3; dy++) {
        __syncthreads();
        const size_t abase = (size_t)(b * HP + y + dy) * HP * CIN;
        const uint4* gAh = reinterpret_cast<const uint4*>(inh + abase);
        const uint4* gAl = reinterpret_cast<const uint4*>(inl + abase);
        #pragma unroll 1
        for (int i = tid; i < 2 * 130 * NU4; i += 256) {
            int buf = i / (130 * NU4);
            int rem = i - buf * 130 * NU4;
            int r = rem / NU4, c = rem % NU4;
            uint4 v = (buf ? gAl : gAh)[r * NU4 + c];
            *reinterpret_cast<uint4*>(smem + (buf ? OFF_AL : OFF_AH) + r * STRIDE + c * 16) = v;
        }
        {
            const int tap = dy * 3;
            const uint4* gBh = reinterpret_cast<const uint4*>(wbh + (size_t)tap * 64 * CIN);
            const uint4* gBl = reinterpret_cast<const uint4*>(wbl + (size_t)tap * 64 * CIN);
            #pragma unroll 1
            for (int i = tid; i < 2 * 64 * NU4; i += 256) {
                int buf = i / (64 * NU4);
                int rem = i - buf * 64 * NU4;
                int r = rem / NU4, c = rem % NU4;
                uint4 v = (buf ? gBl : gBh)[r * NU4 + c];
                *reinterpret_cast<uint4*>(smem + (buf ? OFF_BL : OFF_BH) + r * STRIDE + c * 16) = v;
            }
        }
        __syncthreads();

        #pragma unroll 1
        for (int dx = 0; dx < 3; dx++) {
            if (dx > 0) {
                __syncthreads();
                const int tap = dy * 3 + dx;
                const uint4* gBh = reinterpret_cast<const uint4*>(wbh + (size_t)tap * 64 * CIN);
                const uint4* gBl = reinterpret_cast<const uint4*>(wbl + (size_t)tap * 64 * CIN);
                #pragma unroll 1
                for (int i = tid; i < 2 * 64 * NU4; i += 256) {
                    int buf = i / (64 * NU4);
                    int rem = i - buf * 64 * NU4;
                    int r = rem / NU4, c = rem % NU4;
                    uint4 v = (buf ? gBl : gBh)[r * NU4 + c];
                    *reinterpret_cast<uint4*>(smem + (buf ? OFF_BL : OFF_BH) + r * STRIDE + c * 16) = v;
                }
                __syncthreads();
            }
            const uint32_t arow_b = (a_row + dx) * STRIDE + a_khalf;
            #pragma unroll 1
            for (int kc = 0; kc < KCH; kc++) {
                const int k0b = kc * 32;
                uint32_t a_h[4], a_l[4];
                ldsm_x4(a_h, sbase + OFF_AH + arow_b + k0b);
                ldsm_x4(a_l, sbase + OFF_AL + arow_b + k0b);
                #pragma unroll
                for (int j = 0; j < 8; j++) {
                    const int brow = j * 8 + b_rowin;
                    uint32_t b_h[2], b_l[2];
                    ldsm_x2(b_h, sbase + OFF_BH + brow * STRIDE + k0b + b_khalf);
                    ldsm_x2(b_l, sbase + OFF_BL + brow * STRIDE + k0b + b_khalf);
                    mma_bf16(C[j], a_h, b_h);
                    mma_bf16(C[j], a_h, b_l);
                    mma_bf16(C[j], a_l, b_h);
                }
            }
        }
    }

    const int g = lane >> 2, t = lane & 3;
    const int xp0 = mw * 16 + g;
    #pragma unroll
    for (int j = 0; j < 8; j++) {
        #pragma unroll
        for (int r = 0; r < 4; r++) {
            const int co = j * 8 + t * 2 + (r & 1);
            const int xp = (r < 2) ? xp0 : xp0 + 8;
            float v = C[j][r] + __ldg(&bias[co]);
            v = (v >= 0.f) ? v : 0.1f * v;
            __nv_bfloat16 h = __float2bfloat16(v);
            __nv_bfloat16 l = __float2bfloat16(v - __bfloat162float(h));
            size_t base = ((size_t)(b * HP + y + 1) * HP + (xp + 1)) * 64 + co;
            outh[base] = h;
            outl[base] = l;
        }
    }
}

// ---------------- conv3 via warp MMA, per-dy A staging ----------------
constexpr int STR3 = 144;
constexpr int OFF_AH3 = 0;
constexpr int OFF_AL3 = 130 * STR3;
constexpr int OFF_BH3 = 2 * 130 * STR3;
constexpr int OFF_BL3 = OFF_BH3 + 144 * STR3;
constexpr int SMEM3_TOTAL = OFF_BL3 + 144 * STR3;  // 78912

__global__ __launch_bounds__(512)
void conv3_hmma_kernel(const __nv_bfloat16* __restrict__ h2ph, const __nv_bfloat16* __restrict__ h2pl,
                       const __nv_bfloat16* __restrict__ wbh, const __nv_bfloat16* __restrict__ wbl,
                       const float* __restrict__ b3, const float* __restrict__ flow,
                       float* __restrict__ po)
{
    extern __shared__ char smem[];
    const uint32_t sbase = smem_to_u32(smem);
    const int tid  = threadIdx.x;
    const int wid  = tid / 32;
    const int lane = tid % 32;
    const int mw   = wid / 2;
    const int wn   = wid % 2;
    const int y    = blockIdx.x;
    const int nt   = blockIdx.y;
    const int b    = blockIdx.z;

    float C[9][4];
    #pragma unroll
    for (int j = 0; j < 9; j++)
        #pragma unroll
        for (int r = 0; r < 4; r++) C[j][r] = 0.f;

    const int a_row = mw * 16 + (lane & 15);
    const int a_khalf = (lane & 16) ? 16 : 0;
    const int bl15 = lane & 15;
    const int b_rowin = bl15 & 7;
    const int b_khalf = (bl15 & 8) ? 16 : 0;

    #pragma unroll 1
    for (int dy = 0; dy < 3; dy++) {
        __syncthreads();
        const size_t abase = (size_t)(b * HP + y + dy) * HP * 64;
        const uint4* gAh = reinterpret_cast<const uint4*>(h2ph + abase);
        const uint4* gAl = reinterpret_cast<const uint4*>(h2pl + abase);
        #pragma unroll 1
        for (int i = tid; i < 2 * 130 * 8; i += 512) {
            int buf = i / 1040;
            int rem = i - buf * 1040;
            int r = rem >> 3, c = rem & 7;
            uint4 v = (buf ? gAl : gAh)[r * 8 + c];
            *reinterpret_cast<uint4*>(smem + (buf ? OFF_AL3 : OFF_AH3) + r * STR3 + c * 16) = v;
        }
        {
            const int tap = dy * 3;
            const uint4* gBh = reinterpret_cast<const uint4*>(wbh + ((size_t)tap * 432 + nt * 144) * 64);
            const uint4* gBl = reinterpret_cast<const uint4*>(wbl + ((size_t)tap * 432 + nt * 144) * 64);
            #pragma unroll 1
            for (int i = tid; i < 2304; i += 512) {
                int buf = (i >= 1152) ? 1 : 0;
                int j2  = buf ? i - 1152 : i;
                int r = j2 >> 3, c = j2 & 7;
                uint4 v = (buf ? gBl : gBh)[r * 8 + c];
                *reinterpret_cast<uint4*>(smem + (buf ? OFF_BL3 : OFF_BH3) + r * STR3 + c * 16) = v;
            }
        }
        __syncthreads();

        #pragma unroll 1
        for (int dx = 0; dx < 3; dx++) {
            if (dx > 0) {
                __syncthreads();
                const int tap = dy * 3 + dx;
                const uint4* gBh = reinterpret_cast<const uint4*>(wbh + ((size_t)tap * 432 + nt * 144) * 64);
                const uint4* gBl = reinterpret_cast<const uint4*>(wbl + ((size_t)tap * 432 + nt * 144) * 64);
                #pragma unroll 1
                for (int i = tid; i < 2304; i += 512) {
                    int buf = (i >= 1152) ? 1 : 0;
                    int j2  = buf ? i - 1152 : i;
                    int r = j2 >> 3, c = j2 & 7;
                    uint4 v = (buf ? gBl : gBh)[r * 8 + c];
                    *reinterpret_cast<uint4*>(smem + (buf ? OFF_BL3 : OFF_BH3) + r * STR3 + c * 16) = v;
                }
                __syncthreads();
            }
            const uint32_t arow_b = (a_row + dx) * STR3 + a_khalf;
            #pragma unroll
            for (int kc = 0; kc < 4; kc++) {
                const int k0b = kc * 32;
                uint32_t a_h[4], a_l[4];
                ldsm_x4(a_h, sbase + OFF_AH3 + arow_b + k0b);
                ldsm_x4(a_l, sbase + OFF_AL3 + arow_b + k0b);
                #pragma unroll
                for (int j = 0; j < 9; j++) {
                    const int brow = wn * 72 + j * 8 + b_rowin;
                    uint32_t b_h[2], b_l[2];
                    ldsm_x2(b_h, sbase + OFF_BH3 + brow * STR3 + k0b + b_khalf);
                    ldsm_x2(b_l, sbase + OFF_BL3 + brow * STR3 + k0b + b_khalf);
                    mma_bf16(C[j], a_h, b_h);
                    mma_bf16(C[j], a_h, b_l);
                    mma_bf16(C[j], a_l, b_h);
                }
            }
        }
    }

    const int g = lane >> 2, t = lane & 3;
    const int hw0 = y * Wc + mw * 16 + g;
    const int hw1 = hw0 + 8;
    const float fy0 = flow[(b * 2 + 1) * HWc + hw0];
    const float fx0 = flow[(b * 2 + 0) * HWc + hw0];
    const float fy1 = flow[(b * 2 + 1) * HWc + hw1];
    const float fx1 = flow[(b * 2 + 0) * HWc + hw1];
    #pragma unroll
    for (int j = 0; j < 9; j++) {
        const int cobase = nt * 144 + wn * 72 + j * 8 + t * 2;
        #pragma unroll
        for (int r = 0; r < 4; r++) {
            const int co = cobase + (r & 1);
            const int hw = (r < 2) ? hw0 : hw1;
            float v = C[j][r] + __ldg(&b3[co]);
            if (co < 288) {
                const float fyv = (r < 2) ? fy0 : fy1;
                const float fxv = (r < 2) ? fx0 : fx1;
                v = 10.f * tanhf(v) + ((co & 1) ? fxv : fyv);
            } else {
                v = 1.f / (1.f + expf(-v));
            }
            po[((size_t)b * 432 + co) * HWc + hw] = v;
        }
    }
}

// ---------------- x transpose ----------------
__global__ __launch_bounds__(256)
void transpose_kernel(const float* __restrict__ x, float* __restrict__ xt)
{
    int hw = blockIdx.x * 256 + threadIdx.x;
    int g  = blockIdx.y;
    int b  = blockIdx.z;
    const float* xp = x + (b * 64 + g * 4) * HWc + hw;
    float4 v;
    v.x = xp[0];
    v.y = xp[HWc];
    v.z = xp[2 * HWc];
    v.w = xp[3 * HWc];
    reinterpret_cast<float4*>(xt + ((b * 16 + g) * HWc + hw) * 4)[0] = v;
}

// ---------------- deformable gather + einsum via HMMA, 4-way group split ----------------
constexpr int NSPL = 4;
constexpr int GPS  = 16 / NSPL;   // 4 groups per block
constexpr int STRA = 112;
constexpr int DOFF_AH = 0;
constexpr int DOFF_AL = 128 * STRA;
constexpr int DOFF_BH = 2 * 128 * STRA;
constexpr int DOFF_BL = DOFF_BH + 64 * STRA;
constexpr int DSMEM = DOFF_BL + 64 * STRA;    // 43008

__global__ __launch_bounds__(256)
void deform_hmma_kernel(const float* __restrict__ xt, const float* __restrict__ po,
                        const __nv_bfloat16* __restrict__ wdh, const __nv_bfloat16* __restrict__ wdl,
                        float* __restrict__ dp)
{
    extern __shared__ char smem[];
    const uint32_t sbase = smem_to_u32(smem);
    const int tid  = threadIdx.x;
    const int mw   = tid / 32;
    const int lane = tid % 32;
    const int y    = blockIdx.x;
    const int gsp  = blockIdx.y;
    const int b    = blockIdx.z;
    const int B    = gridDim.z;

    float C[8][4];
    #pragma unroll
    for (int j = 0; j < 8; j++)
        #pragma unroll
        for (int r = 0; r < 4; r++) C[j][r] = 0.f;

    // zero A K-pad region (kk 36..47) once
    #pragma unroll 1
    for (int i = tid; i < 128 * 2 * 6; i += 256) {
        int w = i % 6;
        int r = (i / 6) % 128;
        int buf = i / (6 * 128);
        *reinterpret_cast<uint32_t*>(smem + (buf ? DOFF_AL : DOFF_AH) + r * STRA + 72 + w * 4) = 0u;
    }

    const int a_row   = mw * 16 + (lane & 15);
    const int a_khalf = (lane & 16) ? 16 : 0;
    const int bl15    = lane & 15;
    const int b_rowin = bl15 & 7;
    const int b_khalf = (bl15 & 8) ? 16 : 0;

    const float* pobase = po + (size_t)b * 432 * HWc + y * Wc;
    const float* xtb = xt + (size_t)b * 16 * HWc * 4;

    #pragma unroll 1
    for (int gl = 0; gl < GPS; gl++) {
        const int g = gsp * GPS + gl;
        __syncthreads();

        const uint4* gBh = reinterpret_cast<const uint4*>(wdh + (size_t)g * 64 * 48);
        const uint4* gBl = reinterpret_cast<const uint4*>(wdl + (size_t)g * 64 * 48);
        #pragma unroll 1
        for (int i = tid; i < 2 * 64 * 6; i += 256) {
            int buf = i / 384;
            int rem = i - buf * 384;
            int r = rem / 6, c = rem % 6;
            uint4 v = (buf ? gBl : gBh)[r * 6 + c];
            *reinterpret_cast<uint4*>(smem + (buf ? DOFF_BL : DOFF_BH) + r * STRA + c * 16) = v;
        }

        const float4* xg = reinterpret_cast<const float4*>(xtb + (size_t)g * HWc * 4);
        #pragma unroll 1
        for (int i = tid; i < 9 * 128; i += 256) {
            const int px  = i & 127;
            const int tap = i >> 7;
            const int gk  = g * 9 + tap;
            const float* pob = pobase + px;
            float offy = pob[(2 * gk) * HWc];
            float offx = pob[(2 * gk + 1) * HWc];
            float msk  = pob[(288 + gk) * HWc];

            float py = (float)(y + tap / 3 - 1) + offy;
            float pxf = (float)(px + tap % 3 - 1) + offx;
            float fy = floorf(py), fxv = floorf(pxf);
            int iy0 = (int)fy, ix0 = (int)fxv;
            float wy = py - fy, wx = pxf - fxv;

            bool vy0 = (unsigned)iy0       < (unsigned)Hc;
            bool vy1 = (unsigned)(iy0 + 1) < (unsigned)Hc;
            bool vx0 = (unsigned)ix0       < (unsigned)Wc;
            bool vx1 = (unsigned)(ix0 + 1) < (unsigned)Wc;
            int cy0 = min(max(iy0, 0), Hc - 1), cy1 = min(max(iy0 + 1, 0), Hc - 1);
            int cx0 = min(max(ix0, 0), Wc - 1), cx1 = min(max(ix0 + 1, 0), Wc - 1);

            float w00 = (1.f - wy) * (1.f - wx) * msk; if (!(vy0 && vx0)) w00 = 0.f;
            float w01 = (1.f - wy) * wx        * msk; if (!(vy0 && vx1)) w01 = 0.f;
            float w10 = wy        * (1.f - wx) * msk; if (!(vy1 && vx0)) w10 = 0.f;
            float w11 = wy        * wx         * msk; if (!(vy1 && vx1)) w11 = 0.f;

            float4 p00 = __ldg(xg + cy0 * Wc + cx0);
            float4 p01 = __ldg(xg + cy0 * Wc + cx1);
            float4 p10 = __ldg(xg + cy1 * Wc + cx0);
            float4 p11 = __ldg(xg + cy1 * Wc + cx1);

            float val[4];
            val[0] = w00 * p00.x + w01 * p01.x + w10 * p10.x + w11 * p11.x;
            val[1] = w00 * p00.y + w01 * p01.y + w10 * p10.y + w11 * p11.y;
            val[2] = w00 * p00.z + w01 * p01.z + w10 * p10.z + w11 * p11.z;
            val[3] = w00 * p00.w + w01 * p01.w + w10 * p10.w + w11 * p11.w;

            uint32_t h01, h23, l01, l23;
            {
                __nv_bfloat16 h0 = __float2bfloat16(val[0]);
                __nv_bfloat16 h1 = __float2bfloat16(val[1]);
                __nv_bfloat16 h2 = __float2bfloat16(val[2]);
                __nv_bfloat16 h3 = __float2bfloat16(val[3]);
                __nv_bfloat16 l0 = __float2bfloat16(val[0] - __bfloat162float(h0));
                __nv_bfloat16 l1 = __float2bfloat16(val[1] - __bfloat162float(h1));
                __nv_bfloat16 l2 = __float2bfloat16(val[2] - __bfloat162float(h2));
                __nv_bfloat16 l3 = __float2bfloat16(val[3] - __bfloat162float(h3));
                h01 = (uint32_t)__bfloat16_as_ushort(h0) | ((uint32_t)__bfloat16_as_ushort(h1) << 16);
                h23 = (uint32_t)__bfloat16_as_ushort(h2) | ((uint32_t)__bfloat16_as_ushort(h3) << 16);
                l01 = (uint32_t)__bfloat16_as_ushort(l0) | ((uint32_t)__bfloat16_as_ushort(l1) << 16);
                l23 = (uint32_t)__bfloat16_as_ushort(l2) | ((uint32_t)__bfloat16_as_ushort(l3) << 16);
            }
            uint32_t ao = px * STRA + tap * 8;
            *reinterpret_cast<uint2*>(smem + DOFF_AH + ao) = make_uint2(h01, h23);
            *reinterpret_cast<uint2*>(smem + DOFF_AL + ao) = make_uint2(l01, l23);
        }
        __syncthreads();

        #pragma unroll
        for (int kc = 0; kc < 3; kc++) {
            const int k0b = kc * 32;
            uint32_t a_h[4], a_l[4];
            ldsm_x4(a_h, sbase + DOFF_AH + a_row * STRA + k0b + a_khalf);
            ldsm_x4(a_l, sbase + DOFF_AL + a_row * STRA + k0b + a_khalf);
            #pragma unroll
            for (int j = 0; j < 8; j++) {
                const int brow = j * 8 + b_rowin;
                uint32_t b_h[2], b_l[2];
                ldsm_x2(b_h, sbase + DOFF_BH + brow * STRA + k0b + b_khalf);
                ldsm_x2(b_l, sbase + DOFF_BL + brow * STRA + k0b + b_khalf);
                mma_bf16(C[j], a_h, b_h);
                mma_bf16(C[j], a_h, b_l);
                mma_bf16(C[j], a_l, b_h);
            }
        }
    }

    const int gfrag = lane >> 2, t = lane & 3;
    const int xp0 = mw * 16 + gfrag;
    float* dpo = dp + ((size_t)gsp * B + b) * 64 * HWc + y * Wc;
    #pragma unroll
    for (int j = 0; j < 8; j++) {
        #pragma unroll
        for (int r = 0; r < 4; r++) {
            const int co = j * 8 + t * 2 + (r & 1);
            const int xp = (r < 2) ? xp0 : xp0 + 8;
            dpo[(size_t)co * HWc + xp] = C[j][r];
        }
    }
}

// ---------------- combine partials (4-way) ----------------
__global__ __launch_bounds__(256)
void combine_kernel(const float* __restrict__ dp, float* __restrict__ out, int n4)
{
    int i = blockIdx.x * 256 + threadIdx.x;
    if (i < n4) {
        float4 a0 = reinterpret_cast<const float4*>(dp)[i];
        float4 a1 = reinterpret_cast<const float4*>(dp)[n4 + i];
        float4 a2 = reinterpret_cast<const float4*>(dp)[2 * n4 + i];
        float4 a3 = reinterpret_cast<const float4*>(dp)[3 * n4 + i];
        float4 o;
        o.x = (a0.x + a1.x) + (a2.x + a3.x);
        o.y = (a0.y + a1.y) + (a2.y + a3.y);
        o.z = (a0.z + a1.z) + (a2.z + a3.z);
        o.w = (a0.w + a1.w) + (a2.w + a3.w);
        reinterpret_cast<float4*>(out)[i] = o;
    }
}

// ---------------- launch ----------------
extern "C" void kernel_launch(void* const* d_in, const int* in_sizes, int n_in,
                              void* d_out, int out_size)
{
    const float* x    = (const float*)d_in[0];
    const float* ef   = (const float*)d_in[1];
    const float* flow = (const float*)d_in[2];
    const float* w1   = (const float*)d_in[3];
    const float* b1   = (const float*)d_in[4];
    const float* w2   = (const float*)d_in[5];
    const float* b2   = (const float*)d_in[6];
    const float* w3   = (const float*)d_in[7];
    const float* b3   = (const float*)d_in[8];
    const float* wgt  = (const float*)d_in[9];
    float* out = (float*)d_out;

    const int B = in_sizes[0] / (64 * HWc);  // = 2

    float *ppo, *pxt, *pdp;
    __nv_bfloat16 *pefh, *pefl, *ph1h, *ph1l, *ph2h, *ph2l;
    __nv_bfloat16 *pw1h, *pw1l, *pw2h, *pw2l, *pw3h, *pw3l, *pwdh, *pwdl;
    cudaGetSymbolAddress((void**)&ppo,  g_po);
    cudaGetSymbolAddress((void**)&pxt,  g_xt);
    cudaGetSymbolAddress((void**)&pdp,  g_dp);
    cudaGetSymbolAddress((void**)&pefh, g_efph);
    cudaGetSymbolAddress((void**)&pefl, g_efpl);
    cudaGetSymbolAddress((void**)&ph1h, g_h1ph);
    cudaGetSymbolAddress((void**)&ph1l, g_h1pl);
    cudaGetSymbolAddress((void**)&ph2h, g_h2ph);
    cudaGetSymbolAddress((void**)&ph2l, g_h2pl);
    cudaGetSymbolAddress((void**)&pw1h, g_w1bh);
    cudaGetSymbolAddress((void**)&pw1l, g_w1bl);
    cudaGetSymbolAddress((void**)&pw2h, g_w2bh);
    cudaGetSymbolAddress((void**)&pw2l, g_w2bl);
    cudaGetSymbolAddress((void**)&pw3h, g_w3bh);
    cudaGetSymbolAddress((void**)&pw3l, g_w3bl);
    cudaGetSymbolAddress((void**)&pwdh, g_wdh);
    cudaGetSymbolAddress((void**)&pwdl, g_wdl);

    constexpr int STR1 = 128 * 2 + 16;
    constexpr int STR2 = 64 * 2 + 16;
    constexpr int SMEM1 = 2 * 130 * STR1 + 2 * 64 * STR1;  // 105536
    constexpr int SMEM2 = 2 * 130 * STR2 + 2 * 64 * STR2;  // 55872
    cudaFuncSetAttribute(conv12_hmma_kernel<128>, cudaFuncAttributeMaxDynamicSharedMemorySize, SMEM1);
    cudaFuncSetAttribute(conv12_hmma_kernel<64>,  cudaFuncAttributeMaxDynamicSharedMemorySize, SMEM2);
    cudaFuncSetAttribute(conv3_hmma_kernel, cudaFuncAttributeMaxDynamicSharedMemorySize, SMEM3_TOTAL);
    cudaFuncSetAttribute(deform_hmma_kernel, cudaFuncAttributeMaxDynamicSharedMemorySize, DSMEM);

    // prep
    transpose_kernel<<<dim3(HWc / 256, 16, B), 256>>>(x, pxt);
    int nborder = B * 516 * 16;
    fill_border_kernel<<<(nborder + 255) / 256, 256>>>(pefh, pefl, ph1h, ph1l, ph2h, ph2l, B);
    efprep_kernel<<<dim3(HWc / 256, 32, B), 256>>>(ef, pefh, pefl);
    wprep_all_kernel<<<(WTOT + 255) / 256, 256>>>(w1, w2, w3, wgt,
                                                  pw1h, pw1l, pw2h, pw2l, pw3h, pw3l, pwdh, pwdl);

    // conv chain (all HMMA)
    conv12_hmma_kernel<128><<<dim3(Hc, B), 256, SMEM1>>>(pefh, pefl, pw1h, pw1l, b1, ph1h, ph1l);
    conv12_hmma_kernel<64><<<dim3(Hc, B), 256, SMEM2>>>(ph1h, ph1l, pw2h, pw2l, b2, ph2h, ph2l);
    conv3_hmma_kernel<<<dim3(Hc, 3, B), 512, SMEM3_TOTAL>>>(ph2h, ph2l, pw3h, pw3l, b3, flow, ppo);

    // deformable gather + einsum via HMMA, 4-way group split
    deform_hmma_kernel<<<dim3(Hc, NSPL, B), 256, DSMEM>>>(pxt, ppo, pwdh, pwdl, pdp);
    int n4 = B * 64 * HWc / 4;
    combine_kernel<<<(n4 + 255) / 256, 256>>>(pdp, out, n4);
}

// round 15
// speedup vs baseline: 3.6389x; 1.0159x over previous
#include <cuda_runtime.h>
#include <cuda_bf16.h>
#include <cstdint>

constexpr int Hc = 128, Wc = 128, HWc = Hc * Wc;
constexpr int HP = 130;   // padded spatial dim

// ---------------- scratch (device globals; no allocation allowed) ----------------
__device__ float g_po[2 * 432 * HWc];
__device__ float g_xt[2 * 16 * HWc * 4];             // x transposed: [b][g][hw][4]
__device__ float g_dp[4 * 2 * 64 * HWc];             // [gsplit][b][co][hw]
__device__ __nv_bfloat16 g_efph[2 * HP * HP * 128];
__device__ __nv_bfloat16 g_efpl[2 * HP * HP * 128];
__device__ __nv_bfloat16 g_h1ph[2 * HP * HP * 64];
__device__ __nv_bfloat16 g_h1pl[2 * HP * HP * 64];
__device__ __nv_bfloat16 g_h2ph[2 * HP * HP * 64];
__device__ __nv_bfloat16 g_h2pl[2 * HP * HP * 64];
__device__ __nv_bfloat16 g_w1bh[9 * 64 * 128];
__device__ __nv_bfloat16 g_w1bl[9 * 64 * 128];
__device__ __nv_bfloat16 g_w2bh[9 * 64 * 64];
__device__ __nv_bfloat16 g_w2bl[9 * 64 * 64];
__device__ __nv_bfloat16 g_w3bh[9 * 432 * 64];
__device__ __nv_bfloat16 g_w3bl[9 * 432 * 64];
__device__ __nv_bfloat16 g_wdh[16 * 64 * 48];
__device__ __nv_bfloat16 g_wdl[16 * 64 * 48];

// ---------------- warp MMA helpers (arch-neutral PTX) ----------------
__device__ __forceinline__ uint32_t smem_to_u32(const void* p) {
    uint32_t a;
    asm("{ .reg .u64 t; cvta.to.shared.u64 t, %1; cvt.u32.u64 %0, t; }" : "=r"(a) : "l"(p));
    return a;
}
__device__ __forceinline__ void ldsm_x4(uint32_t (&r)[4], uint32_t addr) {
    asm volatile("ldmatrix.sync.aligned.m8n8.x4.shared.b16 {%0,%1,%2,%3}, [%4];"
        : "=r"(r[0]), "=r"(r[1]), "=r"(r[2]), "=r"(r[3]) : "r"(addr));
}
__device__ __forceinline__ void ldsm_x2(uint32_t (&r)[2], uint32_t addr) {
    asm volatile("ldmatrix.sync.aligned.m8n8.x2.shared.b16 {%0,%1}, [%2];"
        : "=r"(r[0]), "=r"(r[1]) : "r"(addr));
}
__device__ __forceinline__ void mma_bf16(float (&c)[4], const uint32_t (&a)[4], const uint32_t (&bb)[2]) {
    asm volatile("mma.sync.aligned.m16n8k16.row.col.f32.bf16.bf16.f32 "
        "{%0,%1,%2,%3}, {%4,%5,%6,%7}, {%8,%9}, {%0,%1,%2,%3};"
        : "+f"(c[0]), "+f"(c[1]), "+f"(c[2]), "+f"(c[3])
        : "r"(a[0]), "r"(a[1]), "r"(a[2]), "r"(a[3]), "r"(bb[0]), "r"(bb[1]));
}

__device__ __forceinline__ void hilo_store(float v, __nv_bfloat16* wh, __nv_bfloat16* wl, int idx) {
    __nv_bfloat16 h = __float2bfloat16(v);
    wh[idx] = h;
    wl[idx] = __float2bfloat16(v - __bfloat162float(h));
}

__device__ __forceinline__ void border_yx(int p, int& y, int& x) {
    if (p < 130)      { y = 0;        x = p; }
    else if (p < 260) { y = 129;      x = p - 130; }
    else if (p < 388) { y = p - 259;  x = 0; }
    else              { y = p - 387;  x = 129; }
}

// ---------------- fused prep: transpose + border fill + efprep + wprep ----------------
constexpr int WSEG1 = 9 * 64 * 128;
constexpr int WSEG2 = 9 * 64 * 64;
constexpr int WSEG3 = 9 * 432 * 64;
constexpr int WSEG4 = 16 * 64 * 48;
constexpr int WTOT  = WSEG1 + WSEG2 + WSEG3 + WSEG4;

__global__ __launch_bounds__(256)
void prep_all_kernel(const float* __restrict__ x, float* __restrict__ xt,
                     const float* __restrict__ ef,
                     __nv_bfloat16* __restrict__ efh, __nv_bfloat16* __restrict__ efl,
                     __nv_bfloat16* h1h, __nv_bfloat16* h1l,
                     __nv_bfloat16* h2h, __nv_bfloat16* h2l,
                     const float* __restrict__ w1, const float* __restrict__ w2,
                     const float* __restrict__ w3, const float* __restrict__ wd,
                     __nv_bfloat16* wh1, __nv_bfloat16* wl1,
                     __nv_bfloat16* wh2, __nv_bfloat16* wl2,
                     __nv_bfloat16* wh3, __nv_bfloat16* wl3,
                     __nv_bfloat16* whd, __nv_bfloat16* wld,
                     int B, int t_end, int e_end, int f_end)
{
    const int blk = blockIdx.x;
    const int tid = threadIdx.x;
    if (blk < t_end) {
        // transpose x: [b][64][HW] -> [b][g][hw][4]
        int hw = (blk & 63) * 256 + tid;
        int g  = (blk >> 6) & 15;
        int b  = blk >> 10;
        const float* xp = x + ((size_t)b * 64 + g * 4) * HWc + hw;
        float4 v;
        v.x = xp[0];
        v.y = xp[HWc];
        v.z = xp[2 * HWc];
        v.w = xp[3 * HWc];
        reinterpret_cast<float4*>(xt + (((size_t)b * 16 + g) * HWc + hw) * 4)[0] = v;
    } else if (blk < e_end) {
        // efprep: fp32 CHW -> bf16 hi/lo padded HWC
        int j = blk - t_end;
        int hw = (j & 63) * 256 + tid;
        int g  = (j >> 6) & 31;
        int b  = j >> 11;
        int y = hw >> 7, xx = hw & 127;
        const float* p = ef + ((size_t)b * 128 + g * 4) * HWc + hw;
        size_t base = ((size_t)(b * HP + y + 1) * HP + (xx + 1)) * 128 + g * 4;
        #pragma unroll
        for (int c = 0; c < 4; c++) {
            float v = p[c * HWc];
            __nv_bfloat16 h = __float2bfloat16(v);
            efh[base + c] = h;
            efl[base + c] = __float2bfloat16(v - __bfloat162float(h));
        }
    } else if (blk < f_end) {
        // border fill
        int i = (blk - e_end) * 256 + tid;
        uint4 z = {0u, 0u, 0u, 0u};
        int nef = B * 516 * 16;
        int nh  = B * 516 * 8;
        if (i < nef) {
            int c = i % 16, t = i / 16, p = t % 516, b = t / 516;
            int y, xx;
            border_yx(p, y, xx);
            size_t base = ((size_t)(b * HP + y) * HP + xx) * 128;
            reinterpret_cast<uint4*>(efh + base)[c] = z;
            reinterpret_cast<uint4*>(efl + base)[c] = z;
        }
        if (i < nh) {
            int c = i % 8, t = i / 8, p = t % 516, b = t / 516;
            int y, xx;
            border_yx(p, y, xx);
            size_t base = ((size_t)(b * HP + y) * HP + xx) * 64;
            reinterpret_cast<uint4*>(h1h + base)[c] = z;
            reinterpret_cast<uint4*>(h1l + base)[c] = z;
            reinterpret_cast<uint4*>(h2h + base)[c] = z;
            reinterpret_cast<uint4*>(h2l + base)[c] = z;
        }
    } else {
        // wprep
        int idx = (blk - f_end) * 256 + tid;
        if (idx < WSEG1) {
            int ci = idx % 128, t = idx / 128, co = t % 64, k = t / 64;
            hilo_store(w1[(co * 128 + ci) * 9 + k], wh1, wl1, idx);
        } else if (idx < WSEG1 + WSEG2) {
            int j = idx - WSEG1;
            int ci = j % 64, t = j / 64, co = t % 64, k = t / 64;
            hilo_store(w2[(co * 64 + ci) * 9 + k], wh2, wl2, j);
        } else if (idx < WSEG1 + WSEG2 + WSEG3) {
            int j = idx - WSEG1 - WSEG2;
            int ci = j % 64, t = j / 64, co = t % 432, k = t / 432;
            hilo_store(w3[(co * 64 + ci) * 9 + k], wh3, wl3, j);
        } else if (idx < WTOT) {
            int j = idx - WSEG1 - WSEG2 - WSEG3;
            int kk = j % 48, t = j / 48, o = t % 64, g = t / 64;
            float v = 0.f;
            if (kk < 36) {
                int k = kk >> 2, c = kk & 3;
                v = wd[(o * 64 + g * 4 + c) * 9 + k];
            }
            hilo_store(v, whd, wld, j);
        }
    }
}

// ---------------- conv1/conv2 via warp MMA, per-dy A staging ----------------
template <int CIN>
__global__ __launch_bounds__(256)
void conv12_hmma_kernel(const __nv_bfloat16* __restrict__ inh, const __nv_bfloat16* __restrict__ inl,
                        const __nv_bfloat16* __restrict__ wbh, const __nv_bfloat16* __restrict__ wbl,
                        const float* __restrict__ bias,
                        __nv_bfloat16* __restrict__ outh, __nv_bfloat16* __restrict__ outl)
{
    constexpr int STRIDE = CIN * 2 + 16;
    constexpr int NU4 = CIN / 8;
    constexpr int KCH = CIN / 16;
    constexpr int OFF_AH = 0;
    constexpr int OFF_AL = 130 * STRIDE;
    constexpr int OFF_BH = 2 * 130 * STRIDE;
    constexpr int OFF_BL = OFF_BH + 64 * STRIDE;

    extern __shared__ char smem[];
    const uint32_t sbase = smem_to_u32(smem);
    const int tid  = threadIdx.x;
    const int mw   = tid / 32;
    const int lane = tid % 32;
    const int y    = blockIdx.x;
    const int b    = blockIdx.y;

    float C[8][4];
    #pragma unroll
    for (int j = 0; j < 8; j++)
        #pragma unroll
        for (int r = 0; r < 4; r++) C[j][r] = 0.f;

    const int a_row   = mw * 16 + (lane & 15);
    const int a_khalf = (lane & 16) ? 16 : 0;
    const int bl15    = lane & 15;
    const int b_rowin = bl15 & 7;
    const int b_khalf = (bl15 & 8) ? 16 : 0;

    #pragma unroll 1
    for (int dy = 0; dy < 3; dy++) {
        __syncthreads();
        const size_t abase = (size_t)(b * HP + y + dy) * HP * CIN;
        const uint4* gAh = reinterpret_cast<const uint4*>(inh + abase);
        const uint4* gAl = reinterpret_cast<const uint4*>(inl + abase);
        #pragma unroll 1
        for (int i = tid; i < 2 * 130 * NU4; i += 256) {
            int buf = i / (130 * NU4);
            int rem = i - buf * 130 * NU4;
            int r = rem / NU4, c = rem % NU4;
            uint4 v = (buf ? gAl : gAh)[r * NU4 + c];
            *reinterpret_cast<uint4*>(smem + (buf ? OFF_AL : OFF_AH) + r * STRIDE + c * 16) = v;
        }
        {
            const int tap = dy * 3;
            const uint4* gBh = reinterpret_cast<const uint4*>(wbh + (size_t)tap * 64 * CIN);
            const uint4* gBl = reinterpret_cast<const uint4*>(wbl + (size_t)tap * 64 * CIN);
            #pragma unroll 1
            for (int i = tid; i < 2 * 64 * NU4; i += 256) {
                int buf = i / (64 * NU4);
                int rem = i - buf * 64 * NU4;
                int r = rem / NU4, c = rem % NU4;
                uint4 v = (buf ? gBl : gBh)[r * NU4 + c];
                *reinterpret_cast<uint4*>(smem + (buf ? OFF_BL : OFF_BH) + r * STRIDE + c * 16) = v;
            }
        }
        __syncthreads();

        #pragma unroll 1
        for (int dx = 0; dx < 3; dx++) {
            if (dx > 0) {
                __syncthreads();
                const int tap = dy * 3 + dx;
                const uint4* gBh = reinterpret_cast<const uint4*>(wbh + (size_t)tap * 64 * CIN);
                const uint4* gBl = reinterpret_cast<const uint4*>(wbl + (size_t)tap * 64 * CIN);
                #pragma unroll 1
                for (int i = tid; i < 2 * 64 * NU4; i += 256) {
                    int buf = i / (64 * NU4);
                    int rem = i - buf * 64 * NU4;
                    int r = rem / NU4, c = rem % NU4;
                    uint4 v = (buf ? gBl : gBh)[r * NU4 + c];
                    *reinterpret_cast<uint4*>(smem + (buf ? OFF_BL : OFF_BH) + r * STRIDE + c * 16) = v;
                }
                __syncthreads();
            }
            const uint32_t arow_b = (a_row + dx) * STRIDE + a_khalf;
            #pragma unroll 1
            for (int kc = 0; kc < KCH; kc++) {
                const int k0b = kc * 32;
                uint32_t a_h[4], a_l[4];
                ldsm_x4(a_h, sbase + OFF_AH + arow_b + k0b);
                ldsm_x4(a_l, sbase + OFF_AL + arow_b + k0b);
                #pragma unroll
                for (int j = 0; j < 8; j++) {
                    const int brow = j * 8 + b_rowin;
                    uint32_t b_h[2], b_l[2];
                    ldsm_x2(b_h, sbase + OFF_BH + brow * STRIDE + k0b + b_khalf);
                    ldsm_x2(b_l, sbase + OFF_BL + brow * STRIDE + k0b + b_khalf);
                    mma_bf16(C[j], a_h, b_h);
                    mma_bf16(C[j], a_h, b_l);
                    mma_bf16(C[j], a_l, b_h);
                }
            }
        }
    }

    const int g = lane >> 2, t = lane & 3;
    const int xp0 = mw * 16 + g;
    #pragma unroll
    for (int j = 0; j < 8; j++) {
        #pragma unroll
        for (int r = 0; r < 4; r++) {
            const int co = j * 8 + t * 2 + (r & 1);
            const int xp = (r < 2) ? xp0 : xp0 + 8;
            float v = C[j][r] + __ldg(&bias[co]);
            v = (v >= 0.f) ? v : 0.1f * v;
            __nv_bfloat16 h = __float2bfloat16(v);
            __nv_bfloat16 l = __float2bfloat16(v - __bfloat162float(h));
            size_t base = ((size_t)(b * HP + y + 1) * HP + (xp + 1)) * 64 + co;
            outh[base] = h;
            outl[base] = l;
        }
    }
}

// ---------------- conv3 via warp MMA, per-dy A staging, 2 CTAs/SM ----------------
constexpr int STR3 = 144;
constexpr int OFF_AH3 = 0;
constexpr int OFF_AL3 = 130 * STR3;
constexpr int OFF_BH3 = 2 * 130 * STR3;
constexpr int OFF_BL3 = OFF_BH3 + 144 * STR3;
constexpr int SMEM3_TOTAL = OFF_BL3 + 144 * STR3;  // 78912

__global__ __launch_bounds__(512, 2)
void conv3_hmma_kernel(const __nv_bfloat16* __restrict__ h2ph, const __nv_bfloat16* __restrict__ h2pl,
                       const __nv_bfloat16* __restrict__ wbh, const __nv_bfloat16* __restrict__ wbl,
                       const float* __restrict__ b3, const float* __restrict__ flow,
                       float* __restrict__ po)
{
    extern __shared__ char smem[];
    const uint32_t sbase = smem_to_u32(smem);
    const int tid  = threadIdx.x;
    const int wid  = tid / 32;
    const int lane = tid % 32;
    const int mw   = wid / 2;
    const int wn   = wid % 2;
    const int y    = blockIdx.x;
    const int nt   = blockIdx.y;
    const int b    = blockIdx.z;

    float C[9][4];
    #pragma unroll
    for (int j = 0; j < 9; j++)
        #pragma unroll
        for (int r = 0; r < 4; r++) C[j][r] = 0.f;

    const int a_row = mw * 16 + (lane & 15);
    const int a_khalf = (lane & 16) ? 16 : 0;
    const int bl15 = lane & 15;
    const int b_rowin = bl15 & 7;
    const int b_khalf = (bl15 & 8) ? 16 : 0;

    #pragma unroll 1
    for (int dy = 0; dy < 3; dy++) {
        __syncthreads();
        const size_t abase = (size_t)(b * HP + y + dy) * HP * 64;
        const uint4* gAh = reinterpret_cast<const uint4*>(h2ph + abase);
        const uint4* gAl = reinterpret_cast<const uint4*>(h2pl + abase);
        #pragma unroll 1
        for (int i = tid; i < 2 * 130 * 8; i += 512) {
            int buf = i / 1040;
            int rem = i - buf * 1040;
            int r = rem >> 3, c = rem & 7;
            uint4 v = (buf ? gAl : gAh)[r * 8 + c];
            *reinterpret_cast<uint4*>(smem + (buf ? OFF_AL3 : OFF_AH3) + r * STR3 + c * 16) = v;
        }
        {
            const int tap = dy * 3;
            const uint4* gBh = reinterpret_cast<const uint4*>(wbh + ((size_t)tap * 432 + nt * 144) * 64);
            const uint4* gBl = reinterpret_cast<const uint4*>(wbl + ((size_t)tap * 432 + nt * 144) * 64);
            #pragma unroll 1
            for (int i = tid; i < 2304; i += 512) {
                int buf = (i >= 1152) ? 1 : 0;
                int j2  = buf ? i - 1152 : i;
                int r = j2 >> 3, c = j2 & 7;
                uint4 v = (buf ? gBl : gBh)[r * 8 + c];
                *reinterpret_cast<uint4*>(smem + (buf ? OFF_BL3 : OFF_BH3) + r * STR3 + c * 16) = v;
            }
        }
        __syncthreads();

        #pragma unroll 1
        for (int dx = 0; dx < 3; dx++) {
            if (dx > 0) {
                __syncthreads();
                const int tap = dy * 3 + dx;
                const uint4* gBh = reinterpret_cast<const uint4*>(wbh + ((size_t)tap * 432 + nt * 144) * 64);
                const uint4* gBl = reinterpret_cast<const uint4*>(wbl + ((size_t)tap * 432 + nt * 144) * 64);
                #pragma unroll 1
                for (int i = tid; i < 2304; i += 512) {
                    int buf = (i >= 1152) ? 1 : 0;
                    int j2  = buf ? i - 1152 : i;
                    int r = j2 >> 3, c = j2 & 7;
                    uint4 v = (buf ? gBl : gBh)[r * 8 + c];
                    *reinterpret_cast<uint4*>(smem + (buf ? OFF_BL3 : OFF_BH3) + r * STR3 + c * 16) = v;
                }
                __syncthreads();
            }
            const uint32_t arow_b = (a_row + dx) * STR3 + a_khalf;
            #pragma unroll
            for (int kc = 0; kc < 4; kc++) {
                const int k0b = kc * 32;
                uint32_t a_h[4], a_l[4];
                ldsm_x4(a_h, sbase + OFF_AH3 + arow_b + k0b);
                ldsm_x4(a_l, sbase + OFF_AL3 + arow_b + k0b);
                #pragma unroll
                for (int j = 0; j < 9; j++) {
                    const int brow = wn * 72 + j * 8 + b_rowin;
                    uint32_t b_h[2], b_l[2];
                    ldsm_x2(b_h, sbase + OFF_BH3 + brow * STR3 + k0b + b_khalf);
                    ldsm_x2(b_l, sbase + OFF_BL3 + brow * STR3 + k0b + b_khalf);
                    mma_bf16(C[j], a_h, b_h);
                    mma_bf16(C[j], a_h, b_l);
                    mma_bf16(C[j], a_l, b_h);
                }
            }
        }
    }

    const int g = lane >> 2, t = lane & 3;
    const int hw0 = y * Wc + mw * 16 + g;
    const int hw1 = hw0 + 8;
    const float fy0 = flow[(b * 2 + 1) * HWc + hw0];
    const float fx0 = flow[(b * 2 + 0) * HWc + hw0];
    const float fy1 = flow[(b * 2 + 1) * HWc + hw1];
    const float fx1 = flow[(b * 2 + 0) * HWc + hw1];
    #pragma unroll
    for (int j = 0; j < 9; j++) {
        const int cobase = nt * 144 + wn * 72 + j * 8 + t * 2;
        #pragma unroll
        for (int r = 0; r < 4; r++) {
            const int co = cobase + (r & 1);
            const int hw = (r < 2) ? hw0 : hw1;
            float v = C[j][r] + __ldg(&b3[co]);
            if (co < 288) {
                const float fyv = (r < 2) ? fy0 : fy1;
                const float fxv = (r < 2) ? fx0 : fx1;
                v = 10.f * tanhf(v) + ((co & 1) ? fxv : fyv);
            } else {
                v = 1.f / (1.f + expf(-v));
            }
            po[((size_t)b * 432 + co) * HWc + hw] = v;
        }
    }
}

// ---------------- deformable gather + einsum via HMMA, 4-way group split ----------------
constexpr int NSPL = 4;
constexpr int GPS  = 16 / NSPL;
constexpr int STRA = 112;
constexpr int DOFF_AH = 0;
constexpr int DOFF_AL = 128 * STRA;
constexpr int DOFF_BH = 2 * 128 * STRA;
constexpr int DOFF_BL = DOFF_BH + 64 * STRA;
constexpr int DSMEM = DOFF_BL + 64 * STRA;    // 43008

__global__ __launch_bounds__(256)
void deform_hmma_kernel(const float* __restrict__ xt, const float* __restrict__ po,
                        const __nv_bfloat16* __restrict__ wdh, const __nv_bfloat16* __restrict__ wdl,
                        float* __restrict__ dp)
{
    extern __shared__ char smem[];
    const uint32_t sbase = smem_to_u32(smem);
    const int tid  = threadIdx.x;
    const int mw   = tid / 32;
    const int lane = tid % 32;
    const int y    = blockIdx.x;
    const int gsp  = blockIdx.y;
    const int b    = blockIdx.z;
    const int B    = gridDim.z;

    float C[8][4];
    #pragma unroll
    for (int j = 0; j < 8; j++)
        #pragma unroll
        for (int r = 0; r < 4; r++) C[j][r] = 0.f;

    #pragma unroll 1
    for (int i = tid; i < 128 * 2 * 6; i += 256) {
        int w = i % 6;
        int r = (i / 6) % 128;
        int buf = i / (6 * 128);
        *reinterpret_cast<uint32_t*>(smem + (buf ? DOFF_AL : DOFF_AH) + r * STRA + 72 + w * 4) = 0u;
    }

    const int a_row   = mw * 16 + (lane & 15);
    const int a_khalf = (lane & 16) ? 16 : 0;
    const int bl15    = lane & 15;
    const int b_rowin = bl15 & 7;
    const int b_khalf = (bl15 & 8) ? 16 : 0;

    const float* pobase = po + (size_t)b * 432 * HWc + y * Wc;
    const float* xtb = xt + (size_t)b * 16 * HWc * 4;

    #pragma unroll 1
    for (int gl = 0; gl < GPS; gl++) {
        const int g = gsp * GPS + gl;
        __syncthreads();

        const uint4* gBh = reinterpret_cast<const uint4*>(wdh + (size_t)g * 64 * 48);
        const uint4* gBl = reinterpret_cast<const uint4*>(wdl + (size_t)g * 64 * 48);
        #pragma unroll 1
        for (int i = tid; i < 2 * 64 * 6; i += 256) {
            int buf = i / 384;
            int rem = i - buf * 384;
            int r = rem / 6, c = rem % 6;
            uint4 v = (buf ? gBl : gBh)[r * 6 + c];
            *reinterpret_cast<uint4*>(smem + (buf ? DOFF_BL : DOFF_BH) + r * STRA + c * 16) = v;
        }

        const float4* xg = reinterpret_cast<const float4*>(xtb + (size_t)g * HWc * 4);
        #pragma unroll 1
        for (int i = tid; i < 9 * 128; i += 256) {
            const int px  = i & 127;
            const int tap = i >> 7;
            const int gk  = g * 9 + tap;
            const float* pob = pobase + px;
            float offy = pob[(2 * gk) * HWc];
            float offx = pob[(2 * gk + 1) * HWc];
            float msk  = pob[(288 + gk) * HWc];

            float py = (float)(y + tap / 3 - 1) + offy;
            float pxf = (float)(px + tap % 3 - 1) + offx;
            float fy = floorf(py), fxv = floorf(pxf);
            int iy0 = (int)fy, ix0 = (int)fxv;
            float wy = py - fy, wx = pxf - fxv;

            bool vy0 = (unsigned)iy0       < (unsigned)Hc;
            bool vy1 = (unsigned)(iy0 + 1) < (unsigned)Hc;
            bool vx0 = (unsigned)ix0       < (unsigned)Wc;
            bool vx1 = (unsigned)(ix0 + 1) < (unsigned)Wc;
            int cy0 = min(max(iy0, 0), Hc - 1), cy1 = min(max(iy0 + 1, 0), Hc - 1);
            int cx0 = min(max(ix0, 0), Wc - 1), cx1 = min(max(ix0 + 1, 0), Wc - 1);

            float w00 = (1.f - wy) * (1.f - wx) * msk; if (!(vy0 && vx0)) w00 = 0.f;
            float w01 = (1.f - wy) * wx        * msk; if (!(vy0 && vx1)) w01 = 0.f;
            float w10 = wy        * (1.f - wx) * msk; if (!(vy1 && vx0)) w10 = 0.f;
            float w11 = wy        * wx         * msk; if (!(vy1 && vx1)) w11 = 0.f;

            float4 p00 = __ldg(xg + cy0 * Wc + cx0);
            float4 p01 = __ldg(xg + cy0 * Wc + cx1);
            float4 p10 = __ldg(xg + cy1 * Wc + cx0);
            float4 p11 = __ldg(xg + cy1 * Wc + cx1);

            float val[4];
            val[0] = w00 * p00.x + w01 * p01.x + w10 * p10.x + w11 * p11.x;
            val[1] = w00 * p00.y + w01 * p01.y + w10 * p10.y + w11 * p11.y;
            val[2] = w00 * p00.z + w01 * p01.z + w10 * p10.z + w11 * p11.z;
            val[3] = w00 * p00.w + w01 * p01.w + w10 * p10.w + w11 * p11.w;

            uint32_t h01, h23, l01, l23;
            {
                __nv_bfloat16 h0 = __float2bfloat16(val[0]);
                __nv_bfloat16 h1 = __float2bfloat16(val[1]);
                __nv_bfloat16 h2 = __float2bfloat16(val[2]);
                __nv_bfloat16 h3 = __float2bfloat16(val[3]);
                __nv_bfloat16 l0 = __float2bfloat16(val[0] - __bfloat162float(h0));
                __nv_bfloat16 l1 = __float2bfloat16(val[1] - __bfloat162float(h1));
                __nv_bfloat16 l2 = __float2bfloat16(val[2] - __bfloat162float(h2));
                __nv_bfloat16 l3 = __float2bfloat16(val[3] - __bfloat162float(h3));
                h01 = (uint32_t)__bfloat16_as_ushort(h0) | ((uint32_t)__bfloat16_as_ushort(h1) << 16);
                h23 = (uint32_t)__bfloat16_as_ushort(h2) | ((uint32_t)__bfloat16_as_ushort(h3) << 16);
                l01 = (uint32_t)__bfloat16_as_ushort(l0) | ((uint32_t)__bfloat16_as_ushort(l1) << 16);
                l23 = (uint32_t)__bfloat16_as_ushort(l2) | ((uint32_t)__bfloat16_as_ushort(l3) << 16);
            }
            uint32_t ao = px * STRA + tap * 8;
            *reinterpret_cast<uint2*>(smem + DOFF_AH + ao) = make_uint2(h01, h23);
            *reinterpret_cast<uint2*>(smem + DOFF_AL + ao) = make_uint2(l01, l23);
        }
        __syncthreads();

        #pragma unroll
        for (int kc = 0; kc < 3; kc++) {
            const int k0b = kc * 32;
            uint32_t a_h[4], a_l[4];
            ldsm_x4(a_h, sbase + DOFF_AH + a_row * STRA + k0b + a_khalf);
            ldsm_x4(a_l, sbase + DOFF_AL + a_row * STRA + k0b + a_khalf);
            #pragma unroll
            for (int j = 0; j < 8; j++) {
                const int brow = j * 8 + b_rowin;
                uint32_t b_h[2], b_l[2];
                ldsm_x2(b_h, sbase + DOFF_BH + brow * STRA + k0b + b_khalf);
                ldsm_x2(b_l, sbase + DOFF_BL + brow * STRA + k0b + b_khalf);
                mma_bf16(C[j], a_h, b_h);
                mma_bf16(C[j], a_h, b_l);
                mma_bf16(C[j], a_l, b_h);
            }
        }
    }

    const int gfrag = lane >> 2, t = lane & 3;
    const int xp0 = mw * 16 + gfrag;
    float* dpo = dp + ((size_t)gsp * B + b) * 64 * HWc + y * Wc;
    #pragma unroll
    for (int j = 0; j < 8; j++) {
        #pragma unroll
        for (int r = 0; r < 4; r++) {
            const int co = j * 8 + t * 2 + (r & 1);
            const int xp = (r < 2) ? xp0 : xp0 + 8;
            dpo[(size_t)co * HWc + xp] = C[j][r];
        }
    }
}

// ---------------- combine partials (4-way) ----------------
__global__ __launch_bounds__(256)
void combine_kernel(const float* __restrict__ dp, float* __restrict__ out, int n4)
{
    int i = blockIdx.x * 256 + threadIdx.x;
    if (i < n4) {
        float4 a0 = reinterpret_cast<const float4*>(dp)[i];
        float4 a1 = reinterpret_cast<const float4*>(dp)[n4 + i];
        float4 a2 = reinterpret_cast<const float4*>(dp)[2 * n4 + i];
        float4 a3 = reinterpret_cast<const float4*>(dp)[3 * n4 + i];
        float4 o;
        o.x = (a0.x + a1.x) + (a2.x + a3.x);
        o.y = (a0.y + a1.y) + (a2.y + a3.y);
        o.z = (a0.z + a1.z) + (a2.z + a3.z);
        o.w = (a0.w + a1.w) + (a2.w + a3.w);
        reinterpret_cast<float4*>(out)[i] = o;
    }
}

// ---------------- launch ----------------
extern "C" void kernel_launch(void* const* d_in, const int* in_sizes, int n_in,
                              void* d_out, int out_size)
{
    const float* x    = (const float*)d_in[0];
    const float* ef   = (const float*)d_in[1];
    const float* flow = (const float*)d_in[2];
    const float* w1   = (const float*)d_in[3];
    const float* b1   = (const float*)d_in[4];
    const float* w2   = (const float*)d_in[5];
    const float* b2   = (const float*)d_in[6];
    const float* w3   = (const float*)d_in[7];
    const float* b3   = (const float*)d_in[8];
    const float* wgt  = (const float*)d_in[9];
    float* out = (float*)d_out;

    const int B = in_sizes[0] / (64 * HWc);  // = 2

    float *ppo, *pxt, *pdp;
    __nv_bfloat16 *pefh, *pefl, *ph1h, *ph1l, *ph2h, *ph2l;
    __nv_bfloat16 *pw1h, *pw1l, *pw2h, *pw2l, *pw3h, *pw3l, *pwdh, *pwdl;
    cudaGetSymbolAddress((void**)&ppo,  g_po);
    cudaGetSymbolAddress((void**)&pxt,  g_xt);
    cudaGetSymbolAddress((void**)&pdp,  g_dp);
    cudaGetSymbolAddress((void**)&pefh, g_efph);
    cudaGetSymbolAddress((void**)&pefl, g_efpl);
    cudaGetSymbolAddress((void**)&ph1h, g_h1ph);
    cudaGetSymbolAddress((void**)&ph1l, g_h1pl);
    cudaGetSymbolAddress((void**)&ph2h, g_h2ph);
    cudaGetSymbolAddress((void**)&ph2l, g_h2pl);
    cudaGetSymbolAddress((void**)&pw1h, g_w1bh);
    cudaGetSymbolAddress((void**)&pw1l, g_w1bl);
    cudaGetSymbolAddress((void**)&pw2h, g_w2bh);
    cudaGetSymbolAddress((void**)&pw2l, g_w2bl);
    cudaGetSymbolAddress((void**)&pw3h, g_w3bh);
    cudaGetSymbolAddress((void**)&pw3l, g_w3bl);
    cudaGetSymbolAddress((void**)&pwdh, g_wdh);
    cudaGetSymbolAddress((void**)&pwdl, g_wdl);

    constexpr int STR1 = 128 * 2 + 16;
    constexpr int STR2 = 64 * 2 + 16;
    constexpr int SMEM1 = 2 * 130 * STR1 + 2 * 64 * STR1;
    constexpr int SMEM2 = 2 * 130 * STR2 + 2 * 64 * STR2;
    cudaFuncSetAttribute(conv12_hmma_kernel<128>, cudaFuncAttributeMaxDynamicSharedMemorySize, SMEM1);
    cudaFuncSetAttribute(conv12_hmma_kernel<64>,  cudaFuncAttributeMaxDynamicSharedMemorySize, SMEM2);
    cudaFuncSetAttribute(conv3_hmma_kernel, cudaFuncAttributeMaxDynamicSharedMemorySize, SMEM3_TOTAL);
    cudaFuncSetAttribute(deform_hmma_kernel, cudaFuncAttributeMaxDynamicSharedMemorySize, DSMEM);

    // fused prep (1 launch): transpose | efprep | border fill | wprep
    int t_end = 1024 * B;
    int e_end = t_end + 2048 * B;
    int f_end = e_end + (B * 8256 + 255) / 256;
    int total = f_end + (WTOT + 255) / 256;
    prep_all_kernel<<<total, 256>>>(x, pxt, ef, pefh, pefl, ph1h, ph1l, ph2h, ph2l,
                                    w1, w2, w3, wgt,
                                    pw1h, pw1l, pw2h, pw2l, pw3h, pw3l, pwdh, pwdl,
                                    B, t_end, e_end, f_end);

    // conv chain (all HMMA) — conv3 is launch index 3 (profiled by ncu)
    conv12_hmma_kernel<128><<<dim3(Hc, B), 256, SMEM1>>>(pefh, pefl, pw1h, pw1l, b1, ph1h, ph1l);
    conv12_hmma_kernel<64><<<dim3(Hc, B), 256, SMEM2>>>(ph1h, ph1l, pw2h, pw2l, b2, ph2h, ph2l);
    conv3_hmma_kernel<<<dim3(Hc, 3, B), 512, SMEM3_TOTAL>>>(ph2h, ph2l, pw3h, pw3l, b3, flow, ppo);

    // deformable gather + einsum via HMMA, 4-way group split
    deform_hmma_kernel<<<dim3(Hc, NSPL, B), 256, DSMEM>>>(pxt, ppo, pwdh, pwdl, pdp);
    int n4 = B * 64 * HWc / 4;
    combine_kernel<<<(n4 + 255) / 256, 256>>>(pdp, out, n4);
}